// round 5
// baseline (speedup 1.0000x reference)
#include <cuda_runtime.h>
#include <cstddef>

#define NA 100000
#define NB 100000
#define DD 64
#define EMAX 1250000

// ---------------- scratch (device globals: no allocation allowed) ----------
__device__ int g_cnt0[NB], g_cnt1[NA], g_cnt2[NA];
__device__ int g_ptr0[NB + 1], g_ptr1[NA + 1], g_ptr2[NA + 1];
__device__ int g_wofs0[NB], g_wofs1[NA], g_wofs2[NA];
__device__ int g_col0[EMAX], g_col1[EMAX], g_col2[EMAX];
__device__ float g_A1[NA * DD];
__device__ float g_B1[NB * DD];

// ---------------- CSR build: histogram --------------------------------------
__global__ void hist_kernel(const int* __restrict__ d0,
                            const int* __restrict__ d1,
                            const int* __restrict__ d2,
                            int E0, int E1, int E2) {
    int i = blockIdx.x * blockDim.x + threadIdx.x;
    int stride = gridDim.x * blockDim.x;
    for (int e = i; e < E0; e += stride) atomicAdd(&g_cnt0[__ldg(d0 + e)], 1);
    for (int e = i; e < E1; e += stride) atomicAdd(&g_cnt1[__ldg(d1 + e)], 1);
    for (int e = i; e < E2; e += stride) atomicAdd(&g_cnt2[__ldg(d2 + e)], 1);
}

// ---------------- CSR build: exclusive scan (one block per edge type) -------
__global__ void scan_kernel(int E0, int E1, int E2) {
    const int* cnt; int* ptr; int* wofs; int N; int E;
    if (blockIdx.x == 0)      { cnt = g_cnt0; ptr = g_ptr0; wofs = g_wofs0; N = NB; E = E0; }
    else if (blockIdx.x == 1) { cnt = g_cnt1; ptr = g_ptr1; wofs = g_wofs1; N = NA; E = E1; }
    else                      { cnt = g_cnt2; ptr = g_ptr2; wofs = g_wofs2; N = NA; E = E2; }
    __shared__ int sdata[1024];
    int t = threadIdx.x;
    const int C = (N + 1023) / 1024;
    int lo = t * C;
    int hi = lo + C < N ? lo + C : N;
    int local = 0;
    for (int i = lo; i < hi; i++) local += cnt[i];
    sdata[t] = local;
    __syncthreads();
    for (int o = 1; o < 1024; o <<= 1) {
        int v = (t >= o) ? sdata[t - o] : 0;
        __syncthreads();
        sdata[t] += v;
        __syncthreads();
    }
    int base = sdata[t] - local;  // exclusive prefix
    for (int i = lo; i < hi; i++) {
        ptr[i] = base;
        wofs[i] = base;
        base += cnt[i];
    }
    if (t == 1023) ptr[N] = E;
}

// ---------------- CSR build: scatter src ids into dst-sorted order ----------
__global__ void scatter_kernel(const int* __restrict__ s0, const int* __restrict__ d0,
                               const int* __restrict__ s1, const int* __restrict__ d1,
                               const int* __restrict__ s2, const int* __restrict__ d2,
                               int E0, int E1, int E2) {
    int i = blockIdx.x * blockDim.x + threadIdx.x;
    int stride = gridDim.x * blockDim.x;
    for (int e = i; e < E0; e += stride) {
        int p = atomicAdd(&g_wofs0[__ldg(d0 + e)], 1);
        g_col0[p] = __ldg(s0 + e);
    }
    for (int e = i; e < E1; e += stride) {
        int p = atomicAdd(&g_wofs1[__ldg(d1 + e)], 1);
        g_col1[p] = __ldg(s1 + e);
    }
    for (int e = i; e < E2; e += stride) {
        int p = atomicAdd(&g_wofs2[__ldg(d2 + e)], 1);
        g_col2[p] = __ldg(s2 + e);
    }
}

// ---------------- atomic-free gather of mean-aggregated features into smem --
// 8 threads per node; thread c accumulates float4 slots 2c, 2c+1 (32B).
// 2-edge software pipeline -> 4 independent feature LDG.128s in flight.
__device__ __forceinline__ void gather_into(float4* sm, const int* __restrict__ ptr,
                                            const int* __restrict__ col,
                                            const float* __restrict__ x,
                                            int row0, int g, int c) {
    int n = row0 + g;
    int beg = __ldg(ptr + n), end = __ldg(ptr + n + 1);
    float4 a0 = make_float4(0.f, 0.f, 0.f, 0.f);
    float4 a1 = make_float4(0.f, 0.f, 0.f, 0.f);
    int k = beg;
    int s0 = 0, s1 = 0;
    if (k < end) s0 = __ldg(col + k);
    if (k + 1 < end) s1 = __ldg(col + k + 1);
    while (k + 1 < end) {
        int ns0 = 0, ns1 = 0;
        if (k + 2 < end) ns0 = __ldg(col + k + 2);
        if (k + 3 < end) ns1 = __ldg(col + k + 3);
        const float4* f0 = (const float4*)x + (size_t)s0 * 16 + c * 2;
        const float4* f1 = (const float4*)x + (size_t)s1 * 16 + c * 2;
        float4 u0 = __ldg(f0), v0 = __ldg(f0 + 1);
        float4 u1 = __ldg(f1), v1 = __ldg(f1 + 1);
        a0.x += u0.x + u1.x; a0.y += u0.y + u1.y;
        a0.z += u0.z + u1.z; a0.w += u0.w + u1.w;
        a1.x += v0.x + v1.x; a1.y += v0.y + v1.y;
        a1.z += v0.z + v1.z; a1.w += v0.w + v1.w;
        s0 = ns0; s1 = ns1; k += 2;
    }
    if (k < end) {
        const float4* f0 = (const float4*)x + (size_t)s0 * 16 + c * 2;
        float4 u0 = __ldg(f0), v0 = __ldg(f0 + 1);
        a0.x += u0.x; a0.y += u0.y; a0.z += u0.z; a0.w += u0.w;
        a1.x += v0.x; a1.y += v0.y; a1.z += v0.z; a1.w += v0.w;
    }
    float inv = 1.0f / fmaxf((float)(end - beg), 1.0f);
    a0.x *= inv; a0.y *= inv; a0.z *= inv; a0.w *= inv;
    a1.x *= inv; a1.y *= inv; a1.z *= inv; a1.w *= inv;
    sm[g * 16 + c * 2] = a0;
    sm[g * 16 + c * 2 + 1] = a1;
}

// ---------------- fused layer: gather -> mean -> GEMM combine (-> head) -----
// block = 256 threads, 32 dst rows. A-side gathers types 1,2; B-side type 0.
template<bool HEAD>
__global__ __launch_bounds__(256) void layer_kernel(
    const float* __restrict__ xA, const float* __restrict__ xB,
    const float* __restrict__ Wn, const float* __restrict__ Wr,
    const float* __restrict__ bias,
    const float* __restrict__ Wout, const float* __restrict__ bout,
    float* __restrict__ outA, float* __restrict__ outB, int nbA) {
    __shared__ float4 sbuf[3 * 512];
    const int j = threadIdx.x & 63;
    const int rg = threadIdx.x >> 6;
    const int g = threadIdx.x >> 3;   // node within tile, 0..31
    const int c = threadIdx.x & 7;    // float4-pair slot, 0..7
    float h[8];
    float* outX;
    int row0;

    if (blockIdx.x < nbA) {
        // ---------- A side: mean(m1)@Wn1 + mean(m2)@Wn2 + x@(Wr1+Wr2) + b1+b2
        row0 = blockIdx.x * 32;
        outX = outA;
        float4* sm1 = sbuf;
        float4* sm2 = sbuf + 512;
        float4* smx = sbuf + 1024;
        for (int i = threadIdx.x; i < 512; i += 256)
            smx[i] = __ldg((const float4*)xA + (size_t)row0 * 16 + i);
        gather_into(sm1, g_ptr1, g_col1, xB, row0, g, c);  // B -> A
        gather_into(sm2, g_ptr2, g_col2, xA, row0, g, c);  // A -> A
        float wn1[64], wn2[64], wrs[64];
#pragma unroll
        for (int k = 0; k < 64; k++) {
            wn1[k] = __ldg(Wn + 1 * 4096 + k * 64 + j);
            wn2[k] = __ldg(Wn + 2 * 4096 + k * 64 + j);
            wrs[k] = __ldg(Wr + 1 * 4096 + k * 64 + j) + __ldg(Wr + 2 * 4096 + k * 64 + j);
        }
        float bj = __ldg(bias + 1 * 64 + j) + __ldg(bias + 2 * 64 + j);
        __syncthreads();
#pragma unroll
        for (int rr = 0; rr < 8; rr++) {
            int r = rg * 8 + rr;
            const float4* p1 = sm1 + r * 16;
            const float4* p2 = sm2 + r * 16;
            const float4* px = smx + r * 16;
            float a0 = bj, a1 = 0.f;
#pragma unroll
            for (int k4 = 0; k4 < 8; k4++) {
                float4 a = p1[k4];
                a0 += a.x * wn1[4 * k4 + 0] + a.y * wn1[4 * k4 + 1]
                    + a.z * wn1[4 * k4 + 2] + a.w * wn1[4 * k4 + 3];
                float4 b = p2[k4];
                a0 += b.x * wn2[4 * k4 + 0] + b.y * wn2[4 * k4 + 1]
                    + b.z * wn2[4 * k4 + 2] + b.w * wn2[4 * k4 + 3];
                float4 cc = px[k4];
                a0 += cc.x * wrs[4 * k4 + 0] + cc.y * wrs[4 * k4 + 1]
                    + cc.z * wrs[4 * k4 + 2] + cc.w * wrs[4 * k4 + 3];
            }
#pragma unroll
            for (int k4 = 8; k4 < 16; k4++) {
                float4 a = p1[k4];
                a1 += a.x * wn1[4 * k4 + 0] + a.y * wn1[4 * k4 + 1]
                    + a.z * wn1[4 * k4 + 2] + a.w * wn1[4 * k4 + 3];
                float4 b = p2[k4];
                a1 += b.x * wn2[4 * k4 + 0] + b.y * wn2[4 * k4 + 1]
                    + b.z * wn2[4 * k4 + 2] + b.w * wn2[4 * k4 + 3];
                float4 cc = px[k4];
                a1 += cc.x * wrs[4 * k4 + 0] + cc.y * wrs[4 * k4 + 1]
                    + cc.z * wrs[4 * k4 + 2] + cc.w * wrs[4 * k4 + 3];
            }
            h[rr] = a0 + a1;
        }
    } else {
        // ---------- B side: mean(m0)@Wn0 + x@Wr0 + b0
        row0 = (blockIdx.x - nbA) * 32;
        outX = outB;
        float4* smm = sbuf;
        float4* smx = sbuf + 1024;
        for (int i = threadIdx.x; i < 512; i += 256)
            smx[i] = __ldg((const float4*)xB + (size_t)row0 * 16 + i);
        gather_into(smm, g_ptr0, g_col0, xA, row0, g, c);  // A -> B
        float wn[64], wr[64];
#pragma unroll
        for (int k = 0; k < 64; k++) {
            wn[k] = __ldg(Wn + k * 64 + j);
            wr[k] = __ldg(Wr + k * 64 + j);
        }
        float bj = __ldg(bias + j);
        __syncthreads();
#pragma unroll
        for (int rr = 0; rr < 8; rr++) {
            int r = rg * 8 + rr;
            const float4* pm = smm + r * 16;
            const float4* px = smx + r * 16;
            float a0 = bj, a1 = 0.f;
#pragma unroll
            for (int k4 = 0; k4 < 8; k4++) {
                float4 a = pm[k4];
                a0 += a.x * wn[4 * k4 + 0] + a.y * wn[4 * k4 + 1]
                    + a.z * wn[4 * k4 + 2] + a.w * wn[4 * k4 + 3];
                float4 bv = px[k4];
                a0 += bv.x * wr[4 * k4 + 0] + bv.y * wr[4 * k4 + 1]
                    + bv.z * wr[4 * k4 + 2] + bv.w * wr[4 * k4 + 3];
            }
#pragma unroll
            for (int k4 = 8; k4 < 16; k4++) {
                float4 a = pm[k4];
                a1 += a.x * wn[4 * k4 + 0] + a.y * wn[4 * k4 + 1]
                    + a.z * wn[4 * k4 + 2] + a.w * wn[4 * k4 + 3];
                float4 bv = px[k4];
                a1 += bv.x * wr[4 * k4 + 0] + bv.y * wr[4 * k4 + 1]
                    + bv.z * wr[4 * k4 + 2] + bv.w * wr[4 * k4 + 3];
            }
            h[rr] = a0 + a1;
        }
    }

    if (!HEAD) {
#pragma unroll
        for (int rr = 0; rr < 8; rr++)
            outX[(size_t)(row0 + rg * 8 + rr) * 64 + j] = h[rr];
    } else {
        // ---------- fused head: out = relu(h @ Wout + bout), h staged in smem
        __syncthreads();
        float* hb = (float*)sbuf;
#pragma unroll
        for (int rr = 0; rr < 8; rr++)
            hb[(rg * 8 + rr) * 64 + j] = h[rr];
        float w[64];
#pragma unroll
        for (int k = 0; k < 64; k++) w[k] = __ldg(Wout + k * 64 + j);
        float bj2 = __ldg(bout + j);
        __syncthreads();
#pragma unroll
        for (int rr = 0; rr < 8; rr++) {
            int r = rg * 8 + rr;
            const float4* ph = (const float4*)(hb + r * 64);
            float a0 = bj2, a1 = 0.f;
#pragma unroll
            for (int k4 = 0; k4 < 8; k4++) {
                float4 cc = ph[k4];
                a0 += cc.x * w[4 * k4 + 0] + cc.y * w[4 * k4 + 1]
                    + cc.z * w[4 * k4 + 2] + cc.w * w[4 * k4 + 3];
            }
#pragma unroll
            for (int k4 = 8; k4 < 16; k4++) {
                float4 cc = ph[k4];
                a1 += cc.x * w[4 * k4 + 0] + cc.y * w[4 * k4 + 1]
                    + cc.z * w[4 * k4 + 2] + cc.w * w[4 * k4 + 3];
            }
            outX[(size_t)(row0 + r) * 64 + j] = fmaxf(a0 + a1, 0.0f);
        }
    }
}

// ---------------- launcher --------------------------------------------------
extern "C" void kernel_launch(void* const* d_in, const int* in_sizes, int n_in,
                              void* d_out, int out_size) {
    const float* x_A   = (const float*)d_in[0];
    const float* x_B   = (const float*)d_in[1];
    const float* Wn    = (const float*)d_in[2];   // [2,3,64,64]
    const float* Wr    = (const float*)d_in[3];   // [2,3,64,64]
    const float* b     = (const float*)d_in[4];   // [2,3,64]
    const float* W_out = (const float*)d_in[5];   // [64,64]
    const float* b_out = (const float*)d_in[6];   // [64]
    const int* src0 = (const int*)d_in[7];
    const int* dst0 = (const int*)d_in[8];
    const int* src1 = (const int*)d_in[9];
    const int* dst1 = (const int*)d_in[10];
    const int* src2 = (const int*)d_in[11];
    const int* dst2 = (const int*)d_in[12];
    const int E0 = in_sizes[7];
    const int E1 = in_sizes[9];
    const int E2 = in_sizes[11];
    float* out = (float*)d_out;

    float *A1, *B1;
    int *cnt0, *cnt1, *cnt2;
    cudaGetSymbolAddress((void**)&A1, g_A1);
    cudaGetSymbolAddress((void**)&B1, g_B1);
    cudaGetSymbolAddress((void**)&cnt0, g_cnt0);
    cudaGetSymbolAddress((void**)&cnt1, g_cnt1);
    cudaGetSymbolAddress((void**)&cnt2, g_cnt2);

    const int nbA = NA / 32;  // 3125
    const int nbB = NB / 32;  // 3125

    // ---- CSR build (dst distributions shared by both layers) ----
    cudaMemsetAsync(cnt0, 0, NB * sizeof(int));
    cudaMemsetAsync(cnt1, 0, NA * sizeof(int));
    cudaMemsetAsync(cnt2, 0, NA * sizeof(int));
    hist_kernel<<<1024, 256>>>(dst0, dst1, dst2, E0, E1, E2);
    scan_kernel<<<3, 1024>>>(E0, E1, E2);
    scatter_kernel<<<1024, 256>>>(src0, dst0, src1, dst1, src2, dst2, E0, E1, E2);

    // ---- layer 0: fused gather + combine ----
    layer_kernel<false><<<nbA + nbB, 256>>>(x_A, x_B, Wn, Wr, b,
                                            nullptr, nullptr, A1, B1, nbA);

    // ---- layer 1: fused gather + combine + ReLU head ----
    layer_kernel<true><<<nbA + nbB, 256>>>(A1, B1,
                                           Wn + 3 * 4096, Wr + 3 * 4096, b + 3 * 64,
                                           W_out, b_out,
                                           out, out + (size_t)NA * 64, nbA);
}

// round 6
// speedup vs baseline: 1.2506x; 1.2506x over previous
#include <cuda_runtime.h>
#include <cstddef>

#define NA 100000
#define NB 100000
#define DD 64
#define EMAX 1250000

// ---------------- scratch (device globals: no allocation allowed) ----------
__device__ int g_cnt0[NB], g_cnt1[NA], g_cnt2[NA];
__device__ int g_ptr0[NB + 1], g_ptr1[NA + 1], g_ptr2[NA + 1];
__device__ int g_wofs0[NB], g_wofs1[NA], g_wofs2[NA];
__device__ int g_col0[EMAX], g_col1[EMAX], g_col2[EMAX];
__device__ float g_m0[NB * DD];
__device__ float g_m1[NA * DD];
__device__ float g_m2[NA * DD];
__device__ float g_A1[NA * DD];
__device__ float g_B1[NB * DD];

// ---------------- CSR build: histogram --------------------------------------
__global__ void hist_kernel(const int* __restrict__ d0,
                            const int* __restrict__ d1,
                            const int* __restrict__ d2,
                            int E0, int E1, int E2) {
    int i = blockIdx.x * blockDim.x + threadIdx.x;
    int stride = gridDim.x * blockDim.x;
    for (int e = i; e < E0; e += stride) atomicAdd(&g_cnt0[__ldg(d0 + e)], 1);
    for (int e = i; e < E1; e += stride) atomicAdd(&g_cnt1[__ldg(d1 + e)], 1);
    for (int e = i; e < E2; e += stride) atomicAdd(&g_cnt2[__ldg(d2 + e)], 1);
}

// ---------------- CSR build: exclusive scan (one block per edge type) -------
__global__ void scan_kernel(int E0, int E1, int E2) {
    const int* cnt; int* ptr; int* wofs; int N; int E;
    if (blockIdx.x == 0)      { cnt = g_cnt0; ptr = g_ptr0; wofs = g_wofs0; N = NB; E = E0; }
    else if (blockIdx.x == 1) { cnt = g_cnt1; ptr = g_ptr1; wofs = g_wofs1; N = NA; E = E1; }
    else                      { cnt = g_cnt2; ptr = g_ptr2; wofs = g_wofs2; N = NA; E = E2; }
    __shared__ int sdata[1024];
    int t = threadIdx.x;
    const int C = (N + 1023) / 1024;
    int lo = t * C;
    int hi = lo + C < N ? lo + C : N;
    int local = 0;
    for (int i = lo; i < hi; i++) local += cnt[i];
    sdata[t] = local;
    __syncthreads();
    for (int o = 1; o < 1024; o <<= 1) {
        int v = (t >= o) ? sdata[t - o] : 0;
        __syncthreads();
        sdata[t] += v;
        __syncthreads();
    }
    int base = sdata[t] - local;  // exclusive prefix
    for (int i = lo; i < hi; i++) {
        ptr[i] = base;
        wofs[i] = base;
        base += cnt[i];
    }
    if (t == 1023) ptr[N] = E;
}

// ---------------- CSR build: scatter src ids into dst-sorted order ----------
__global__ void scatter_kernel(const int* __restrict__ s0, const int* __restrict__ d0,
                               const int* __restrict__ s1, const int* __restrict__ d1,
                               const int* __restrict__ s2, const int* __restrict__ d2,
                               int E0, int E1, int E2) {
    int i = blockIdx.x * blockDim.x + threadIdx.x;
    int stride = gridDim.x * blockDim.x;
    for (int e = i; e < E0; e += stride) {
        int p = atomicAdd(&g_wofs0[__ldg(d0 + e)], 1);
        g_col0[p] = __ldg(s0 + e);
    }
    for (int e = i; e < E1; e += stride) {
        int p = atomicAdd(&g_wofs1[__ldg(d1 + e)], 1);
        g_col1[p] = __ldg(s1 + e);
    }
    for (int e = i; e < E2; e += stride) {
        int p = atomicAdd(&g_wofs2[__ldg(d2 + e)], 1);
        g_col2[p] = __ldg(s2 + e);
    }
}

// ---------------- standalone atomic-free CSR gather (mean) ------------------
// Grid split into 3 per-type segments. 8 threads per node; thread c owns
// float4 slots 2c,2c+1. 2-edge software pipeline -> 4 LDG.128 in flight.
// Writes the mean directly (zero-degree nodes write 0), so no memset/recip.
__global__ __launch_bounds__(256, 6)
void gather_kernel(const float* __restrict__ xA, const float* __restrict__ xB,
                   int nb0, int nb01) {
    int bid = blockIdx.x;
    const float* x; const int* ptr; const int* col; float* m; int row0;
    if (bid < nb0)       { row0 = bid * 32;          x = xA; ptr = g_ptr0; col = g_col0; m = g_m0; }
    else if (bid < nb01) { row0 = (bid - nb0) * 32;  x = xB; ptr = g_ptr1; col = g_col1; m = g_m1; }
    else                 { row0 = (bid - nb01) * 32; x = xA; ptr = g_ptr2; col = g_col2; m = g_m2; }

    int g = threadIdx.x >> 3;   // node in tile
    int c = threadIdx.x & 7;    // slot
    int n = row0 + g;
    int beg = __ldg(ptr + n), end = __ldg(ptr + n + 1);
    float4 a0 = make_float4(0.f, 0.f, 0.f, 0.f);
    float4 a1 = make_float4(0.f, 0.f, 0.f, 0.f);
    int k = beg;
    int s0 = 0, s1 = 0;
    if (k < end) s0 = __ldg(col + k);
    if (k + 1 < end) s1 = __ldg(col + k + 1);
    while (k + 1 < end) {
        int ns0 = 0, ns1 = 0;
        if (k + 2 < end) ns0 = __ldg(col + k + 2);
        if (k + 3 < end) ns1 = __ldg(col + k + 3);
        const float4* f0 = (const float4*)x + (size_t)s0 * 16 + c * 2;
        const float4* f1 = (const float4*)x + (size_t)s1 * 16 + c * 2;
        float4 u0 = __ldg(f0), v0 = __ldg(f0 + 1);
        float4 u1 = __ldg(f1), v1 = __ldg(f1 + 1);
        a0.x += u0.x + u1.x; a0.y += u0.y + u1.y;
        a0.z += u0.z + u1.z; a0.w += u0.w + u1.w;
        a1.x += v0.x + v1.x; a1.y += v0.y + v1.y;
        a1.z += v0.z + v1.z; a1.w += v0.w + v1.w;
        s0 = ns0; s1 = ns1; k += 2;
    }
    if (k < end) {
        const float4* f0 = (const float4*)x + (size_t)s0 * 16 + c * 2;
        float4 u0 = __ldg(f0), v0 = __ldg(f0 + 1);
        a0.x += u0.x; a0.y += u0.y; a0.z += u0.z; a0.w += u0.w;
        a1.x += v0.x; a1.y += v0.y; a1.z += v0.z; a1.w += v0.w;
    }
    float inv = 1.0f / fmaxf((float)(end - beg), 1.0f);
    a0.x *= inv; a0.y *= inv; a0.z *= inv; a0.w *= inv;
    a1.x *= inv; a1.y *= inv; a1.z *= inv; a1.w *= inv;
    float4* mo = (float4*)m + (size_t)n * 16 + c * 2;
    mo[0] = a0;
    mo[1] = a1;
}

// ---------------- fused combine (A-side combine3 + B-side combine2),
//                  optionally with the ReLU head fused on top ---------------
template<bool HEAD>
__global__ __launch_bounds__(256) void combine_kernel(
    const float* __restrict__ xA, const float* __restrict__ xB,
    const float* __restrict__ Wn, const float* __restrict__ Wr,
    const float* __restrict__ bias,
    const float* __restrict__ Wout, const float* __restrict__ bout,
    float* __restrict__ outA, float* __restrict__ outB, int nbA) {
    __shared__ float4 sbuf[3 * 512];
    const int j = threadIdx.x & 63;
    const int rg = threadIdx.x >> 6;
    float h[8];
    float* outX;
    int row0;

    if (blockIdx.x < nbA) {
        // ---------- A side: m1@Wn1 + m2@Wn2 + x@(Wr1+Wr2) + b1+b2
        row0 = blockIdx.x * 32;
        outX = outA;
        float4* sm1 = sbuf;
        float4* sm2 = sbuf + 512;
        float4* smx = sbuf + 1024;
        for (int i = threadIdx.x; i < 512; i += 256) {
            sm1[i] = __ldg((const float4*)g_m1 + (size_t)row0 * 16 + i);
            sm2[i] = __ldg((const float4*)g_m2 + (size_t)row0 * 16 + i);
            smx[i] = __ldg((const float4*)xA + (size_t)row0 * 16 + i);
        }
        float wn1[64], wn2[64], wrs[64];
#pragma unroll
        for (int k = 0; k < 64; k++) {
            wn1[k] = __ldg(Wn + 1 * 4096 + k * 64 + j);
            wn2[k] = __ldg(Wn + 2 * 4096 + k * 64 + j);
            wrs[k] = __ldg(Wr + 1 * 4096 + k * 64 + j) + __ldg(Wr + 2 * 4096 + k * 64 + j);
        }
        float bj = __ldg(bias + 1 * 64 + j) + __ldg(bias + 2 * 64 + j);
        __syncthreads();
#pragma unroll
        for (int rr = 0; rr < 8; rr++) {
            int r = rg * 8 + rr;
            const float4* p1 = sm1 + r * 16;
            const float4* p2 = sm2 + r * 16;
            const float4* px = smx + r * 16;
            float a0 = bj, a1 = 0.f;
#pragma unroll
            for (int k4 = 0; k4 < 8; k4++) {
                float4 a = p1[k4];
                a0 += a.x * wn1[4 * k4 + 0] + a.y * wn1[4 * k4 + 1]
                    + a.z * wn1[4 * k4 + 2] + a.w * wn1[4 * k4 + 3];
                float4 b = p2[k4];
                a0 += b.x * wn2[4 * k4 + 0] + b.y * wn2[4 * k4 + 1]
                    + b.z * wn2[4 * k4 + 2] + b.w * wn2[4 * k4 + 3];
                float4 cc = px[k4];
                a0 += cc.x * wrs[4 * k4 + 0] + cc.y * wrs[4 * k4 + 1]
                    + cc.z * wrs[4 * k4 + 2] + cc.w * wrs[4 * k4 + 3];
            }
#pragma unroll
            for (int k4 = 8; k4 < 16; k4++) {
                float4 a = p1[k4];
                a1 += a.x * wn1[4 * k4 + 0] + a.y * wn1[4 * k4 + 1]
                    + a.z * wn1[4 * k4 + 2] + a.w * wn1[4 * k4 + 3];
                float4 b = p2[k4];
                a1 += b.x * wn2[4 * k4 + 0] + b.y * wn2[4 * k4 + 1]
                    + b.z * wn2[4 * k4 + 2] + b.w * wn2[4 * k4 + 3];
                float4 cc = px[k4];
                a1 += cc.x * wrs[4 * k4 + 0] + cc.y * wrs[4 * k4 + 1]
                    + cc.z * wrs[4 * k4 + 2] + cc.w * wrs[4 * k4 + 3];
            }
            h[rr] = a0 + a1;
        }
    } else {
        // ---------- B side: m0@Wn0 + x@Wr0 + b0
        row0 = (blockIdx.x - nbA) * 32;
        outX = outB;
        float4* smm = sbuf;
        float4* smx = sbuf + 1024;
        for (int i = threadIdx.x; i < 512; i += 256) {
            smm[i] = __ldg((const float4*)g_m0 + (size_t)row0 * 16 + i);
            smx[i] = __ldg((const float4*)xB + (size_t)row0 * 16 + i);
        }
        float wn[64], wr[64];
#pragma unroll
        for (int k = 0; k < 64; k++) {
            wn[k] = __ldg(Wn + k * 64 + j);
            wr[k] = __ldg(Wr + k * 64 + j);
        }
        float bj = __ldg(bias + j);
        __syncthreads();
#pragma unroll
        for (int rr = 0; rr < 8; rr++) {
            int r = rg * 8 + rr;
            const float4* pm = smm + r * 16;
            const float4* px = smx + r * 16;
            float a0 = bj, a1 = 0.f;
#pragma unroll
            for (int k4 = 0; k4 < 8; k4++) {
                float4 a = pm[k4];
                a0 += a.x * wn[4 * k4 + 0] + a.y * wn[4 * k4 + 1]
                    + a.z * wn[4 * k4 + 2] + a.w * wn[4 * k4 + 3];
                float4 bv = px[k4];
                a0 += bv.x * wr[4 * k4 + 0] + bv.y * wr[4 * k4 + 1]
                    + bv.z * wr[4 * k4 + 2] + bv.w * wr[4 * k4 + 3];
            }
#pragma unroll
            for (int k4 = 8; k4 < 16; k4++) {
                float4 a = pm[k4];
                a1 += a.x * wn[4 * k4 + 0] + a.y * wn[4 * k4 + 1]
                    + a.z * wn[4 * k4 + 2] + a.w * wn[4 * k4 + 3];
                float4 bv = px[k4];
                a1 += bv.x * wr[4 * k4 + 0] + bv.y * wr[4 * k4 + 1]
                    + bv.z * wr[4 * k4 + 2] + bv.w * wr[4 * k4 + 3];
            }
            h[rr] = a0 + a1;
        }
    }

    if (!HEAD) {
#pragma unroll
        for (int rr = 0; rr < 8; rr++)
            outX[(size_t)(row0 + rg * 8 + rr) * 64 + j] = h[rr];
    } else {
        // ---------- fused head: out = relu(h @ Wout + bout), h staged in smem
        __syncthreads();
        float* hb = (float*)sbuf;
#pragma unroll
        for (int rr = 0; rr < 8; rr++)
            hb[(rg * 8 + rr) * 64 + j] = h[rr];
        float w[64];
#pragma unroll
        for (int k = 0; k < 64; k++) w[k] = __ldg(Wout + k * 64 + j);
        float bj2 = __ldg(bout + j);
        __syncthreads();
#pragma unroll
        for (int rr = 0; rr < 8; rr++) {
            int r = rg * 8 + rr;
            const float4* ph = (const float4*)(hb + r * 64);
            float a0 = bj2, a1 = 0.f;
#pragma unroll
            for (int k4 = 0; k4 < 8; k4++) {
                float4 cc = ph[k4];
                a0 += cc.x * w[4 * k4 + 0] + cc.y * w[4 * k4 + 1]
                    + cc.z * w[4 * k4 + 2] + cc.w * w[4 * k4 + 3];
            }
#pragma unroll
            for (int k4 = 8; k4 < 16; k4++) {
                float4 cc = ph[k4];
                a1 += cc.x * w[4 * k4 + 0] + cc.y * w[4 * k4 + 1]
                    + cc.z * w[4 * k4 + 2] + cc.w * w[4 * k4 + 3];
            }
            outX[(size_t)(row0 + r) * 64 + j] = fmaxf(a0 + a1, 0.0f);
        }
    }
}

// ---------------- launcher --------------------------------------------------
extern "C" void kernel_launch(void* const* d_in, const int* in_sizes, int n_in,
                              void* d_out, int out_size) {
    const float* x_A   = (const float*)d_in[0];
    const float* x_B   = (const float*)d_in[1];
    const float* Wn    = (const float*)d_in[2];   // [2,3,64,64]
    const float* Wr    = (const float*)d_in[3];   // [2,3,64,64]
    const float* b     = (const float*)d_in[4];   // [2,3,64]
    const float* W_out = (const float*)d_in[5];   // [64,64]
    const float* b_out = (const float*)d_in[6];   // [64]
    const int* src0 = (const int*)d_in[7];
    const int* dst0 = (const int*)d_in[8];
    const int* src1 = (const int*)d_in[9];
    const int* dst1 = (const int*)d_in[10];
    const int* src2 = (const int*)d_in[11];
    const int* dst2 = (const int*)d_in[12];
    const int E0 = in_sizes[7];
    const int E1 = in_sizes[9];
    const int E2 = in_sizes[11];
    float* out = (float*)d_out;

    float *A1, *B1;
    int *cnt0, *cnt1, *cnt2;
    cudaGetSymbolAddress((void**)&A1, g_A1);
    cudaGetSymbolAddress((void**)&B1, g_B1);
    cudaGetSymbolAddress((void**)&cnt0, g_cnt0);
    cudaGetSymbolAddress((void**)&cnt1, g_cnt1);
    cudaGetSymbolAddress((void**)&cnt2, g_cnt2);

    const int nbA = NA / 32;  // 3125
    const int nbB = NB / 32;  // 3125
    const int nb0 = NB / 32, nb1 = NA / 32, nb2 = NA / 32;
    const int gatherBlocks = nb0 + nb1 + nb2;

    // ---- CSR build (shared by both layers) ----
    cudaMemsetAsync(cnt0, 0, NB * sizeof(int));
    cudaMemsetAsync(cnt1, 0, NA * sizeof(int));
    cudaMemsetAsync(cnt2, 0, NA * sizeof(int));
    hist_kernel<<<1024, 256>>>(dst0, dst1, dst2, E0, E1, E2);
    scan_kernel<<<3, 1024>>>(E0, E1, E2);
    scatter_kernel<<<1024, 256>>>(src0, dst0, src1, dst1, src2, dst2, E0, E1, E2);

    // ---- layer 0 ----
    gather_kernel<<<gatherBlocks, 256>>>(x_A, x_B, nb0, nb0 + nb1);
    combine_kernel<false><<<nbA + nbB, 256>>>(x_A, x_B, Wn, Wr, b,
                                              nullptr, nullptr, A1, B1, nbA);

    // ---- layer 1 ----
    gather_kernel<<<gatherBlocks, 256>>>(A1, B1, nb0, nb0 + nb1);
    combine_kernel<true><<<nbA + nbB, 256>>>(A1, B1,
                                             Wn + 3 * 4096, Wr + 3 * 4096, b + 3 * 64,
                                             W_out, b_out,
                                             out, out + (size_t)NA * 64, nbA);
}

// round 7
// speedup vs baseline: 1.5147x; 1.2113x over previous
#include <cuda_runtime.h>
#include <cstddef>

#define NA 100000
#define NB 100000
#define DD 64
#define EMAX 1250000
#define NCH 49          // chunks of 2048 nodes: 49*2048 >= 100000

// ---------------- scratch (device globals: no allocation allowed) ----------
__device__ int g_cnt0[NB], g_cnt1[NA], g_cnt2[NA];
__device__ int g_ptr0[NB + 1], g_ptr1[NA + 1], g_ptr2[NA + 1];
__device__ int g_wofs0[NB], g_wofs1[NA], g_wofs2[NA];
__device__ int g_col0[EMAX], g_col1[EMAX], g_col2[EMAX];
__device__ int g_csum[3 * 64];
__device__ float g_m0[NB * DD];
__device__ float g_m1[NA * DD];
__device__ float g_m2[NA * DD];
__device__ float g_A1[NA * DD];
__device__ float g_B1[NB * DD];
// per-layer prepped weights: [l][5][64*64] = Wn_A1, Wn_A2, Wr_Asum, Wn_B, Wr_B
__device__ float g_W[2][5 * 4096];
__device__ float g_bias[2][128];   // [l][0:64]=A bias, [64:128]=B bias

// ---------------- CSR build: histogram --------------------------------------
__global__ void hist_kernel(const int* __restrict__ d0,
                            const int* __restrict__ d1,
                            const int* __restrict__ d2,
                            int E0, int E1, int E2) {
    int i = blockIdx.x * blockDim.x + threadIdx.x;
    int stride = gridDim.x * blockDim.x;
    for (int e = i; e < E0; e += stride) atomicAdd(&g_cnt0[__ldg(d0 + e)], 1);
    for (int e = i; e < E1; e += stride) atomicAdd(&g_cnt1[__ldg(d1 + e)], 1);
    for (int e = i; e < E2; e += stride) atomicAdd(&g_cnt2[__ldg(d2 + e)], 1);
}

// ---------------- CSR build: parallel 3-phase scan ---------------------------
__global__ void chunk_sum_kernel() {
    int type = blockIdx.x / NCH, ch = blockIdx.x % NCH;
    const int* cnt = (type == 0) ? g_cnt0 : (type == 1) ? g_cnt1 : g_cnt2;
    int N = (type == 0) ? NB : NA;
    int i0 = ch * 2048 + threadIdx.x * 8;
    int s = 0;
#pragma unroll
    for (int k = 0; k < 8; k++) {
        int i = i0 + k;
        if (i < N) s += cnt[i];
    }
    __shared__ int red[256];
    red[threadIdx.x] = s;
    __syncthreads();
    for (int o = 128; o > 0; o >>= 1) {
        if (threadIdx.x < o) red[threadIdx.x] += red[threadIdx.x + o];
        __syncthreads();
    }
    if (threadIdx.x == 0) g_csum[type * 64 + ch] = red[0];
}

__global__ void scan_csum_kernel(int E0, int E1, int E2) {
    int t = threadIdx.x;
    if (t < 3) {
        int run = 0;
        for (int ch = 0; ch < NCH; ch++) {
            int v = g_csum[t * 64 + ch];
            g_csum[t * 64 + ch] = run;
            run += v;
        }
        if (t == 0) g_ptr0[NB] = E0;
        if (t == 1) g_ptr1[NA] = E1;
        if (t == 2) g_ptr2[NA] = E2;
    }
}

__global__ void write_ptr_kernel() {
    int type = blockIdx.x / NCH, ch = blockIdx.x % NCH;
    const int* cnt; int* ptr; int* wofs; int N;
    if (type == 0)      { cnt = g_cnt0; ptr = g_ptr0; wofs = g_wofs0; N = NB; }
    else if (type == 1) { cnt = g_cnt1; ptr = g_ptr1; wofs = g_wofs1; N = NA; }
    else                { cnt = g_cnt2; ptr = g_ptr2; wofs = g_wofs2; N = NA; }
    int i0 = ch * 2048 + threadIdx.x * 8;
    int c[8];
    int s = 0;
#pragma unroll
    for (int k = 0; k < 8; k++) {
        int i = i0 + k;
        c[k] = (i < N) ? cnt[i] : 0;
        s += c[k];
    }
    __shared__ int sd[256];
    sd[threadIdx.x] = s;
    __syncthreads();
    for (int o = 1; o < 256; o <<= 1) {
        int v = (threadIdx.x >= o) ? sd[threadIdx.x - o] : 0;
        __syncthreads();
        sd[threadIdx.x] += v;
        __syncthreads();
    }
    int base = g_csum[type * 64 + ch] + sd[threadIdx.x] - s;
#pragma unroll
    for (int k = 0; k < 8; k++) {
        int i = i0 + k;
        if (i < N) {
            ptr[i] = base;
            wofs[i] = base;
            base += c[k];
        }
    }
}

// ---------------- CSR build: scatter src ids into dst-sorted order ----------
__global__ void scatter_kernel(const int* __restrict__ s0, const int* __restrict__ d0,
                               const int* __restrict__ s1, const int* __restrict__ d1,
                               const int* __restrict__ s2, const int* __restrict__ d2,
                               int E0, int E1, int E2) {
    int i = blockIdx.x * blockDim.x + threadIdx.x;
    int stride = gridDim.x * blockDim.x;
    for (int e = i; e < E0; e += stride) {
        int p = atomicAdd(&g_wofs0[__ldg(d0 + e)], 1);
        g_col0[p] = __ldg(s0 + e);
    }
    for (int e = i; e < E1; e += stride) {
        int p = atomicAdd(&g_wofs1[__ldg(d1 + e)], 1);
        g_col1[p] = __ldg(s1 + e);
    }
    for (int e = i; e < E2; e += stride) {
        int p = atomicAdd(&g_wofs2[__ldg(d2 + e)], 1);
        g_col2[p] = __ldg(s2 + e);
    }
}

// ---------------- weight prep: layer-0 copy/sum; layer-1 folded with W_out --
// blocks 0..9: matrix m of layer l (l=blk/5, m=blk%5); block 10: biases.
__global__ void prep_kernel(const float* __restrict__ Wn, const float* __restrict__ Wr,
                            const float* __restrict__ b,
                            const float* __restrict__ Wout, const float* __restrict__ bout) {
    if (blockIdx.x < 10) {
        int l = blockIdx.x / 5, m = blockIdx.x % 5;
        __shared__ float S[4096];
        // source matrix (summed where needed)
        const float* base = nullptr;
        for (int i = threadIdx.x; i < 4096; i += blockDim.x) {
            float v;
            if (m == 0)      v = Wn[(l * 3 + 1) * 4096 + i];
            else if (m == 1) v = Wn[(l * 3 + 2) * 4096 + i];
            else if (m == 2) v = Wr[(l * 3 + 1) * 4096 + i] + Wr[(l * 3 + 2) * 4096 + i];
            else if (m == 3) v = Wn[(l * 3 + 0) * 4096 + i];
            else             v = Wr[(l * 3 + 0) * 4096 + i];
            S[i] = v;
        }
        __syncthreads();
        float* dst = g_W[l] + m * 4096;
        if (l == 0) {
            for (int i = threadIdx.x; i < 4096; i += blockDim.x) dst[i] = S[i];
        } else {
            // folded: dst = S @ Wout
            for (int o = threadIdx.x; o < 4096; o += blockDim.x) {
                int i = o >> 6, j = o & 63;
                float acc = 0.f;
#pragma unroll 16
                for (int k = 0; k < 64; k++)
                    acc += S[i * 64 + k] * __ldg(Wout + k * 64 + j);
                dst[o] = acc;
            }
        }
    } else {
        // biases
        int j = threadIdx.x;
        if (j < 64) {
            g_bias[0][j]      = b[1 * 64 + j] + b[2 * 64 + j];  // layer0 A
            g_bias[0][64 + j] = b[j];                           // layer0 B
            float accA = 0.f, accB = 0.f;
            for (int k = 0; k < 64; k++) {
                float w = __ldg(Wout + k * 64 + j);
                accA += (b[4 * 64 + k] + b[5 * 64 + k]) * w;
                accB += b[3 * 64 + k] * w;
            }
            g_bias[1][j]      = accA + bout[j];                 // layer1 A (folded)
            g_bias[1][64 + j] = accB + bout[j];                 // layer1 B (folded)
        }
    }
}

// ---------------- standalone atomic-free CSR gather (mean) ------------------
__global__ __launch_bounds__(256, 6)
void gather_kernel(const float* __restrict__ xA, const float* __restrict__ xB,
                   int nb0, int nb01) {
    int bid = blockIdx.x;
    const float* x; const int* ptr; const int* col; float* m; int row0;
    if (bid < nb0)       { row0 = bid * 32;          x = xA; ptr = g_ptr0; col = g_col0; m = g_m0; }
    else if (bid < nb01) { row0 = (bid - nb0) * 32;  x = xB; ptr = g_ptr1; col = g_col1; m = g_m1; }
    else                 { row0 = (bid - nb01) * 32; x = xA; ptr = g_ptr2; col = g_col2; m = g_m2; }

    int g = threadIdx.x >> 3;
    int c = threadIdx.x & 7;
    int n = row0 + g;
    int beg = __ldg(ptr + n), end = __ldg(ptr + n + 1);
    float4 a0 = make_float4(0.f, 0.f, 0.f, 0.f);
    float4 a1 = make_float4(0.f, 0.f, 0.f, 0.f);
    int k = beg;
    int s0 = 0, s1 = 0;
    if (k < end) s0 = __ldg(col + k);
    if (k + 1 < end) s1 = __ldg(col + k + 1);
    while (k + 1 < end) {
        int ns0 = 0, ns1 = 0;
        if (k + 2 < end) ns0 = __ldg(col + k + 2);
        if (k + 3 < end) ns1 = __ldg(col + k + 3);
        const float4* f0 = (const float4*)x + (size_t)s0 * 16 + c * 2;
        const float4* f1 = (const float4*)x + (size_t)s1 * 16 + c * 2;
        float4 u0 = __ldg(f0), v0 = __ldg(f0 + 1);
        float4 u1 = __ldg(f1), v1 = __ldg(f1 + 1);
        a0.x += u0.x + u1.x; a0.y += u0.y + u1.y;
        a0.z += u0.z + u1.z; a0.w += u0.w + u1.w;
        a1.x += v0.x + v1.x; a1.y += v0.y + v1.y;
        a1.z += v0.z + v1.z; a1.w += v0.w + v1.w;
        s0 = ns0; s1 = ns1; k += 2;
    }
    if (k < end) {
        const float4* f0 = (const float4*)x + (size_t)s0 * 16 + c * 2;
        float4 u0 = __ldg(f0), v0 = __ldg(f0 + 1);
        a0.x += u0.x; a0.y += u0.y; a0.z += u0.z; a0.w += u0.w;
        a1.x += v0.x; a1.y += v0.y; a1.z += v0.z; a1.w += v0.w;
    }
    float inv = 1.0f / fmaxf((float)(end - beg), 1.0f);
    a0.x *= inv; a0.y *= inv; a0.z *= inv; a0.w *= inv;
    a1.x *= inv; a1.y *= inv; a1.z *= inv; a1.w *= inv;
    float4* mo = (float4*)m + (size_t)n * 16 + c * 2;
    mo[0] = a0;
    mo[1] = a1;
}

// ---------------- combine: 64 rows/block, weights in regs, direct stores ----
// A-side: m1@W0 + m2@W1 + x@W2 + bias[0:64]; B-side: m0@W3 + x@W4 + bias[64:128]
template<bool RELU>
__global__ __launch_bounds__(256) void combine_kernel(
    const float* __restrict__ xA, const float* __restrict__ xB,
    const float* __restrict__ Wl, const float* __restrict__ bl,
    float* __restrict__ outA, float* __restrict__ outB, int nbA) {
    __shared__ float4 sbuf[3 * 1024];   // 48KB
    const int j = threadIdx.x & 63;
    const int rg = threadIdx.x >> 6;

    if (blockIdx.x < nbA) {
        int row0 = blockIdx.x * 64;
        int rows = NA - row0 < 64 ? NA - row0 : 64;
        float4* sm1 = sbuf;
        float4* sm2 = sbuf + 1024;
        float4* smx = sbuf + 2048;
        for (int i = threadIdx.x; i < rows * 16; i += 256) {
            sm1[i] = __ldg((const float4*)g_m1 + (size_t)row0 * 16 + i);
            sm2[i] = __ldg((const float4*)g_m2 + (size_t)row0 * 16 + i);
            smx[i] = __ldg((const float4*)xA + (size_t)row0 * 16 + i);
        }
        float wn1[64], wn2[64], wrs[64];
#pragma unroll
        for (int k = 0; k < 64; k++) {
            wn1[k] = __ldg(Wl + k * 64 + j);
            wn2[k] = __ldg(Wl + 4096 + k * 64 + j);
            wrs[k] = __ldg(Wl + 8192 + k * 64 + j);
        }
        float bj = __ldg(bl + j);
        __syncthreads();
#pragma unroll
        for (int rr = 0; rr < 16; rr++) {
            int r = rg * 16 + rr;
            if (r < rows) {
                const float4* p1 = sm1 + r * 16;
                const float4* p2 = sm2 + r * 16;
                const float4* px = smx + r * 16;
                float a0 = bj, a1 = 0.f;
#pragma unroll
                for (int k4 = 0; k4 < 8; k4++) {
                    float4 a = p1[k4];
                    a0 += a.x * wn1[4 * k4 + 0] + a.y * wn1[4 * k4 + 1]
                        + a.z * wn1[4 * k4 + 2] + a.w * wn1[4 * k4 + 3];
                    float4 b = p2[k4];
                    a0 += b.x * wn2[4 * k4 + 0] + b.y * wn2[4 * k4 + 1]
                        + b.z * wn2[4 * k4 + 2] + b.w * wn2[4 * k4 + 3];
                    float4 cc = px[k4];
                    a0 += cc.x * wrs[4 * k4 + 0] + cc.y * wrs[4 * k4 + 1]
                        + cc.z * wrs[4 * k4 + 2] + cc.w * wrs[4 * k4 + 3];
                }
#pragma unroll
                for (int k4 = 8; k4 < 16; k4++) {
                    float4 a = p1[k4];
                    a1 += a.x * wn1[4 * k4 + 0] + a.y * wn1[4 * k4 + 1]
                        + a.z * wn1[4 * k4 + 2] + a.w * wn1[4 * k4 + 3];
                    float4 b = p2[k4];
                    a1 += b.x * wn2[4 * k4 + 0] + b.y * wn2[4 * k4 + 1]
                        + b.z * wn2[4 * k4 + 2] + b.w * wn2[4 * k4 + 3];
                    float4 cc = px[k4];
                    a1 += cc.x * wrs[4 * k4 + 0] + cc.y * wrs[4 * k4 + 1]
                        + cc.z * wrs[4 * k4 + 2] + cc.w * wrs[4 * k4 + 3];
                }
                float v = a0 + a1;
                outA[(size_t)(row0 + r) * 64 + j] = RELU ? fmaxf(v, 0.0f) : v;
            }
        }
    } else {
        int row0 = (blockIdx.x - nbA) * 64;
        int rows = NB - row0 < 64 ? NB - row0 : 64;
        float4* smm = sbuf;
        float4* smx = sbuf + 1024;
        for (int i = threadIdx.x; i < rows * 16; i += 256) {
            smm[i] = __ldg((const float4*)g_m0 + (size_t)row0 * 16 + i);
            smx[i] = __ldg((const float4*)xB + (size_t)row0 * 16 + i);
        }
        float wn[64], wr[64];
#pragma unroll
        for (int k = 0; k < 64; k++) {
            wn[k] = __ldg(Wl + 3 * 4096 + k * 64 + j);
            wr[k] = __ldg(Wl + 4 * 4096 + k * 64 + j);
        }
        float bj = __ldg(bl + 64 + j);
        __syncthreads();
#pragma unroll
        for (int rr = 0; rr < 16; rr++) {
            int r = rg * 16 + rr;
            if (r < rows) {
                const float4* pm = smm + r * 16;
                const float4* px = smx + r * 16;
                float a0 = bj, a1 = 0.f;
#pragma unroll
                for (int k4 = 0; k4 < 8; k4++) {
                    float4 a = pm[k4];
                    a0 += a.x * wn[4 * k4 + 0] + a.y * wn[4 * k4 + 1]
                        + a.z * wn[4 * k4 + 2] + a.w * wn[4 * k4 + 3];
                    float4 bv = px[k4];
                    a0 += bv.x * wr[4 * k4 + 0] + bv.y * wr[4 * k4 + 1]
                        + bv.z * wr[4 * k4 + 2] + bv.w * wr[4 * k4 + 3];
                }
#pragma unroll
                for (int k4 = 8; k4 < 16; k4++) {
                    float4 a = pm[k4];
                    a1 += a.x * wn[4 * k4 + 0] + a.y * wn[4 * k4 + 1]
                        + a.z * wn[4 * k4 + 2] + a.w * wn[4 * k4 + 3];
                    float4 bv = px[k4];
                    a1 += bv.x * wr[4 * k4 + 0] + bv.y * wr[4 * k4 + 1]
                        + bv.z * wr[4 * k4 + 2] + bv.w * wr[4 * k4 + 3];
                }
                float v = a0 + a1;
                outB[(size_t)(row0 + r) * 64 + j] = RELU ? fmaxf(v, 0.0f) : v;
            }
        }
    }
}

// ---------------- launcher --------------------------------------------------
extern "C" void kernel_launch(void* const* d_in, const int* in_sizes, int n_in,
                              void* d_out, int out_size) {
    const float* x_A   = (const float*)d_in[0];
    const float* x_B   = (const float*)d_in[1];
    const float* Wn    = (const float*)d_in[2];
    const float* Wr    = (const float*)d_in[3];
    const float* b     = (const float*)d_in[4];
    const float* W_out = (const float*)d_in[5];
    const float* b_out = (const float*)d_in[6];
    const int* src0 = (const int*)d_in[7];
    const int* dst0 = (const int*)d_in[8];
    const int* src1 = (const int*)d_in[9];
    const int* dst1 = (const int*)d_in[10];
    const int* src2 = (const int*)d_in[11];
    const int* dst2 = (const int*)d_in[12];
    const int E0 = in_sizes[7];
    const int E1 = in_sizes[9];
    const int E2 = in_sizes[11];
    float* out = (float*)d_out;

    float *A1, *B1, *W0, *W1, *bias0, *bias1;
    int *cnt0, *cnt1, *cnt2;
    cudaGetSymbolAddress((void**)&A1, g_A1);
    cudaGetSymbolAddress((void**)&B1, g_B1);
    cudaGetSymbolAddress((void**)&cnt0, g_cnt0);
    cudaGetSymbolAddress((void**)&cnt1, g_cnt1);
    cudaGetSymbolAddress((void**)&cnt2, g_cnt2);
    cudaGetSymbolAddress((void**)&W0, g_W);
    W1 = W0 + 5 * 4096;
    cudaGetSymbolAddress((void**)&bias0, g_bias);
    bias1 = bias0 + 128;

    const int nb0 = NB / 32, nb1 = NA / 32, nb2 = NA / 32;
    const int gatherBlocks = nb0 + nb1 + nb2;
    const int nbA = (NA + 63) / 64;  // 1563
    const int nbB = (NB + 63) / 64;

    // ---- weight prep (independent of CSR) ----
    prep_kernel<<<11, 256>>>(Wn, Wr, b, W_out, b_out);

    // ---- CSR build ----
    cudaMemsetAsync(cnt0, 0, NB * sizeof(int));
    cudaMemsetAsync(cnt1, 0, NA * sizeof(int));
    cudaMemsetAsync(cnt2, 0, NA * sizeof(int));
    hist_kernel<<<1024, 256>>>(dst0, dst1, dst2, E0, E1, E2);
    chunk_sum_kernel<<<3 * NCH, 256>>>();
    scan_csum_kernel<<<1, 32>>>(E0, E1, E2);
    write_ptr_kernel<<<3 * NCH, 256>>>();
    scatter_kernel<<<1024, 256>>>(src0, dst0, src1, dst1, src2, dst2, E0, E1, E2);

    // ---- layer 0 ----
    gather_kernel<<<gatherBlocks, 256>>>(x_A, x_B, nb0, nb0 + nb1);
    combine_kernel<false><<<nbA + nbB, 256>>>(x_A, x_B, W0, bias0, A1, B1, nbA);

    // ---- layer 1 (head folded into weights; relu at store) ----
    gather_kernel<<<gatherBlocks, 256>>>(A1, B1, nb0, nb0 + nb1);
    combine_kernel<true><<<nbA + nbB, 256>>>(A1, B1, W1, bias1,
                                             out, out + (size_t)NA * 64, nbA);
}

// round 8
// speedup vs baseline: 1.7134x; 1.1312x over previous
#include <cuda_runtime.h>
#include <cstddef>

#define NA 100000
#define NB 100000
#define DD 64
#define EMAX 1250000
#define NCH 49          // chunks of 2048 nodes: 49*2048 >= 100000

typedef unsigned long long ull;

// packed f32x2 helpers (sm_100+)
#define FMA2(d, a, b, c) asm("fma.rn.f32x2 %0, %1, %2, %3;" : "=l"(d) : "l"(a), "l"(b), "l"(c))
#define ADD2(d, a, b)    asm("add.rn.f32x2 %0, %1, %2;"     : "=l"(d) : "l"(a), "l"(b))
#define MUL2(d, a, b)    asm("mul.rn.f32x2 %0, %1, %2;"     : "=l"(d) : "l"(a), "l"(b))
#define PK2(d, lo, hi)   asm("mov.b64 %0, {%1, %2};"        : "=l"(d) : "f"(lo), "f"(hi))
#define UPK2(lo, hi, s)  asm("mov.b64 {%0, %1}, %2;"        : "=f"(lo), "=f"(hi) : "l"(s))

// ---------------- scratch (device globals: no allocation allowed) ----------
__device__ int g_cnt0[NB], g_cnt1[NA], g_cnt2[NA];
__device__ int g_ptr0[NB + 1], g_ptr1[NA + 1], g_ptr2[NA + 1];
__device__ int g_wofs0[NB], g_wofs1[NA], g_wofs2[NA];
__device__ int g_col0[EMAX], g_col1[EMAX], g_col2[EMAX];
__device__ int g_csum[3 * 64];
__device__ float g_m0[NB * DD];
__device__ float g_m1[NA * DD];
__device__ float g_m2[NA * DD];
__device__ float g_A1[NA * DD];
__device__ float g_B1[NB * DD];
// per-layer prepped PAIR-PACKED weights: [l][5][2048 float2] =
//   Wn_A1, Wn_A2, Wr_Asum, Wn_B, Wr_B ; layer1 pre-folded with W_out
__device__ float g_W[2][5 * 4096];
__device__ float g_bias[2][128];   // [l][0:64]=A bias, [64:128]=B bias

// ---------------- CSR build: histogram --------------------------------------
__global__ void hist_kernel(const int* __restrict__ d0,
                            const int* __restrict__ d1,
                            const int* __restrict__ d2,
                            int E0, int E1, int E2) {
    int i = blockIdx.x * blockDim.x + threadIdx.x;
    int stride = gridDim.x * blockDim.x;
    for (int e = i; e < E0; e += stride) atomicAdd(&g_cnt0[__ldg(d0 + e)], 1);
    for (int e = i; e < E1; e += stride) atomicAdd(&g_cnt1[__ldg(d1 + e)], 1);
    for (int e = i; e < E2; e += stride) atomicAdd(&g_cnt2[__ldg(d2 + e)], 1);
}

// ---------------- CSR build: chunk sums -------------------------------------
__global__ void chunk_sum_kernel() {
    int type = blockIdx.x / NCH, ch = blockIdx.x % NCH;
    const int* cnt = (type == 0) ? g_cnt0 : (type == 1) ? g_cnt1 : g_cnt2;
    int N = (type == 0) ? NB : NA;
    int i0 = ch * 2048 + threadIdx.x * 8;
    int s = 0;
#pragma unroll
    for (int k = 0; k < 8; k++) {
        int i = i0 + k;
        if (i < N) s += cnt[i];
    }
    __shared__ int red[256];
    red[threadIdx.x] = s;
    __syncthreads();
    for (int o = 128; o > 0; o >>= 1) {
        if (threadIdx.x < o) red[threadIdx.x] += red[threadIdx.x + o];
        __syncthreads();
    }
    if (threadIdx.x == 0) g_csum[type * 64 + ch] = red[0];
}

// ---------------- CSR build: write ptr (chunk prefix computed in-block) -----
__global__ void write_ptr_kernel(int E0, int E1, int E2) {
    int type = blockIdx.x / NCH, ch = blockIdx.x % NCH;
    const int* cnt; int* ptr; int* wofs; int N;
    if (type == 0)      { cnt = g_cnt0; ptr = g_ptr0; wofs = g_wofs0; N = NB; }
    else if (type == 1) { cnt = g_cnt1; ptr = g_ptr1; wofs = g_wofs1; N = NA; }
    else                { cnt = g_cnt2; ptr = g_ptr2; wofs = g_wofs2; N = NA; }

    if (threadIdx.x == 0 && ch == 0) {
        if (type == 0) g_ptr0[NB] = E0;
        else if (type == 1) g_ptr1[NA] = E1;
        else g_ptr2[NA] = E2;
    }

    int cbase = 0;
    for (int c2 = 0; c2 < ch; c2++) cbase += __ldg(&g_csum[type * 64 + c2]);

    int i0 = ch * 2048 + threadIdx.x * 8;
    int c[8];
    int s = 0;
#pragma unroll
    for (int k = 0; k < 8; k++) {
        int i = i0 + k;
        c[k] = (i < N) ? cnt[i] : 0;
        s += c[k];
    }
    __shared__ int sd[256];
    sd[threadIdx.x] = s;
    __syncthreads();
    for (int o = 1; o < 256; o <<= 1) {
        int v = (threadIdx.x >= o) ? sd[threadIdx.x - o] : 0;
        __syncthreads();
        sd[threadIdx.x] += v;
        __syncthreads();
    }
    int base = cbase + sd[threadIdx.x] - s;
#pragma unroll
    for (int k = 0; k < 8; k++) {
        int i = i0 + k;
        if (i < N) {
            ptr[i] = base;
            wofs[i] = base;
            base += c[k];
        }
    }
}

// ---------------- CSR build: scatter src ids into dst-sorted order ----------
__global__ void scatter_kernel(const int* __restrict__ s0, const int* __restrict__ d0,
                               const int* __restrict__ s1, const int* __restrict__ d1,
                               const int* __restrict__ s2, const int* __restrict__ d2,
                               int E0, int E1, int E2) {
    int i = blockIdx.x * blockDim.x + threadIdx.x;
    int stride = gridDim.x * blockDim.x;
    for (int e = i; e < E0; e += stride) {
        int p = atomicAdd(&g_wofs0[__ldg(d0 + e)], 1);
        g_col0[p] = __ldg(s0 + e);
    }
    for (int e = i; e < E1; e += stride) {
        int p = atomicAdd(&g_wofs1[__ldg(d1 + e)], 1);
        g_col1[p] = __ldg(s1 + e);
    }
    for (int e = i; e < E2; e += stride) {
        int p = atomicAdd(&g_wofs2[__ldg(d2 + e)], 1);
        g_col2[p] = __ldg(s2 + e);
    }
}

// ---------------- weight prep: fold + PAIR-PACK -----------------------------
// blocks 0..9: matrix m of layer l; block 10: biases.
// Output layout per matrix: float2 dst[k2*64 + j] = {W[2k2][j], W[2k2+1][j]}
__global__ void prep_kernel(const float* __restrict__ Wn, const float* __restrict__ Wr,
                            const float* __restrict__ b,
                            const float* __restrict__ Wout, const float* __restrict__ bout) {
    if (blockIdx.x < 10) {
        int l = blockIdx.x / 5, m = blockIdx.x % 5;
        __shared__ float S[4096];
        __shared__ float T[4096];
        for (int i = threadIdx.x; i < 4096; i += blockDim.x) {
            float v;
            if (m == 0)      v = Wn[(l * 3 + 1) * 4096 + i];
            else if (m == 1) v = Wn[(l * 3 + 2) * 4096 + i];
            else if (m == 2) v = Wr[(l * 3 + 1) * 4096 + i] + Wr[(l * 3 + 2) * 4096 + i];
            else if (m == 3) v = Wn[(l * 3 + 0) * 4096 + i];
            else             v = Wr[(l * 3 + 0) * 4096 + i];
            S[i] = v;
        }
        __syncthreads();
        const float* src = S;
        if (l == 1) {
            for (int o = threadIdx.x; o < 4096; o += blockDim.x) {
                int i = o >> 6, j = o & 63;
                float acc = 0.f;
#pragma unroll 16
                for (int k = 0; k < 64; k++)
                    acc += S[i * 64 + k] * __ldg(Wout + k * 64 + j);
                T[o] = acc;
            }
            __syncthreads();
            src = T;
        }
        float2* dst = (float2*)(g_W[l] + m * 4096);
        for (int o = threadIdx.x; o < 2048; o += blockDim.x) {
            int k2 = o >> 6, j = o & 63;
            dst[o] = make_float2(src[(2 * k2) * 64 + j], src[(2 * k2 + 1) * 64 + j]);
        }
    } else {
        int j = threadIdx.x;
        if (j < 64) {
            g_bias[0][j]      = b[1 * 64 + j] + b[2 * 64 + j];
            g_bias[0][64 + j] = b[j];
            float accA = 0.f, accB = 0.f;
            for (int k = 0; k < 64; k++) {
                float w = __ldg(Wout + k * 64 + j);
                accA += (b[4 * 64 + k] + b[5 * 64 + k]) * w;
                accB += b[3 * 64 + k] * w;
            }
            g_bias[1][j]      = accA + bout[j];
            g_bias[1][64 + j] = accB + bout[j];
        }
    }
}

// ---------------- standalone atomic-free CSR gather (mean, f32x2 adds) ------
__global__ __launch_bounds__(256, 6)
void gather_kernel(const float* __restrict__ xA, const float* __restrict__ xB,
                   int nb0, int nb01) {
    int bid = blockIdx.x;
    const float* x; const int* ptr; const int* col; float* m; int row0;
    if (bid < nb0)       { row0 = bid * 32;          x = xA; ptr = g_ptr0; col = g_col0; m = g_m0; }
    else if (bid < nb01) { row0 = (bid - nb0) * 32;  x = xB; ptr = g_ptr1; col = g_col1; m = g_m1; }
    else                 { row0 = (bid - nb01) * 32; x = xA; ptr = g_ptr2; col = g_col2; m = g_m2; }

    int g = threadIdx.x >> 3;
    int c = threadIdx.x & 7;
    int n = row0 + g;
    int beg = __ldg(ptr + n), end = __ldg(ptr + n + 1);

    ull A0 = 0ULL, A1 = 0ULL, A2 = 0ULL, A3 = 0ULL;
    const ulonglong2* X = (const ulonglong2*)x;
    int k = beg;
    int s0 = 0, s1 = 0;
    if (k < end) s0 = __ldg(col + k);
    if (k + 1 < end) s1 = __ldg(col + k + 1);
    while (k + 1 < end) {
        int ns0 = 0, ns1 = 0;
        if (k + 2 < end) ns0 = __ldg(col + k + 2);
        if (k + 3 < end) ns1 = __ldg(col + k + 3);
        const ulonglong2* f0 = X + (size_t)s0 * 16 + c * 2;
        const ulonglong2* f1 = X + (size_t)s1 * 16 + c * 2;
        ulonglong2 u0 = __ldg(f0), v0 = __ldg(f0 + 1);
        ulonglong2 u1 = __ldg(f1), v1 = __ldg(f1 + 1);
        ull t0, t1, t2, t3;
        ADD2(t0, u0.x, u1.x); ADD2(A0, A0, t0);
        ADD2(t1, u0.y, u1.y); ADD2(A1, A1, t1);
        ADD2(t2, v0.x, v1.x); ADD2(A2, A2, t2);
        ADD2(t3, v0.y, v1.y); ADD2(A3, A3, t3);
        s0 = ns0; s1 = ns1; k += 2;
    }
    if (k < end) {
        const ulonglong2* f0 = X + (size_t)s0 * 16 + c * 2;
        ulonglong2 u0 = __ldg(f0), v0 = __ldg(f0 + 1);
        ADD2(A0, A0, u0.x);
        ADD2(A1, A1, u0.y);
        ADD2(A2, A2, v0.x);
        ADD2(A3, A3, v0.y);
    }
    float inv = 1.0f / fmaxf((float)(end - beg), 1.0f);
    ull inv2; PK2(inv2, inv, inv);
    MUL2(A0, A0, inv2); MUL2(A1, A1, inv2);
    MUL2(A2, A2, inv2); MUL2(A3, A3, inv2);
    ulonglong2* mo = (ulonglong2*)m + (size_t)n * 16 + c * 2;
    ulonglong2 o0; o0.x = A0; o0.y = A1;
    ulonglong2 o1; o1.x = A2; o1.y = A3;
    mo[0] = o0;
    mo[1] = o1;
}

// ---------------- combine: 64 rows/block, pair-packed weights, f32x2 FMA ----
// A-side: m1@W0 + m2@W1 + x@W2 + bias[0:64]; B-side: m0@W3 + x@W4 + bias[64:128]
template<bool RELU>
__global__ __launch_bounds__(256) void combine_kernel(
    const float* __restrict__ xA, const float* __restrict__ xB,
    const float* __restrict__ Wl, const float* __restrict__ bl,
    float* __restrict__ outA, float* __restrict__ outB, int nbA) {
    __shared__ float4 sbuf[3 * 1024];   // 48KB
    const int j = threadIdx.x & 63;
    const int rg = threadIdx.x >> 6;
    const ull* W64 = (const ull*)Wl;

    if (blockIdx.x < nbA) {
        int row0 = blockIdx.x * 64;
        int rows = NA - row0 < 64 ? NA - row0 : 64;
        float4* sm1 = sbuf;
        float4* sm2 = sbuf + 1024;
        float4* smx = sbuf + 2048;
        for (int i = threadIdx.x; i < rows * 16; i += 256) {
            sm1[i] = __ldg((const float4*)g_m1 + (size_t)row0 * 16 + i);
            sm2[i] = __ldg((const float4*)g_m2 + (size_t)row0 * 16 + i);
            smx[i] = __ldg((const float4*)xA + (size_t)row0 * 16 + i);
        }
        ull wn1p[32], wn2p[32], wrsp[32];
#pragma unroll
        for (int k2 = 0; k2 < 32; k2++) {
            wn1p[k2] = __ldg(W64 + 0 * 2048 + k2 * 64 + j);
            wn2p[k2] = __ldg(W64 + 1 * 2048 + k2 * 64 + j);
            wrsp[k2] = __ldg(W64 + 2 * 2048 + k2 * 64 + j);
        }
        float bj = __ldg(bl + j);
        __syncthreads();
#pragma unroll
        for (int rr = 0; rr < 16; rr++) {
            int r = rg * 16 + rr;
            if (r < rows) {
                const ulonglong2* p1 = (const ulonglong2*)(sm1 + r * 16);
                const ulonglong2* p2 = (const ulonglong2*)(sm2 + r * 16);
                const ulonglong2* px = (const ulonglong2*)(smx + r * 16);
                ull acc0, acc1;
                PK2(acc0, bj, 0.0f);
                acc1 = 0ULL;
#pragma unroll
                for (int k4 = 0; k4 < 16; k4++) {
                    ulonglong2 a = p1[k4];
                    FMA2(acc0, a.x, wn1p[2 * k4], acc0);
                    FMA2(acc1, a.y, wn1p[2 * k4 + 1], acc1);
                    ulonglong2 bq = p2[k4];
                    FMA2(acc0, bq.x, wn2p[2 * k4], acc0);
                    FMA2(acc1, bq.y, wn2p[2 * k4 + 1], acc1);
                    ulonglong2 cq = px[k4];
                    FMA2(acc0, cq.x, wrsp[2 * k4], acc0);
                    FMA2(acc1, cq.y, wrsp[2 * k4 + 1], acc1);
                }
                float l0, h0, l1, h1;
                UPK2(l0, h0, acc0);
                UPK2(l1, h1, acc1);
                float v = (l0 + h0) + (l1 + h1);
                outA[(size_t)(row0 + r) * 64 + j] = RELU ? fmaxf(v, 0.0f) : v;
            }
        }
    } else {
        int row0 = (blockIdx.x - nbA) * 64;
        int rows = NB - row0 < 64 ? NB - row0 : 64;
        float4* smm = sbuf;
        float4* smx = sbuf + 1024;
        for (int i = threadIdx.x; i < rows * 16; i += 256) {
            smm[i] = __ldg((const float4*)g_m0 + (size_t)row0 * 16 + i);
            smx[i] = __ldg((const float4*)xB + (size_t)row0 * 16 + i);
        }
        ull wnp[32], wrp[32];
#pragma unroll
        for (int k2 = 0; k2 < 32; k2++) {
            wnp[k2] = __ldg(W64 + 3 * 2048 + k2 * 64 + j);
            wrp[k2] = __ldg(W64 + 4 * 2048 + k2 * 64 + j);
        }
        float bj = __ldg(bl + 64 + j);
        __syncthreads();
#pragma unroll
        for (int rr = 0; rr < 16; rr++) {
            int r = rg * 16 + rr;
            if (r < rows) {
                const ulonglong2* pm = (const ulonglong2*)(smm + r * 16);
                const ulonglong2* px = (const ulonglong2*)(smx + r * 16);
                ull acc0, acc1;
                PK2(acc0, bj, 0.0f);
                acc1 = 0ULL;
#pragma unroll
                for (int k4 = 0; k4 < 16; k4++) {
                    ulonglong2 a = pm[k4];
                    FMA2(acc0, a.x, wnp[2 * k4], acc0);
                    FMA2(acc1, a.y, wnp[2 * k4 + 1], acc1);
                    ulonglong2 bq = px[k4];
                    FMA2(acc0, bq.x, wrp[2 * k4], acc0);
                    FMA2(acc1, bq.y, wrp[2 * k4 + 1], acc1);
                }
                float l0, h0, l1, h1;
                UPK2(l0, h0, acc0);
                UPK2(l1, h1, acc1);
                float v = (l0 + h0) + (l1 + h1);
                outB[(size_t)(row0 + r) * 64 + j] = RELU ? fmaxf(v, 0.0f) : v;
            }
        }
    }
}

// ---------------- launcher --------------------------------------------------
extern "C" void kernel_launch(void* const* d_in, const int* in_sizes, int n_in,
                              void* d_out, int out_size) {
    const float* x_A   = (const float*)d_in[0];
    const float* x_B   = (const float*)d_in[1];
    const float* Wn    = (const float*)d_in[2];
    const float* Wr    = (const float*)d_in[3];
    const float* b     = (const float*)d_in[4];
    const float* W_out = (const float*)d_in[5];
    const float* b_out = (const float*)d_in[6];
    const int* src0 = (const int*)d_in[7];
    const int* dst0 = (const int*)d_in[8];
    const int* src1 = (const int*)d_in[9];
    const int* dst1 = (const int*)d_in[10];
    const int* src2 = (const int*)d_in[11];
    const int* dst2 = (const int*)d_in[12];
    const int E0 = in_sizes[7];
    const int E1 = in_sizes[9];
    const int E2 = in_sizes[11];
    float* out = (float*)d_out;

    float *A1, *B1, *W0, *W1, *bias0, *bias1;
    int *cnt0, *cnt1, *cnt2;
    cudaGetSymbolAddress((void**)&A1, g_A1);
    cudaGetSymbolAddress((void**)&B1, g_B1);
    cudaGetSymbolAddress((void**)&cnt0, g_cnt0);
    cudaGetSymbolAddress((void**)&cnt1, g_cnt1);
    cudaGetSymbolAddress((void**)&cnt2, g_cnt2);
    cudaGetSymbolAddress((void**)&W0, g_W);
    W1 = W0 + 5 * 4096;
    cudaGetSymbolAddress((void**)&bias0, g_bias);
    bias1 = bias0 + 128;

    const int nb0 = NB / 32, nb1 = NA / 32, nb2 = NA / 32;
    const int gatherBlocks = nb0 + nb1 + nb2;
    const int nbA = (NA + 63) / 64;
    const int nbB = (NB + 63) / 64;

    // ---- weight prep (independent of CSR) ----
    prep_kernel<<<11, 256>>>(Wn, Wr, b, W_out, b_out);

    // ---- CSR build ----
    cudaMemsetAsync(cnt0, 0, NB * sizeof(int));
    cudaMemsetAsync(cnt1, 0, NA * sizeof(int));
    cudaMemsetAsync(cnt2, 0, NA * sizeof(int));
    hist_kernel<<<1024, 256>>>(dst0, dst1, dst2, E0, E1, E2);
    chunk_sum_kernel<<<3 * NCH, 256>>>();
    write_ptr_kernel<<<3 * NCH, 256>>>(E0, E1, E2);
    scatter_kernel<<<1024, 256>>>(src0, dst0, src1, dst1, src2, dst2, E0, E1, E2);

    // ---- layer 0 ----
    gather_kernel<<<gatherBlocks, 256>>>(x_A, x_B, nb0, nb0 + nb1);
    combine_kernel<false><<<nbA + nbB, 256>>>(x_A, x_B, W0, bias0, A1, B1, nbA);

    // ---- layer 1 (head folded into weights; relu at store) ----
    gather_kernel<<<gatherBlocks, 256>>>(A1, B1, nb0, nb0 + nb1);
    combine_kernel<true><<<nbA + nbB, 256>>>(A1, B1, W1, bias1,
                                             out, out + (size_t)NA * 64, nbA);
}

// round 9
// speedup vs baseline: 1.7670x; 1.0313x over previous
#include <cuda_runtime.h>
#include <cuda_fp16.h>
#include <cstddef>

#define NA 100000
#define NB 100000
#define DD 64
#define EMAX 1250000
#define NCH 49          // chunks of 2048 nodes: 49*2048 >= 100000

typedef unsigned long long ull;

// packed f32x2 helpers (sm_100+)
#define FMA2(d, a, b, c) asm("fma.rn.f32x2 %0, %1, %2, %3;" : "=l"(d) : "l"(a), "l"(b), "l"(c))
#define PK2(d, lo, hi)   asm("mov.b64 %0, {%1, %2};"        : "=l"(d) : "f"(lo), "f"(hi))
#define UPK2(lo, hi, s)  asm("mov.b64 {%0, %1}, %2;"        : "=f"(lo), "=f"(hi) : "l"(s))

// ---------------- scratch (device globals: no allocation allowed) ----------
__device__ int g_cnt0[NB], g_cnt1[NA], g_cnt2[NA];
__device__ int g_ptr0[NB + 1], g_ptr1[NA + 1], g_ptr2[NA + 1];
__device__ int g_wofs0[NB], g_wofs1[NA], g_wofs2[NA];
__device__ int g_col0[EMAX], g_col1[EMAX], g_col2[EMAX];
__device__ int g_csum[3 * 64];
__device__ float g_m0[NB * DD];
__device__ float g_m1[NA * DD];
__device__ float g_m2[NA * DD];
__device__ float g_A1[NA * DD];
__device__ float g_B1[NB * DD];
// half-precision message features (aligned for uint4 loads)
__device__ __align__(16) __half g_hA[NA * DD];
__device__ __align__(16) __half g_hB[NB * DD];
__device__ __align__(16) __half g_hA1[NA * DD];
__device__ __align__(16) __half g_hB1[NB * DD];
// per-layer prepped PAIR-PACKED weights: [l][5][2048 float2] =
//   Wn_A1, Wn_A2, Wr_Asum, Wn_B, Wr_B ; layer1 pre-folded with W_out
__device__ float g_W[2][5 * 4096];
__device__ float g_bias[2][128];   // [l][0:64]=A bias, [64:128]=B bias

// ---------------- fp32 -> fp16 feature conversion ----------------------------
__global__ void conv_kernel(const float* __restrict__ xA, const float* __restrict__ xB) {
    int i = blockIdx.x * blockDim.x + threadIdx.x;
    int stride = gridDim.x * blockDim.x;
    const int n8 = NA * 8;   // 8-float chunks
    for (int k = i; k < n8; k += stride) {
        float4 f0 = __ldg((const float4*)xA + k * 2);
        float4 f1 = __ldg((const float4*)xA + k * 2 + 1);
        __half2 h0 = __floats2half2_rn(f0.x, f0.y);
        __half2 h1 = __floats2half2_rn(f0.z, f0.w);
        __half2 h2 = __floats2half2_rn(f1.x, f1.y);
        __half2 h3 = __floats2half2_rn(f1.z, f1.w);
        uint4 o;
        o.x = *(unsigned*)&h0; o.y = *(unsigned*)&h1;
        o.z = *(unsigned*)&h2; o.w = *(unsigned*)&h3;
        ((uint4*)g_hA)[k] = o;
    }
    const int m8 = NB * 8;
    for (int k = i; k < m8; k += stride) {
        float4 f0 = __ldg((const float4*)xB + k * 2);
        float4 f1 = __ldg((const float4*)xB + k * 2 + 1);
        __half2 h0 = __floats2half2_rn(f0.x, f0.y);
        __half2 h1 = __floats2half2_rn(f0.z, f0.w);
        __half2 h2 = __floats2half2_rn(f1.x, f1.y);
        __half2 h3 = __floats2half2_rn(f1.z, f1.w);
        uint4 o;
        o.x = *(unsigned*)&h0; o.y = *(unsigned*)&h1;
        o.z = *(unsigned*)&h2; o.w = *(unsigned*)&h3;
        ((uint4*)g_hB)[k] = o;
    }
}

// ---------------- CSR build: histogram --------------------------------------
__global__ void hist_kernel(const int* __restrict__ d0,
                            const int* __restrict__ d1,
                            const int* __restrict__ d2,
                            int E0, int E1, int E2) {
    int i = blockIdx.x * blockDim.x + threadIdx.x;
    int stride = gridDim.x * blockDim.x;
    for (int e = i; e < E0; e += stride) atomicAdd(&g_cnt0[__ldg(d0 + e)], 1);
    for (int e = i; e < E1; e += stride) atomicAdd(&g_cnt1[__ldg(d1 + e)], 1);
    for (int e = i; e < E2; e += stride) atomicAdd(&g_cnt2[__ldg(d2 + e)], 1);
}

// ---------------- CSR build: chunk sums -------------------------------------
__global__ void chunk_sum_kernel() {
    int type = blockIdx.x / NCH, ch = blockIdx.x % NCH;
    const int* cnt = (type == 0) ? g_cnt0 : (type == 1) ? g_cnt1 : g_cnt2;
    int N = (type == 0) ? NB : NA;
    int i0 = ch * 2048 + threadIdx.x * 8;
    int s = 0;
#pragma unroll
    for (int k = 0; k < 8; k++) {
        int i = i0 + k;
        if (i < N) s += cnt[i];
    }
    __shared__ int red[256];
    red[threadIdx.x] = s;
    __syncthreads();
    for (int o = 128; o > 0; o >>= 1) {
        if (threadIdx.x < o) red[threadIdx.x] += red[threadIdx.x + o];
        __syncthreads();
    }
    if (threadIdx.x == 0) g_csum[type * 64 + ch] = red[0];
}

// ---------------- CSR build: write ptr (chunk prefix via smem) --------------
__global__ void write_ptr_kernel(int E0, int E1, int E2) {
    int type = blockIdx.x / NCH, ch = blockIdx.x % NCH;
    const int* cnt; int* ptr; int* wofs; int N;
    if (type == 0)      { cnt = g_cnt0; ptr = g_ptr0; wofs = g_wofs0; N = NB; }
    else if (type == 1) { cnt = g_cnt1; ptr = g_ptr1; wofs = g_wofs1; N = NA; }
    else                { cnt = g_cnt2; ptr = g_ptr2; wofs = g_wofs2; N = NA; }

    if (threadIdx.x == 0 && ch == 0) {
        if (type == 0) g_ptr0[NB] = E0;
        else if (type == 1) g_ptr1[NA] = E1;
        else g_ptr2[NA] = E2;
    }

    __shared__ int csh[NCH];
    if (threadIdx.x < NCH) csh[threadIdx.x] = __ldg(&g_csum[type * 64 + threadIdx.x]);

    int i0 = ch * 2048 + threadIdx.x * 8;
    int c[8];
    int s = 0;
#pragma unroll
    for (int k = 0; k < 8; k++) {
        int i = i0 + k;
        c[k] = (i < N) ? cnt[i] : 0;
        s += c[k];
    }
    __shared__ int sd[256];
    sd[threadIdx.x] = s;
    __syncthreads();
    for (int o = 1; o < 256; o <<= 1) {
        int v = (threadIdx.x >= o) ? sd[threadIdx.x - o] : 0;
        __syncthreads();
        sd[threadIdx.x] += v;
        __syncthreads();
    }
    int cbase = 0;
    for (int c2 = 0; c2 < ch; c2++) cbase += csh[c2];
    int base = cbase + sd[threadIdx.x] - s;
#pragma unroll
    for (int k = 0; k < 8; k++) {
        int i = i0 + k;
        if (i < N) {
            ptr[i] = base;
            wofs[i] = base;
            base += c[k];
        }
    }
}

// ---------------- CSR build: scatter src ids into dst-sorted order ----------
__global__ void scatter_kernel(const int* __restrict__ s0, const int* __restrict__ d0,
                               const int* __restrict__ s1, const int* __restrict__ d1,
                               const int* __restrict__ s2, const int* __restrict__ d2,
                               int E0, int E1, int E2) {
    int i = blockIdx.x * blockDim.x + threadIdx.x;
    int stride = gridDim.x * blockDim.x;
    for (int e = i; e < E0; e += stride) {
        int p = atomicAdd(&g_wofs0[__ldg(d0 + e)], 1);
        g_col0[p] = __ldg(s0 + e);
    }
    for (int e = i; e < E1; e += stride) {
        int p = atomicAdd(&g_wofs1[__ldg(d1 + e)], 1);
        g_col1[p] = __ldg(s1 + e);
    }
    for (int e = i; e < E2; e += stride) {
        int p = atomicAdd(&g_wofs2[__ldg(d2 + e)], 1);
        g_col2[p] = __ldg(s2 + e);
    }
}

// ---------------- weight prep: fold + PAIR-PACK -----------------------------
__global__ void prep_kernel(const float* __restrict__ Wn, const float* __restrict__ Wr,
                            const float* __restrict__ b,
                            const float* __restrict__ Wout, const float* __restrict__ bout) {
    if (blockIdx.x < 10) {
        int l = blockIdx.x / 5, m = blockIdx.x % 5;
        __shared__ float S[4096];
        __shared__ float T[4096];
        for (int i = threadIdx.x; i < 4096; i += blockDim.x) {
            float v;
            if (m == 0)      v = Wn[(l * 3 + 1) * 4096 + i];
            else if (m == 1) v = Wn[(l * 3 + 2) * 4096 + i];
            else if (m == 2) v = Wr[(l * 3 + 1) * 4096 + i] + Wr[(l * 3 + 2) * 4096 + i];
            else if (m == 3) v = Wn[(l * 3 + 0) * 4096 + i];
            else             v = Wr[(l * 3 + 0) * 4096 + i];
            S[i] = v;
        }
        __syncthreads();
        const float* src = S;
        if (l == 1) {
            for (int o = threadIdx.x; o < 4096; o += blockDim.x) {
                int i = o >> 6, j = o & 63;
                float acc = 0.f;
#pragma unroll 16
                for (int k = 0; k < 64; k++)
                    acc += S[i * 64 + k] * __ldg(Wout + k * 64 + j);
                T[o] = acc;
            }
            __syncthreads();
            src = T;
        }
        float2* dst = (float2*)(g_W[l] + m * 4096);
        for (int o = threadIdx.x; o < 2048; o += blockDim.x) {
            int k2 = o >> 6, j = o & 63;
            dst[o] = make_float2(src[(2 * k2) * 64 + j], src[(2 * k2 + 1) * 64 + j]);
        }
    } else {
        int j = threadIdx.x;
        if (j < 64) {
            g_bias[0][j]      = b[1 * 64 + j] + b[2 * 64 + j];
            g_bias[0][64 + j] = b[j];
            float accA = 0.f, accB = 0.f;
            for (int k = 0; k < 64; k++) {
                float w = __ldg(Wout + k * 64 + j);
                accA += (b[4 * 64 + k] + b[5 * 64 + k]) * w;
                accB += b[3 * 64 + k] * w;
            }
            g_bias[1][j]      = accA + bout[j];
            g_bias[1][64 + j] = accB + bout[j];
        }
    }
}

// ---------------- atomic-free CSR gather over fp16 features, fp32 accum -----
// 8 threads/node; thread c owns halves [8c, 8c+8) (one uint4 = 16B per edge).
// 4-edge unroll -> 4 independent 16B loads in flight.
__device__ __forceinline__ void acc_u4(uint4 u, float2* A) {
    const __half2* h = (const __half2*)&u;
    float2 f;
    f = __half22float2(h[0]); A[0].x += f.x; A[0].y += f.y;
    f = __half22float2(h[1]); A[1].x += f.x; A[1].y += f.y;
    f = __half22float2(h[2]); A[2].x += f.x; A[2].y += f.y;
    f = __half22float2(h[3]); A[3].x += f.x; A[3].y += f.y;
}

__global__ __launch_bounds__(256, 6)
void gather_kernel(const __half* __restrict__ hA, const __half* __restrict__ hB,
                   int nb0, int nb01) {
    int bid = blockIdx.x;
    const __half* x; const int* ptr; const int* col; float* m; int row0;
    if (bid < nb0)       { row0 = bid * 32;          x = hA; ptr = g_ptr0; col = g_col0; m = g_m0; }
    else if (bid < nb01) { row0 = (bid - nb0) * 32;  x = hB; ptr = g_ptr1; col = g_col1; m = g_m1; }
    else                 { row0 = (bid - nb01) * 32; x = hA; ptr = g_ptr2; col = g_col2; m = g_m2; }

    int g = threadIdx.x >> 3;
    int c = threadIdx.x & 7;
    int n = row0 + g;
    int beg = __ldg(ptr + n), end = __ldg(ptr + n + 1);
    const uint4* X = (const uint4*)x;   // node stride = 8 uint4

    float2 A[4];
    A[0] = A[1] = A[2] = A[3] = make_float2(0.f, 0.f);

    int k = beg;
    while (k + 3 < end) {
        int i0 = __ldg(col + k);
        int i1 = __ldg(col + k + 1);
        int i2 = __ldg(col + k + 2);
        int i3 = __ldg(col + k + 3);
        uint4 u0 = __ldg(X + (size_t)i0 * 8 + c);
        uint4 u1 = __ldg(X + (size_t)i1 * 8 + c);
        uint4 u2 = __ldg(X + (size_t)i2 * 8 + c);
        uint4 u3 = __ldg(X + (size_t)i3 * 8 + c);
        acc_u4(u0, A); acc_u4(u1, A); acc_u4(u2, A); acc_u4(u3, A);
        k += 4;
    }
    while (k < end) {
        int i0 = __ldg(col + k);
        acc_u4(__ldg(X + (size_t)i0 * 8 + c), A);
        k++;
    }

    float inv = 1.0f / fmaxf((float)(end - beg), 1.0f);
    float4 o0 = make_float4(A[0].x * inv, A[0].y * inv, A[1].x * inv, A[1].y * inv);
    float4 o1 = make_float4(A[2].x * inv, A[2].y * inv, A[3].x * inv, A[3].y * inv);
    float4* mo = (float4*)m + (size_t)n * 16 + c * 2;
    mo[0] = o0;
    mo[1] = o1;
}

// ---------------- combine: 64 rows/block, pair-packed weights, f32x2 FMA ----
// A-side: m1@W0 + m2@W1 + x@W2 + bias[0:64]; B-side: m0@W3 + x@W4 + bias[64:128]
// HOUT: also emit fp16 copy (message features for the next layer's gather).
template<bool RELU, bool HOUT>
__global__ __launch_bounds__(256) void combine_kernel(
    const float* __restrict__ xA, const float* __restrict__ xB,
    const float* __restrict__ Wl, const float* __restrict__ bl,
    float* __restrict__ outA, float* __restrict__ outB,
    __half* __restrict__ houtA, __half* __restrict__ houtB, int nbA) {
    __shared__ float4 sbuf[3 * 1024];   // 48KB
    const int j = threadIdx.x & 63;
    const int rg = threadIdx.x >> 6;
    const ull* W64 = (const ull*)Wl;

    if (blockIdx.x < nbA) {
        int row0 = blockIdx.x * 64;
        int rows = NA - row0 < 64 ? NA - row0 : 64;
        float4* sm1 = sbuf;
        float4* sm2 = sbuf + 1024;
        float4* smx = sbuf + 2048;
        for (int i = threadIdx.x; i < rows * 16; i += 256) {
            sm1[i] = __ldg((const float4*)g_m1 + (size_t)row0 * 16 + i);
            sm2[i] = __ldg((const float4*)g_m2 + (size_t)row0 * 16 + i);
            smx[i] = __ldg((const float4*)xA + (size_t)row0 * 16 + i);
        }
        ull wn1p[32], wn2p[32], wrsp[32];
#pragma unroll
        for (int k2 = 0; k2 < 32; k2++) {
            wn1p[k2] = __ldg(W64 + 0 * 2048 + k2 * 64 + j);
            wn2p[k2] = __ldg(W64 + 1 * 2048 + k2 * 64 + j);
            wrsp[k2] = __ldg(W64 + 2 * 2048 + k2 * 64 + j);
        }
        float bj = __ldg(bl + j);
        __syncthreads();
#pragma unroll
        for (int rr = 0; rr < 16; rr++) {
            int r = rg * 16 + rr;
            if (r < rows) {
                const ulonglong2* p1 = (const ulonglong2*)(sm1 + r * 16);
                const ulonglong2* p2 = (const ulonglong2*)(sm2 + r * 16);
                const ulonglong2* px = (const ulonglong2*)(smx + r * 16);
                ull acc0, acc1;
                PK2(acc0, bj, 0.0f);
                acc1 = 0ULL;
#pragma unroll
                for (int k4 = 0; k4 < 16; k4++) {
                    ulonglong2 a = p1[k4];
                    FMA2(acc0, a.x, wn1p[2 * k4], acc0);
                    FMA2(acc1, a.y, wn1p[2 * k4 + 1], acc1);
                    ulonglong2 bq = p2[k4];
                    FMA2(acc0, bq.x, wn2p[2 * k4], acc0);
                    FMA2(acc1, bq.y, wn2p[2 * k4 + 1], acc1);
                    ulonglong2 cq = px[k4];
                    FMA2(acc0, cq.x, wrsp[2 * k4], acc0);
                    FMA2(acc1, cq.y, wrsp[2 * k4 + 1], acc1);
                }
                float l0, h0, l1, h1;
                UPK2(l0, h0, acc0);
                UPK2(l1, h1, acc1);
                float v = (l0 + h0) + (l1 + h1);
                if (RELU) v = fmaxf(v, 0.0f);
                outA[(size_t)(row0 + r) * 64 + j] = v;
                if (HOUT) houtA[(size_t)(row0 + r) * 64 + j] = __float2half_rn(v);
            }
        }
    } else {
        int row0 = (blockIdx.x - nbA) * 64;
        int rows = NB - row0 < 64 ? NB - row0 : 64;
        float4* smm = sbuf;
        float4* smx = sbuf + 1024;
        for (int i = threadIdx.x; i < rows * 16; i += 256) {
            smm[i] = __ldg((const float4*)g_m0 + (size_t)row0 * 16 + i);
            smx[i] = __ldg((const float4*)xB + (size_t)row0 * 16 + i);
        }
        ull wnp[32], wrp[32];
#pragma unroll
        for (int k2 = 0; k2 < 32; k2++) {
            wnp[k2] = __ldg(W64 + 3 * 2048 + k2 * 64 + j);
            wrp[k2] = __ldg(W64 + 4 * 2048 + k2 * 64 + j);
        }
        float bj = __ldg(bl + 64 + j);
        __syncthreads();
#pragma unroll
        for (int rr = 0; rr < 16; rr++) {
            int r = rg * 16 + rr;
            if (r < rows) {
                const ulonglong2* pm = (const ulonglong2*)(smm + r * 16);
                const ulonglong2* px = (const ulonglong2*)(smx + r * 16);
                ull acc0, acc1;
                PK2(acc0, bj, 0.0f);
                acc1 = 0ULL;
#pragma unroll
                for (int k4 = 0; k4 < 16; k4++) {
                    ulonglong2 a = pm[k4];
                    FMA2(acc0, a.x, wnp[2 * k4], acc0);
                    FMA2(acc1, a.y, wnp[2 * k4 + 1], acc1);
                    ulonglong2 bq = px[k4];
                    FMA2(acc0, bq.x, wrp[2 * k4], acc0);
                    FMA2(acc1, bq.y, wrp[2 * k4 + 1], acc1);
                }
                float l0, h0, l1, h1;
                UPK2(l0, h0, acc0);
                UPK2(l1, h1, acc1);
                float v = (l0 + h0) + (l1 + h1);
                if (RELU) v = fmaxf(v, 0.0f);
                outB[(size_t)(row0 + r) * 64 + j] = v;
                if (HOUT) houtB[(size_t)(row0 + r) * 64 + j] = __float2half_rn(v);
            }
        }
    }
}

// ---------------- launcher --------------------------------------------------
extern "C" void kernel_launch(void* const* d_in, const int* in_sizes, int n_in,
                              void* d_out, int out_size) {
    const float* x_A   = (const float*)d_in[0];
    const float* x_B   = (const float*)d_in[1];
    const float* Wn    = (const float*)d_in[2];
    const float* Wr    = (const float*)d_in[3];
    const float* b     = (const float*)d_in[4];
    const float* W_out = (const float*)d_in[5];
    const float* b_out = (const float*)d_in[6];
    const int* src0 = (const int*)d_in[7];
    const int* dst0 = (const int*)d_in[8];
    const int* src1 = (const int*)d_in[9];
    const int* dst1 = (const int*)d_in[10];
    const int* src2 = (const int*)d_in[11];
    const int* dst2 = (const int*)d_in[12];
    const int E0 = in_sizes[7];
    const int E1 = in_sizes[9];
    const int E2 = in_sizes[11];
    float* out = (float*)d_out;

    float *A1, *B1, *W0, *W1, *bias0, *bias1;
    __half *hA, *hB, *hA1, *hB1;
    int *cnt0, *cnt1, *cnt2;
    cudaGetSymbolAddress((void**)&A1, g_A1);
    cudaGetSymbolAddress((void**)&B1, g_B1);
    cudaGetSymbolAddress((void**)&hA, g_hA);
    cudaGetSymbolAddress((void**)&hB, g_hB);
    cudaGetSymbolAddress((void**)&hA1, g_hA1);
    cudaGetSymbolAddress((void**)&hB1, g_hB1);
    cudaGetSymbolAddress((void**)&cnt0, g_cnt0);
    cudaGetSymbolAddress((void**)&cnt1, g_cnt1);
    cudaGetSymbolAddress((void**)&cnt2, g_cnt2);
    cudaGetSymbolAddress((void**)&W0, g_W);
    W1 = W0 + 5 * 4096;
    cudaGetSymbolAddress((void**)&bias0, g_bias);
    bias1 = bias0 + 128;

    const int nb0 = NB / 32, nb1 = NA / 32, nb2 = NA / 32;
    const int gatherBlocks = nb0 + nb1 + nb2;
    const int nbA = (NA + 63) / 64;
    const int nbB = (NB + 63) / 64;

    // ---- prep: weights + fp16 feature conversion (independent of CSR) ----
    prep_kernel<<<11, 256>>>(Wn, Wr, b, W_out, b_out);
    conv_kernel<<<1024, 256>>>(x_A, x_B);

    // ---- CSR build ----
    cudaMemsetAsync(cnt0, 0, NB * sizeof(int));
    cudaMemsetAsync(cnt1, 0, NA * sizeof(int));
    cudaMemsetAsync(cnt2, 0, NA * sizeof(int));
    hist_kernel<<<1024, 256>>>(dst0, dst1, dst2, E0, E1, E2);
    chunk_sum_kernel<<<3 * NCH, 256>>>();
    write_ptr_kernel<<<3 * NCH, 256>>>(E0, E1, E2);
    scatter_kernel<<<1024, 256>>>(src0, dst0, src1, dst1, src2, dst2, E0, E1, E2);

    // ---- layer 0 ----
    gather_kernel<<<gatherBlocks, 256>>>(hA, hB, nb0, nb0 + nb1);
    combine_kernel<false, true><<<nbA + nbB, 256>>>(x_A, x_B, W0, bias0,
                                                    A1, B1, hA1, hB1, nbA);

    // ---- layer 1 (head folded into weights; relu at store) ----
    gather_kernel<<<gatherBlocks, 256>>>(hA1, hB1, nb0, nb0 + nb1);
    combine_kernel<true, false><<<nbA + nbB, 256>>>(A1, B1, W1, bias1,
                                                    out, out + (size_t)NA * 64,
                                                    nullptr, nullptr, nbA);
}

// round 10
// speedup vs baseline: 2.1431x; 1.2128x over previous
#include <cuda_runtime.h>
#include <cuda_fp16.h>
#include <cstddef>

#define NA 100000
#define NB 100000
#define DD 64
#define EMAX 1250000
#define NCH 49          // chunks of 2048 nodes: 49*2048 >= 100000

typedef unsigned long long ull;

// ---------------- tf32 mma helpers ------------------------------------------
__device__ __forceinline__ unsigned f2tf(float f) {
    unsigned u;
    asm("cvt.rna.tf32.f32 %0, %1;" : "=r"(u) : "f"(f));
    return u;
}
__device__ __forceinline__ void mma_tf32(float* c, unsigned a0, unsigned a1,
                                         unsigned a2, unsigned a3,
                                         unsigned b0, unsigned b1) {
    asm("mma.sync.aligned.m16n8k8.row.col.f32.tf32.tf32.f32 "
        "{%0,%1,%2,%3}, {%4,%5,%6,%7}, {%8,%9}, {%0,%1,%2,%3};"
        : "+f"(c[0]), "+f"(c[1]), "+f"(c[2]), "+f"(c[3])
        : "r"(a0), "r"(a1), "r"(a2), "r"(a3), "r"(b0), "r"(b1));
}

// ---------------- scratch (device globals: no allocation allowed) ----------
__device__ int g_cnt0[NB], g_cnt1[NA], g_cnt2[NA];
__device__ int g_ptr0[NB + 1], g_ptr1[NA + 1], g_ptr2[NA + 1];
__device__ int g_wofs0[NB], g_wofs1[NA], g_wofs2[NA];
__device__ int g_col0[EMAX], g_col1[EMAX], g_col2[EMAX];
__device__ int g_csum[3 * 64];
__device__ float g_m0[NB * DD];
__device__ float g_m1[NA * DD];
__device__ float g_m2[NA * DD];
__device__ float g_A1[NA * DD];
__device__ float g_B1[NB * DD];
// half-precision message features (aligned for uint4 loads)
__device__ __align__(16) __half g_hA[NA * DD];
__device__ __align__(16) __half g_hB[NB * DD];
__device__ __align__(16) __half g_hA1[NA * DD];
__device__ __align__(16) __half g_hB1[NB * DD];
// tf32 B-fragments: A-side stacked [Wn1;Wn2;Wrs] = 24 ktiles, B-side [Wn;Wr] = 16
// layout: [ktile][ntile 8][lane 32] float2 = {B[k][n], B[k+4][n]} (tf32 bits)
__device__ __align__(16) float2 g_fragA[2][24 * 8 * 32];
__device__ __align__(16) float2 g_fragB[2][16 * 8 * 32];
__device__ float g_bias[2][128];   // [l][0:64]=A bias, [64:128]=B bias

// ---------------- fp32 -> fp16 feature conversion ----------------------------
__global__ void conv_kernel(const float* __restrict__ xA, const float* __restrict__ xB) {
    int i = blockIdx.x * blockDim.x + threadIdx.x;
    int stride = gridDim.x * blockDim.x;
    const int n8 = NA * 8;
    for (int k = i; k < n8; k += stride) {
        float4 f0 = __ldg((const float4*)xA + k * 2);
        float4 f1 = __ldg((const float4*)xA + k * 2 + 1);
        __half2 h0 = __floats2half2_rn(f0.x, f0.y);
        __half2 h1 = __floats2half2_rn(f0.z, f0.w);
        __half2 h2 = __floats2half2_rn(f1.x, f1.y);
        __half2 h3 = __floats2half2_rn(f1.z, f1.w);
        uint4 o;
        o.x = *(unsigned*)&h0; o.y = *(unsigned*)&h1;
        o.z = *(unsigned*)&h2; o.w = *(unsigned*)&h3;
        ((uint4*)g_hA)[k] = o;
    }
    const int m8 = NB * 8;
    for (int k = i; k < m8; k += stride) {
        float4 f0 = __ldg((const float4*)xB + k * 2);
        float4 f1 = __ldg((const float4*)xB + k * 2 + 1);
        __half2 h0 = __floats2half2_rn(f0.x, f0.y);
        __half2 h1 = __floats2half2_rn(f0.z, f0.w);
        __half2 h2 = __floats2half2_rn(f1.x, f1.y);
        __half2 h3 = __floats2half2_rn(f1.z, f1.w);
        uint4 o;
        o.x = *(unsigned*)&h0; o.y = *(unsigned*)&h1;
        o.z = *(unsigned*)&h2; o.w = *(unsigned*)&h3;
        ((uint4*)g_hB)[k] = o;
    }
}

// ---------------- CSR build: histogram --------------------------------------
__global__ void hist_kernel(const int* __restrict__ d0,
                            const int* __restrict__ d1,
                            const int* __restrict__ d2,
                            int E0, int E1, int E2) {
    int i = blockIdx.x * blockDim.x + threadIdx.x;
    int stride = gridDim.x * blockDim.x;
    for (int e = i; e < E0; e += stride) atomicAdd(&g_cnt0[__ldg(d0 + e)], 1);
    for (int e = i; e < E1; e += stride) atomicAdd(&g_cnt1[__ldg(d1 + e)], 1);
    for (int e = i; e < E2; e += stride) atomicAdd(&g_cnt2[__ldg(d2 + e)], 1);
}

// ---------------- CSR build: chunk sums -------------------------------------
__global__ void chunk_sum_kernel() {
    int type = blockIdx.x / NCH, ch = blockIdx.x % NCH;
    const int* cnt = (type == 0) ? g_cnt0 : (type == 1) ? g_cnt1 : g_cnt2;
    int N = (type == 0) ? NB : NA;
    int i0 = ch * 2048 + threadIdx.x * 8;
    int s = 0;
#pragma unroll
    for (int k = 0; k < 8; k++) {
        int i = i0 + k;
        if (i < N) s += cnt[i];
    }
    __shared__ int red[256];
    red[threadIdx.x] = s;
    __syncthreads();
    for (int o = 128; o > 0; o >>= 1) {
        if (threadIdx.x < o) red[threadIdx.x] += red[threadIdx.x + o];
        __syncthreads();
    }
    if (threadIdx.x == 0) g_csum[type * 64 + ch] = red[0];
}

// ---------------- CSR build: write ptr (chunk prefix via smem) --------------
__global__ void write_ptr_kernel(int E0, int E1, int E2) {
    int type = blockIdx.x / NCH, ch = blockIdx.x % NCH;
    const int* cnt; int* ptr; int* wofs; int N;
    if (type == 0)      { cnt = g_cnt0; ptr = g_ptr0; wofs = g_wofs0; N = NB; }
    else if (type == 1) { cnt = g_cnt1; ptr = g_ptr1; wofs = g_wofs1; N = NA; }
    else                { cnt = g_cnt2; ptr = g_ptr2; wofs = g_wofs2; N = NA; }

    if (threadIdx.x == 0 && ch == 0) {
        if (type == 0) g_ptr0[NB] = E0;
        else if (type == 1) g_ptr1[NA] = E1;
        else g_ptr2[NA] = E2;
    }

    __shared__ int csh[NCH];
    if (threadIdx.x < NCH) csh[threadIdx.x] = __ldg(&g_csum[type * 64 + threadIdx.x]);

    int i0 = ch * 2048 + threadIdx.x * 8;
    int c[8];
    int s = 0;
#pragma unroll
    for (int k = 0; k < 8; k++) {
        int i = i0 + k;
        c[k] = (i < N) ? cnt[i] : 0;
        s += c[k];
    }
    __shared__ int sd[256];
    sd[threadIdx.x] = s;
    __syncthreads();
    for (int o = 1; o < 256; o <<= 1) {
        int v = (threadIdx.x >= o) ? sd[threadIdx.x - o] : 0;
        __syncthreads();
        sd[threadIdx.x] += v;
        __syncthreads();
    }
    int cbase = 0;
    for (int c2 = 0; c2 < ch; c2++) cbase += csh[c2];
    int base = cbase + sd[threadIdx.x] - s;
#pragma unroll
    for (int k = 0; k < 8; k++) {
        int i = i0 + k;
        if (i < N) {
            ptr[i] = base;
            wofs[i] = base;
            base += c[k];
        }
    }
}

// ---------------- CSR build: scatter src ids into dst-sorted order ----------
__global__ void scatter_kernel(const int* __restrict__ s0, const int* __restrict__ d0,
                               const int* __restrict__ s1, const int* __restrict__ d1,
                               const int* __restrict__ s2, const int* __restrict__ d2,
                               int E0, int E1, int E2) {
    int i = blockIdx.x * blockDim.x + threadIdx.x;
    int stride = gridDim.x * blockDim.x;
    for (int e = i; e < E0; e += stride) {
        int p = atomicAdd(&g_wofs0[__ldg(d0 + e)], 1);
        g_col0[p] = __ldg(s0 + e);
    }
    for (int e = i; e < E1; e += stride) {
        int p = atomicAdd(&g_wofs1[__ldg(d1 + e)], 1);
        g_col1[p] = __ldg(s1 + e);
    }
    for (int e = i; e < E2; e += stride) {
        int p = atomicAdd(&g_wofs2[__ldg(d2 + e)], 1);
        g_col2[p] = __ldg(s2 + e);
    }
}

// ---------------- weight prep: fold + emit tf32 B-fragments -----------------
// blocks 0..9: matrix m of layer l (m 0..2 -> A-side ktiles m*8.., m 3..4 -> B-side)
// block 10: biases. Layer-1 weights folded with W_out (head elimination).
__global__ void prep_kernel(const float* __restrict__ Wn, const float* __restrict__ Wr,
                            const float* __restrict__ b,
                            const float* __restrict__ Wout, const float* __restrict__ bout) {
    if (blockIdx.x < 10) {
        int l = blockIdx.x / 5, m = blockIdx.x % 5;
        __shared__ float S[4096];
        __shared__ float T[4096];
        for (int i = threadIdx.x; i < 4096; i += blockDim.x) {
            float v;
            if (m == 0)      v = Wn[(l * 3 + 1) * 4096 + i];
            else if (m == 1) v = Wn[(l * 3 + 2) * 4096 + i];
            else if (m == 2) v = Wr[(l * 3 + 1) * 4096 + i] + Wr[(l * 3 + 2) * 4096 + i];
            else if (m == 3) v = Wn[(l * 3 + 0) * 4096 + i];
            else             v = Wr[(l * 3 + 0) * 4096 + i];
            S[i] = v;
        }
        __syncthreads();
        const float* src = S;
        if (l == 1) {
            for (int o = threadIdx.x; o < 4096; o += blockDim.x) {
                int i = o >> 6, j = o & 63;
                float acc = 0.f;
#pragma unroll 16
                for (int k = 0; k < 64; k++)
                    acc += S[i * 64 + k] * __ldg(Wout + k * 64 + j);
                T[o] = acc;
            }
            __syncthreads();
            src = T;
        }
        float2* dst = (m < 3) ? (g_fragA[l] + m * 2048) : (g_fragB[l] + (m - 3) * 2048);
        for (int o = threadIdx.x; o < 2048; o += blockDim.x) {
            int lane = o & 31, nt = (o >> 5) & 7, kt2 = o >> 8;
            int k = kt2 * 8 + (lane & 3);
            int j = nt * 8 + (lane >> 2);
            float2 f;
            f.x = __uint_as_float(f2tf(src[k * 64 + j]));
            f.y = __uint_as_float(f2tf(src[(k + 4) * 64 + j]));
            dst[o] = f;
        }
    } else {
        int j = threadIdx.x;
        if (j < 64) {
            g_bias[0][j]      = b[1 * 64 + j] + b[2 * 64 + j];
            g_bias[0][64 + j] = b[j];
            float accA = 0.f, accB = 0.f;
            for (int k = 0; k < 64; k++) {
                float w = __ldg(Wout + k * 64 + j);
                accA += (b[4 * 64 + k] + b[5 * 64 + k]) * w;
                accB += b[3 * 64 + k] * w;
            }
            g_bias[1][j]      = accA + bout[j];
            g_bias[1][64 + j] = accB + bout[j];
        }
    }
}

// ---------------- atomic-free CSR gather over fp16 features, fp32 accum -----
__device__ __forceinline__ void acc_u4(uint4 u, float2* A) {
    const __half2* h = (const __half2*)&u;
    float2 f;
    f = __half22float2(h[0]); A[0].x += f.x; A[0].y += f.y;
    f = __half22float2(h[1]); A[1].x += f.x; A[1].y += f.y;
    f = __half22float2(h[2]); A[2].x += f.x; A[2].y += f.y;
    f = __half22float2(h[3]); A[3].x += f.x; A[3].y += f.y;
}

__global__ __launch_bounds__(256, 6)
void gather_kernel(const __half* __restrict__ hA, const __half* __restrict__ hB,
                   int nb0, int nb01) {
    int bid = blockIdx.x;
    const __half* x; const int* ptr; const int* col; float* m; int row0;
    if (bid < nb0)       { row0 = bid * 32;          x = hA; ptr = g_ptr0; col = g_col0; m = g_m0; }
    else if (bid < nb01) { row0 = (bid - nb0) * 32;  x = hB; ptr = g_ptr1; col = g_col1; m = g_m1; }
    else                 { row0 = (bid - nb01) * 32; x = hA; ptr = g_ptr2; col = g_col2; m = g_m2; }

    int g = threadIdx.x >> 3;
    int c = threadIdx.x & 7;
    int n = row0 + g;
    int beg = __ldg(ptr + n), end = __ldg(ptr + n + 1);
    const uint4* X = (const uint4*)x;

    float2 A[4];
    A[0] = A[1] = A[2] = A[3] = make_float2(0.f, 0.f);

    int k = beg;
    while (k + 3 < end) {
        int i0 = __ldg(col + k);
        int i1 = __ldg(col + k + 1);
        int i2 = __ldg(col + k + 2);
        int i3 = __ldg(col + k + 3);
        uint4 u0 = __ldg(X + (size_t)i0 * 8 + c);
        uint4 u1 = __ldg(X + (size_t)i1 * 8 + c);
        uint4 u2 = __ldg(X + (size_t)i2 * 8 + c);
        uint4 u3 = __ldg(X + (size_t)i3 * 8 + c);
        acc_u4(u0, A); acc_u4(u1, A); acc_u4(u2, A); acc_u4(u3, A);
        k += 4;
    }
    while (k < end) {
        int i0 = __ldg(col + k);
        acc_u4(__ldg(X + (size_t)i0 * 8 + c), A);
        k++;
    }

    float inv = 1.0f / fmaxf((float)(end - beg), 1.0f);
    float4 o0 = make_float4(A[0].x * inv, A[0].y * inv, A[1].x * inv, A[1].y * inv);
    float4 o1 = make_float4(A[2].x * inv, A[2].y * inv, A[3].x * inv, A[3].y * inv);
    float4* mo = (float4*)m + (size_t)n * 16 + c * 2;
    mo[0] = o0;
    mo[1] = o1;
}

// ---------------- combine via tf32 tensor cores -----------------------------
// 64 rows/block, 8 warps: warp = (mtile 0..3, nhalf 0..1) -> m16 x n32 strip.
// A-side K=192 ([m1|m2|x] @ [Wn1;Wn2;Wrs]); B-side K=128 ([m0|x] @ [Wn;Wr]).
// smem: X tile 64 x 196 f32 (stride 196 -> conflict-free frag loads), then frags.
#define XSTR 196
template<bool RELU, bool HOUT>
__global__ __launch_bounds__(256) void combine_kernel(
    const float* __restrict__ xA, const float* __restrict__ xB,
    const float2* __restrict__ fragA, const float2* __restrict__ fragB,
    const float* __restrict__ bl,
    float* __restrict__ outA, float* __restrict__ outB,
    __half* __restrict__ houtA, __half* __restrict__ houtB, int nbA) {
    extern __shared__ float sx[];
    float2* sfrag = (float2*)(sx + 64 * XSTR);
    const int lane = threadIdx.x & 31;
    const int warp = threadIdx.x >> 5;
    const int mt = warp & 3;
    const int nh = warp >> 2;
    const int r8 = lane >> 2;
    const int c4 = lane & 3;

    bool isA = (blockIdx.x < nbA);
    int row0, rows, KT;
    float* outX;
    __half* houtX;
    const float* blx;
    if (isA) {
        row0 = blockIdx.x * 64;
        rows = NA - row0 < 64 ? NA - row0 : 64;
        KT = 24;
        outX = outA; houtX = houtA; blx = bl;
        // stage [m1|m2|x] : 64 rows x 48 float4 slots
        for (int i = threadIdx.x; i < 3072; i += 256) {
            int r = i / 48, s = i - r * 48;
            int seg = s >> 4, cc = s & 15;
            float4 v = make_float4(0.f, 0.f, 0.f, 0.f);
            if (r < rows) {
                const float4* sp = (seg == 0) ? (const float4*)g_m1
                                 : (seg == 1) ? (const float4*)g_m2
                                              : (const float4*)xA;
                v = __ldg(sp + (size_t)(row0 + r) * 16 + cc);
            }
            *(float4*)&sx[r * XSTR + seg * 64 + cc * 4] = v;
        }
        for (int i = threadIdx.x; i < 24 * 256; i += 256)
            sfrag[i] = __ldg(fragA + i);
    } else {
        row0 = (blockIdx.x - nbA) * 64;
        rows = NB - row0 < 64 ? NB - row0 : 64;
        KT = 16;
        outX = outB; houtX = houtB; blx = bl + 64;
        for (int i = threadIdx.x; i < 2048; i += 256) {
            int r = i >> 5, s = i & 31;
            int seg = s >> 4, cc = s & 15;
            float4 v = make_float4(0.f, 0.f, 0.f, 0.f);
            if (r < rows) {
                const float4* sp = (seg == 0) ? (const float4*)g_m0
                                              : (const float4*)xB;
                v = __ldg(sp + (size_t)(row0 + r) * 16 + cc);
            }
            *(float4*)&sx[r * XSTR + seg * 64 + cc * 4] = v;
        }
        for (int i = threadIdx.x; i < 16 * 256; i += 256)
            sfrag[i] = __ldg(fragB + i);
    }
    __syncthreads();

    float acc[4][4];
#pragma unroll
    for (int t = 0; t < 4; t++) {
        acc[t][0] = 0.f; acc[t][1] = 0.f; acc[t][2] = 0.f; acc[t][3] = 0.f;
    }

    const float* xp0 = sx + (mt * 16 + r8) * XSTR + c4;
    for (int kt = 0; kt < KT; kt++) {
        const float* xp = xp0 + kt * 8;
        unsigned a0 = f2tf(xp[0]);
        unsigned a1 = f2tf(xp[8 * XSTR]);
        unsigned a2 = f2tf(xp[4]);
        unsigned a3 = f2tf(xp[8 * XSTR + 4]);
        const float2* fp = sfrag + (kt * 8 + nh * 4) * 32 + lane;
#pragma unroll
        for (int t = 0; t < 4; t++) {
            float2 bb = fp[t * 32];
            mma_tf32(acc[t], a0, a1, a2, a3,
                     __float_as_uint(bb.x), __float_as_uint(bb.y));
        }
    }

    // epilogue: +bias, relu, store (rows r0 and r0+8 of this warp's strip)
    int r0 = mt * 16 + r8;
#pragma unroll
    for (int t = 0; t < 4; t++) {
        int colj = (nh * 4 + t) * 8 + c4 * 2;
        float b0 = __ldg(blx + colj), b1 = __ldg(blx + colj + 1);
        float v00 = acc[t][0] + b0, v01 = acc[t][1] + b1;
        float v10 = acc[t][2] + b0, v11 = acc[t][3] + b1;
        if (RELU) {
            v00 = fmaxf(v00, 0.f); v01 = fmaxf(v01, 0.f);
            v10 = fmaxf(v10, 0.f); v11 = fmaxf(v11, 0.f);
        }
        if (r0 < rows) {
            *(float2*)&outX[(size_t)(row0 + r0) * 64 + colj] = make_float2(v00, v01);
            if (HOUT)
                *(__half2*)&houtX[(size_t)(row0 + r0) * 64 + colj] = __floats2half2_rn(v00, v01);
        }
        if (r0 + 8 < rows) {
            *(float2*)&outX[(size_t)(row0 + r0 + 8) * 64 + colj] = make_float2(v10, v11);
            if (HOUT)
                *(__half2*)&houtX[(size_t)(row0 + r0 + 8) * 64 + colj] = __floats2half2_rn(v10, v11);
        }
    }
}

// ---------------- launcher --------------------------------------------------
extern "C" void kernel_launch(void* const* d_in, const int* in_sizes, int n_in,
                              void* d_out, int out_size) {
    const float* x_A   = (const float*)d_in[0];
    const float* x_B   = (const float*)d_in[1];
    const float* Wn    = (const float*)d_in[2];
    const float* Wr    = (const float*)d_in[3];
    const float* b     = (const float*)d_in[4];
    const float* W_out = (const float*)d_in[5];
    const float* b_out = (const float*)d_in[6];
    const int* src0 = (const int*)d_in[7];
    const int* dst0 = (const int*)d_in[8];
    const int* src1 = (const int*)d_in[9];
    const int* dst1 = (const int*)d_in[10];
    const int* src2 = (const int*)d_in[11];
    const int* dst2 = (const int*)d_in[12];
    const int E0 = in_sizes[7];
    const int E1 = in_sizes[9];
    const int E2 = in_sizes[11];
    float* out = (float*)d_out;

    float *A1, *B1, *bias0, *bias1;
    float2 *frA, *frB;
    __half *hA, *hB, *hA1, *hB1;
    int *cnt0, *cnt1, *cnt2;
    cudaGetSymbolAddress((void**)&A1, g_A1);
    cudaGetSymbolAddress((void**)&B1, g_B1);
    cudaGetSymbolAddress((void**)&hA, g_hA);
    cudaGetSymbolAddress((void**)&hB, g_hB);
    cudaGetSymbolAddress((void**)&hA1, g_hA1);
    cudaGetSymbolAddress((void**)&hB1, g_hB1);
    cudaGetSymbolAddress((void**)&cnt0, g_cnt0);
    cudaGetSymbolAddress((void**)&cnt1, g_cnt1);
    cudaGetSymbolAddress((void**)&cnt2, g_cnt2);
    cudaGetSymbolAddress((void**)&frA, g_fragA);
    cudaGetSymbolAddress((void**)&frB, g_fragB);
    cudaGetSymbolAddress((void**)&bias0, g_bias);
    bias1 = bias0 + 128;

    const int nb0 = NB / 32, nb1 = NA / 32, nb2 = NA / 32;
    const int gatherBlocks = nb0 + nb1 + nb2;
    const int nbA = (NA + 63) / 64;
    const int nbB = (NB + 63) / 64;
    const int smemBytes = 64 * XSTR * 4 + 24 * 256 * 8;   // 50176 + 49152

    cudaFuncSetAttribute(combine_kernel<false, true>,
                         cudaFuncAttributeMaxDynamicSharedMemorySize, smemBytes);
    cudaFuncSetAttribute(combine_kernel<true, false>,
                         cudaFuncAttributeMaxDynamicSharedMemorySize, smemBytes);

    // ---- prep: weights + fp16 feature conversion (independent of CSR) ----
    prep_kernel<<<11, 256>>>(Wn, Wr, b, W_out, b_out);
    conv_kernel<<<1024, 256>>>(x_A, x_B);

    // ---- CSR build ----
    cudaMemsetAsync(cnt0, 0, NB * sizeof(int));
    cudaMemsetAsync(cnt1, 0, NA * sizeof(int));
    cudaMemsetAsync(cnt2, 0, NA * sizeof(int));
    hist_kernel<<<1024, 256>>>(dst0, dst1, dst2, E0, E1, E2);
    chunk_sum_kernel<<<3 * NCH, 256>>>();
    write_ptr_kernel<<<3 * NCH, 256>>>(E0, E1, E2);
    scatter_kernel<<<1024, 256>>>(src0, dst0, src1, dst1, src2, dst2, E0, E1, E2);

    // ---- layer 0 ----
    gather_kernel<<<gatherBlocks, 256>>>(hA, hB, nb0, nb0 + nb1);
    combine_kernel<false, true><<<nbA + nbB, 256, smemBytes>>>(
        x_A, x_B, frA, frB, bias0, A1, B1, hA1, hB1, nbA);

    // ---- layer 1 (head folded into weights; relu at store) ----
    gather_kernel<<<gatherBlocks, 256>>>(hA1, hB1, nb0, nb0 + nb1);
    combine_kernel<true, false><<<nbA + nbB, 256, smemBytes>>>(
        A1, B1, frA + 24 * 256, frB + 16 * 256, bias1,
        out, out + (size_t)NA * 64, nullptr, nullptr, nbA);
}

// round 11
// speedup vs baseline: 3.0179x; 1.4082x over previous
#include <cuda_runtime.h>
#include <cuda_fp16.h>
#include <cstddef>

#define NA 100000
#define NB 100000
#define DD 64
#define EMAX 1250000
#define NCH 49          // chunks of 2048 nodes: 49*2048 >= 100000

// ---------------- tf32 mma helper -------------------------------------------
__device__ __forceinline__ void mma_tf32(float* c, unsigned a0, unsigned a1,
                                         unsigned a2, unsigned a3,
                                         unsigned b0, unsigned b1) {
    asm("mma.sync.aligned.m16n8k8.row.col.f32.tf32.tf32.f32 "
        "{%0,%1,%2,%3}, {%4,%5,%6,%7}, {%8,%9}, {%0,%1,%2,%3};"
        : "+f"(c[0]), "+f"(c[1]), "+f"(c[2]), "+f"(c[3])
        : "r"(a0), "r"(a1), "r"(a2), "r"(a3), "r"(b0), "r"(b1));
}

// ---------------- scratch (device globals: no allocation allowed) ----------
__device__ int g_cnt0[NB], g_cnt1[NA], g_cnt2[NA];
__device__ int g_ptr0[NB + 1], g_ptr1[NA + 1], g_ptr2[NA + 1];
__device__ int g_wofs0[NB], g_wofs1[NA], g_wofs2[NA];
__device__ int g_col0[EMAX], g_col1[EMAX], g_col2[EMAX];
__device__ int g_csum[3 * 64];
// fp16 everywhere on the combine path (exact under tf32's 10-bit mantissa)
__device__ __align__(16) __half g_m0[NB * DD];
__device__ __align__(16) __half g_m1[NA * DD];
__device__ __align__(16) __half g_m2[NA * DD];
__device__ __align__(16) __half g_hA[NA * DD];
__device__ __align__(16) __half g_hB[NB * DD];
__device__ __align__(16) __half g_hA1[NA * DD];
__device__ __align__(16) __half g_hB1[NB * DD];
// half2 B-fragments: A-side [Wn1;Wn2;Wrs] = 24 ktiles, B-side [Wn;Wr] = 16
// layout: [ktile][ntile 8][lane 32] half2 = {B[k][n], B[k+4][n]}
__device__ __align__(16) __half2 g_fragA[2][24 * 8 * 32];
__device__ __align__(16) __half2 g_fragB[2][16 * 8 * 32];
__device__ float g_bias[2][128];   // [l][0:64]=A bias, [64:128]=B bias

// ---------------- fp32 -> fp16 feature conversion ----------------------------
__global__ void conv_kernel(const float* __restrict__ xA, const float* __restrict__ xB) {
    int i = blockIdx.x * blockDim.x + threadIdx.x;
    int stride = gridDim.x * blockDim.x;
    const int n8 = NA * 8;
    for (int k = i; k < n8; k += stride) {
        float4 f0 = __ldg((const float4*)xA + k * 2);
        float4 f1 = __ldg((const float4*)xA + k * 2 + 1);
        __half2 h0 = __floats2half2_rn(f0.x, f0.y);
        __half2 h1 = __floats2half2_rn(f0.z, f0.w);
        __half2 h2 = __floats2half2_rn(f1.x, f1.y);
        __half2 h3 = __floats2half2_rn(f1.z, f1.w);
        uint4 o;
        o.x = *(unsigned*)&h0; o.y = *(unsigned*)&h1;
        o.z = *(unsigned*)&h2; o.w = *(unsigned*)&h3;
        ((uint4*)g_hA)[k] = o;
    }
    const int m8 = NB * 8;
    for (int k = i; k < m8; k += stride) {
        float4 f0 = __ldg((const float4*)xB + k * 2);
        float4 f1 = __ldg((const float4*)xB + k * 2 + 1);
        __half2 h0 = __floats2half2_rn(f0.x, f0.y);
        __half2 h1 = __floats2half2_rn(f0.z, f0.w);
        __half2 h2 = __floats2half2_rn(f1.x, f1.y);
        __half2 h3 = __floats2half2_rn(f1.z, f1.w);
        uint4 o;
        o.x = *(unsigned*)&h0; o.y = *(unsigned*)&h1;
        o.z = *(unsigned*)&h2; o.w = *(unsigned*)&h3;
        ((uint4*)g_hB)[k] = o;
    }
}

// ---------------- CSR build: histogram --------------------------------------
__global__ void hist_kernel(const int* __restrict__ d0,
                            const int* __restrict__ d1,
                            const int* __restrict__ d2,
                            int E0, int E1, int E2) {
    int i = blockIdx.x * blockDim.x + threadIdx.x;
    int stride = gridDim.x * blockDim.x;
    for (int e = i; e < E0; e += stride) atomicAdd(&g_cnt0[__ldg(d0 + e)], 1);
    for (int e = i; e < E1; e += stride) atomicAdd(&g_cnt1[__ldg(d1 + e)], 1);
    for (int e = i; e < E2; e += stride) atomicAdd(&g_cnt2[__ldg(d2 + e)], 1);
}

// ---------------- CSR build: chunk sums -------------------------------------
__global__ void chunk_sum_kernel() {
    int type = blockIdx.x / NCH, ch = blockIdx.x % NCH;
    const int* cnt = (type == 0) ? g_cnt0 : (type == 1) ? g_cnt1 : g_cnt2;
    int N = (type == 0) ? NB : NA;
    int i0 = ch * 2048 + threadIdx.x * 8;
    int s = 0;
#pragma unroll
    for (int k = 0; k < 8; k++) {
        int i = i0 + k;
        if (i < N) s += cnt[i];
    }
    __shared__ int red[256];
    red[threadIdx.x] = s;
    __syncthreads();
    for (int o = 128; o > 0; o >>= 1) {
        if (threadIdx.x < o) red[threadIdx.x] += red[threadIdx.x + o];
        __syncthreads();
    }
    if (threadIdx.x == 0) g_csum[type * 64 + ch] = red[0];
}

// ---------------- CSR build: write ptr (chunk prefix via smem) --------------
__global__ void write_ptr_kernel(int E0, int E1, int E2) {
    int type = blockIdx.x / NCH, ch = blockIdx.x % NCH;
    const int* cnt; int* ptr; int* wofs; int N;
    if (type == 0)      { cnt = g_cnt0; ptr = g_ptr0; wofs = g_wofs0; N = NB; }
    else if (type == 1) { cnt = g_cnt1; ptr = g_ptr1; wofs = g_wofs1; N = NA; }
    else                { cnt = g_cnt2; ptr = g_ptr2; wofs = g_wofs2; N = NA; }

    if (threadIdx.x == 0 && ch == 0) {
        if (type == 0) g_ptr0[NB] = E0;
        else if (type == 1) g_ptr1[NA] = E1;
        else g_ptr2[NA] = E2;
    }

    __shared__ int csh[NCH];
    if (threadIdx.x < NCH) csh[threadIdx.x] = __ldg(&g_csum[type * 64 + threadIdx.x]);

    int i0 = ch * 2048 + threadIdx.x * 8;
    int c[8];
    int s = 0;
#pragma unroll
    for (int k = 0; k < 8; k++) {
        int i = i0 + k;
        c[k] = (i < N) ? cnt[i] : 0;
        s += c[k];
    }
    __shared__ int sd[256];
    sd[threadIdx.x] = s;
    __syncthreads();
    for (int o = 1; o < 256; o <<= 1) {
        int v = (threadIdx.x >= o) ? sd[threadIdx.x - o] : 0;
        __syncthreads();
        sd[threadIdx.x] += v;
        __syncthreads();
    }
    int cbase = 0;
    for (int c2 = 0; c2 < ch; c2++) cbase += csh[c2];
    int base = cbase + sd[threadIdx.x] - s;
#pragma unroll
    for (int k = 0; k < 8; k++) {
        int i = i0 + k;
        if (i < N) {
            ptr[i] = base;
            wofs[i] = base;
            base += c[k];
        }
    }
}

// ---------------- CSR build: scatter src ids into dst-sorted order ----------
__global__ void scatter_kernel(const int* __restrict__ s0, const int* __restrict__ d0,
                               const int* __restrict__ s1, const int* __restrict__ d1,
                               const int* __restrict__ s2, const int* __restrict__ d2,
                               int E0, int E1, int E2) {
    int i = blockIdx.x * blockDim.x + threadIdx.x;
    int stride = gridDim.x * blockDim.x;
    for (int e = i; e < E0; e += stride) {
        int p = atomicAdd(&g_wofs0[__ldg(d0 + e)], 1);
        g_col0[p] = __ldg(s0 + e);
    }
    for (int e = i; e < E1; e += stride) {
        int p = atomicAdd(&g_wofs1[__ldg(d1 + e)], 1);
        g_col1[p] = __ldg(s1 + e);
    }
    for (int e = i; e < E2; e += stride) {
        int p = atomicAdd(&g_wofs2[__ldg(d2 + e)], 1);
        g_col2[p] = __ldg(s2 + e);
    }
}

// ---------------- weight prep: fold + emit half2 B-fragments ----------------
__global__ void prep_kernel(const float* __restrict__ Wn, const float* __restrict__ Wr,
                            const float* __restrict__ b,
                            const float* __restrict__ Wout, const float* __restrict__ bout) {
    if (blockIdx.x < 10) {
        int l = blockIdx.x / 5, m = blockIdx.x % 5;
        __shared__ float S[4096];
        __shared__ float T[4096];
        for (int i = threadIdx.x; i < 4096; i += blockDim.x) {
            float v;
            if (m == 0)      v = Wn[(l * 3 + 1) * 4096 + i];
            else if (m == 1) v = Wn[(l * 3 + 2) * 4096 + i];
            else if (m == 2) v = Wr[(l * 3 + 1) * 4096 + i] + Wr[(l * 3 + 2) * 4096 + i];
            else if (m == 3) v = Wn[(l * 3 + 0) * 4096 + i];
            else             v = Wr[(l * 3 + 0) * 4096 + i];
            S[i] = v;
        }
        __syncthreads();
        const float* src = S;
        if (l == 1) {
            for (int o = threadIdx.x; o < 4096; o += blockDim.x) {
                int i = o >> 6, j = o & 63;
                float acc = 0.f;
#pragma unroll 16
                for (int k = 0; k < 64; k++)
                    acc += S[i * 64 + k] * __ldg(Wout + k * 64 + j);
                T[o] = acc;
            }
            __syncthreads();
            src = T;
        }
        __half2* dst = (m < 3) ? (g_fragA[l] + m * 2048) : (g_fragB[l] + (m - 3) * 2048);
        for (int o = threadIdx.x; o < 2048; o += blockDim.x) {
            int lane = o & 31, nt = (o >> 5) & 7, kt2 = o >> 8;
            int k = kt2 * 8 + (lane & 3);
            int j = nt * 8 + (lane >> 2);
            dst[o] = __floats2half2_rn(src[k * 64 + j], src[(k + 4) * 64 + j]);
        }
    } else {
        int j = threadIdx.x;
        if (j < 64) {
            g_bias[0][j]      = b[1 * 64 + j] + b[2 * 64 + j];
            g_bias[0][64 + j] = b[j];
            float accA = 0.f, accB = 0.f;
            for (int k = 0; k < 64; k++) {
                float w = __ldg(Wout + k * 64 + j);
                accA += (b[4 * 64 + k] + b[5 * 64 + k]) * w;
                accB += b[3 * 64 + k] * w;
            }
            g_bias[1][j]      = accA + bout[j];
            g_bias[1][64 + j] = accB + bout[j];
        }
    }
}

// ---------------- atomic-free CSR gather: fp16 in, fp32 accum, fp16 out -----
__device__ __forceinline__ void acc_u4(uint4 u, float2* A) {
    const __half2* h = (const __half2*)&u;
    float2 f;
    f = __half22float2(h[0]); A[0].x += f.x; A[0].y += f.y;
    f = __half22float2(h[1]); A[1].x += f.x; A[1].y += f.y;
    f = __half22float2(h[2]); A[2].x += f.x; A[2].y += f.y;
    f = __half22float2(h[3]); A[3].x += f.x; A[3].y += f.y;
}

__global__ __launch_bounds__(256, 6)
void gather_kernel(const __half* __restrict__ hA, const __half* __restrict__ hB,
                   int nb0, int nb01) {
    int bid = blockIdx.x;
    const __half* x; const int* ptr; const int* col; __half* m; int row0;
    if (bid < nb0)       { row0 = bid * 32;          x = hA; ptr = g_ptr0; col = g_col0; m = g_m0; }
    else if (bid < nb01) { row0 = (bid - nb0) * 32;  x = hB; ptr = g_ptr1; col = g_col1; m = g_m1; }
    else                 { row0 = (bid - nb01) * 32; x = hA; ptr = g_ptr2; col = g_col2; m = g_m2; }

    int g = threadIdx.x >> 3;
    int c = threadIdx.x & 7;
    int n = row0 + g;
    int beg = __ldg(ptr + n), end = __ldg(ptr + n + 1);
    const uint4* X = (const uint4*)x;

    float2 A[4];
    A[0] = A[1] = A[2] = A[3] = make_float2(0.f, 0.f);

    int k = beg;
    while (k + 3 < end) {
        int i0 = __ldg(col + k);
        int i1 = __ldg(col + k + 1);
        int i2 = __ldg(col + k + 2);
        int i3 = __ldg(col + k + 3);
        uint4 u0 = __ldg(X + (size_t)i0 * 8 + c);
        uint4 u1 = __ldg(X + (size_t)i1 * 8 + c);
        uint4 u2 = __ldg(X + (size_t)i2 * 8 + c);
        uint4 u3 = __ldg(X + (size_t)i3 * 8 + c);
        acc_u4(u0, A); acc_u4(u1, A); acc_u4(u2, A); acc_u4(u3, A);
        k += 4;
    }
    while (k < end) {
        int i0 = __ldg(col + k);
        acc_u4(__ldg(X + (size_t)i0 * 8 + c), A);
        k++;
    }

    float inv = 1.0f / fmaxf((float)(end - beg), 1.0f);
    __half2 h0 = __floats2half2_rn(A[0].x * inv, A[0].y * inv);
    __half2 h1 = __floats2half2_rn(A[1].x * inv, A[1].y * inv);
    __half2 h2 = __floats2half2_rn(A[2].x * inv, A[2].y * inv);
    __half2 h3 = __floats2half2_rn(A[3].x * inv, A[3].y * inv);
    uint4 o;
    o.x = *(unsigned*)&h0; o.y = *(unsigned*)&h1;
    o.z = *(unsigned*)&h2; o.w = *(unsigned*)&h3;
    ((uint4*)(m + (size_t)n * 64))[c] = o;
}

// ---------------- combine via tf32 tensor cores (all-fp16 sources) ----------
// 64 rows/block, 8 warps: warp = (mtile 0..3, nhalf 0..1) -> m16 x n32 strip.
// A-side K=192 ([m1|m2|x]); B-side K=128 ([m0|x]).
// smem: X tile 64 x 196 f32 (from fp16 sources -> values are tf32-exact,
// so no cvt needed before MMA) + half2 frag table.
#define XSTR 196
template<bool FP32OUT>
__global__ __launch_bounds__(256) void combine_kernel(
    const __half* __restrict__ hxA, const __half* __restrict__ hxB,
    const __half2* __restrict__ fragA, const __half2* __restrict__ fragB,
    const float* __restrict__ bl,
    float* __restrict__ outA, float* __restrict__ outB,
    __half* __restrict__ houtA, __half* __restrict__ houtB, int nbA) {
    extern __shared__ float sx[];
    __half2* sfrag = (__half2*)(sx + 64 * XSTR);
    const int lane = threadIdx.x & 31;
    const int warp = threadIdx.x >> 5;
    const int mt = warp & 3;
    const int nh = warp >> 2;
    const int r8 = lane >> 2;
    const int c4 = lane & 3;

    bool isA = (blockIdx.x < nbA);
    int row0, rows, KT;
    float* outX;
    __half* houtX;
    const float* blx;
    if (isA) {
        row0 = blockIdx.x * 64;
        rows = NA - row0 < 64 ? NA - row0 : 64;
        KT = 24;
        outX = outA; houtX = houtA; blx = bl;
        // stage [m1|m2|x]: 64 rows x 3 segs x 8 uint4 (8 halves each)
        for (int i = threadIdx.x; i < 1536; i += 256) {
            int r = i / 24, s8 = i % 24;
            int seg = s8 >> 3, q = s8 & 7;
            float4 lo = make_float4(0.f, 0.f, 0.f, 0.f);
            float4 hi = make_float4(0.f, 0.f, 0.f, 0.f);
            if (r < rows) {
                const uint4* sp = (seg == 0) ? (const uint4*)g_m1
                                 : (seg == 1) ? (const uint4*)g_m2
                                              : (const uint4*)hxA;
                uint4 u = __ldg(sp + (size_t)(row0 + r) * 8 + q);
                const __half2* hp = (const __half2*)&u;
                float2 f0 = __half22float2(hp[0]);
                float2 f1 = __half22float2(hp[1]);
                float2 f2 = __half22float2(hp[2]);
                float2 f3 = __half22float2(hp[3]);
                lo = make_float4(f0.x, f0.y, f1.x, f1.y);
                hi = make_float4(f2.x, f2.y, f3.x, f3.y);
            }
            float* dp = &sx[r * XSTR + seg * 64 + q * 8];
            *(float4*)dp = lo;
            *(float4*)(dp + 4) = hi;
        }
        for (int i = threadIdx.x; i < 24 * 64; i += 256)
            ((uint4*)sfrag)[i] = __ldg((const uint4*)fragA + i);
    } else {
        row0 = (blockIdx.x - nbA) * 64;
        rows = NB - row0 < 64 ? NB - row0 : 64;
        KT = 16;
        outX = outB; houtX = houtB; blx = bl + 64;
        for (int i = threadIdx.x; i < 1024; i += 256) {
            int r = i >> 4, s8 = i & 15;
            int seg = s8 >> 3, q = s8 & 7;
            float4 lo = make_float4(0.f, 0.f, 0.f, 0.f);
            float4 hi = make_float4(0.f, 0.f, 0.f, 0.f);
            if (r < rows) {
                const uint4* sp = (seg == 0) ? (const uint4*)g_m0
                                              : (const uint4*)hxB;
                uint4 u = __ldg(sp + (size_t)(row0 + r) * 8 + q);
                const __half2* hp = (const __half2*)&u;
                float2 f0 = __half22float2(hp[0]);
                float2 f1 = __half22float2(hp[1]);
                float2 f2 = __half22float2(hp[2]);
                float2 f3 = __half22float2(hp[3]);
                lo = make_float4(f0.x, f0.y, f1.x, f1.y);
                hi = make_float4(f2.x, f2.y, f3.x, f3.y);
            }
            float* dp = &sx[r * XSTR + seg * 64 + q * 8];
            *(float4*)dp = lo;
            *(float4*)(dp + 4) = hi;
        }
        for (int i = threadIdx.x; i < 16 * 64; i += 256)
            ((uint4*)sfrag)[i] = __ldg((const uint4*)fragB + i);
    }
    __syncthreads();

    float acc[4][4];
#pragma unroll
    for (int t = 0; t < 4; t++) {
        acc[t][0] = 0.f; acc[t][1] = 0.f; acc[t][2] = 0.f; acc[t][3] = 0.f;
    }

    const float* xp0 = sx + (mt * 16 + r8) * XSTR + c4;
    for (int kt = 0; kt < KT; kt++) {
        const float* xp = xp0 + kt * 8;
        // fp16-sourced floats have <=10-bit mantissas: already exact tf32.
        unsigned a0 = __float_as_uint(xp[0]);
        unsigned a1 = __float_as_uint(xp[8 * XSTR]);
        unsigned a2 = __float_as_uint(xp[4]);
        unsigned a3 = __float_as_uint(xp[8 * XSTR + 4]);
        const __half2* fp = sfrag + (kt * 8 + nh * 4) * 32 + lane;
#pragma unroll
        for (int t = 0; t < 4; t++) {
            float2 fb = __half22float2(fp[t * 32]);
            mma_tf32(acc[t], a0, a1, a2, a3,
                     __float_as_uint(fb.x), __float_as_uint(fb.y));
        }
    }

    // epilogue: +bias (, relu), store
    int r0 = mt * 16 + r8;
#pragma unroll
    for (int t = 0; t < 4; t++) {
        int colj = (nh * 4 + t) * 8 + c4 * 2;
        float b0 = __ldg(blx + colj), b1 = __ldg(blx + colj + 1);
        float v00 = acc[t][0] + b0, v01 = acc[t][1] + b1;
        float v10 = acc[t][2] + b0, v11 = acc[t][3] + b1;
        if (FP32OUT) {
            v00 = fmaxf(v00, 0.f); v01 = fmaxf(v01, 0.f);
            v10 = fmaxf(v10, 0.f); v11 = fmaxf(v11, 0.f);
            if (r0 < rows)
                *(float2*)&outX[(size_t)(row0 + r0) * 64 + colj] = make_float2(v00, v01);
            if (r0 + 8 < rows)
                *(float2*)&outX[(size_t)(row0 + r0 + 8) * 64 + colj] = make_float2(v10, v11);
        } else {
            if (r0 < rows)
                *(__half2*)&houtX[(size_t)(row0 + r0) * 64 + colj] = __floats2half2_rn(v00, v01);
            if (r0 + 8 < rows)
                *(__half2*)&houtX[(size_t)(row0 + r0 + 8) * 64 + colj] = __floats2half2_rn(v10, v11);
        }
    }
}

// ---------------- launcher --------------------------------------------------
extern "C" void kernel_launch(void* const* d_in, const int* in_sizes, int n_in,
                              void* d_out, int out_size) {
    const float* x_A   = (const float*)d_in[0];
    const float* x_B   = (const float*)d_in[1];
    const float* Wn    = (const float*)d_in[2];
    const float* Wr    = (const float*)d_in[3];
    const float* b     = (const float*)d_in[4];
    const float* W_out = (const float*)d_in[5];
    const float* b_out = (const float*)d_in[6];
    const int* src0 = (const int*)d_in[7];
    const int* dst0 = (const int*)d_in[8];
    const int* src1 = (const int*)d_in[9];
    const int* dst1 = (const int*)d_in[10];
    const int* src2 = (const int*)d_in[11];
    const int* dst2 = (const int*)d_in[12];
    const int E0 = in_sizes[7];
    const int E1 = in_sizes[9];
    const int E2 = in_sizes[11];
    float* out = (float*)d_out;

    float *bias0, *bias1;
    __half2 *frA, *frB;
    __half *hA, *hB, *hA1, *hB1;
    int *cnt0, *cnt1, *cnt2;
    cudaGetSymbolAddress((void**)&hA, g_hA);
    cudaGetSymbolAddress((void**)&hB, g_hB);
    cudaGetSymbolAddress((void**)&hA1, g_hA1);
    cudaGetSymbolAddress((void**)&hB1, g_hB1);
    cudaGetSymbolAddress((void**)&cnt0, g_cnt0);
    cudaGetSymbolAddress((void**)&cnt1, g_cnt1);
    cudaGetSymbolAddress((void**)&cnt2, g_cnt2);
    cudaGetSymbolAddress((void**)&frA, g_fragA);
    cudaGetSymbolAddress((void**)&frB, g_fragB);
    cudaGetSymbolAddress((void**)&bias0, g_bias);
    bias1 = bias0 + 128;

    const int nb0 = NB / 32, nb1 = NA / 32, nb2 = NA / 32;
    const int gatherBlocks = nb0 + nb1 + nb2;
    const int nbA = (NA + 63) / 64;
    const int nbB = (NB + 63) / 64;
    const int smemBytes = 64 * XSTR * 4 + 24 * 256 * 4;   // 50176 + 24576 = 74752

    cudaFuncSetAttribute(combine_kernel<false>,
                         cudaFuncAttributeMaxDynamicSharedMemorySize, smemBytes);
    cudaFuncSetAttribute(combine_kernel<true>,
                         cudaFuncAttributeMaxDynamicSharedMemorySize, smemBytes);

    // ---- prep: weights + fp16 feature conversion (independent of CSR) ----
    prep_kernel<<<11, 256>>>(Wn, Wr, b, W_out, b_out);
    conv_kernel<<<1024, 256>>>(x_A, x_B);

    // ---- CSR build ----
    cudaMemsetAsync(cnt0, 0, NB * sizeof(int));
    cudaMemsetAsync(cnt1, 0, NA * sizeof(int));
    cudaMemsetAsync(cnt2, 0, NA * sizeof(int));
    hist_kernel<<<1024, 256>>>(dst0, dst1, dst2, E0, E1, E2);
    chunk_sum_kernel<<<3 * NCH, 256>>>();
    write_ptr_kernel<<<3 * NCH, 256>>>(E0, E1, E2);
    scatter_kernel<<<1024, 256>>>(src0, dst0, src1, dst1, src2, dst2, E0, E1, E2);

    // ---- layer 0 (outputs fp16 only) ----
    gather_kernel<<<gatherBlocks, 256>>>(hA, hB, nb0, nb0 + nb1);
    combine_kernel<false><<<nbA + nbB, 256, smemBytes>>>(
        hA, hB, frA, frB, bias0, nullptr, nullptr, hA1, hB1, nbA);

    // ---- layer 1 (head folded into weights; relu at store; fp32 out) ----
    gather_kernel<<<gatherBlocks, 256>>>(hA1, hB1, nb0, nb0 + nb1);
    combine_kernel<true><<<nbA + nbB, 256, smemBytes>>>(
        hA1, hB1, frA + 24 * 256, frB + 16 * 256, bias1,
        out, out + (size_t)NA * 64, nullptr, nullptr, nbA);
}

// round 12
// speedup vs baseline: 3.2903x; 1.0902x over previous
#include <cuda_runtime.h>
#include <cuda_fp16.h>
#include <cstddef>

#define NA 100000
#define NB 100000
#define DD 64
#define EMAX 1250000
#define NCH 49          // chunks of 2048 nodes: 49*2048 >= 100000

// ---------------- fp16 mma helper (m16n8k16, fp32 accum) --------------------
__device__ __forceinline__ void mma_f16(float* c, unsigned a0, unsigned a1,
                                        unsigned a2, unsigned a3,
                                        unsigned b0, unsigned b1) {
    asm("mma.sync.aligned.m16n8k16.row.col.f32.f16.f16.f32 "
        "{%0,%1,%2,%3}, {%4,%5,%6,%7}, {%8,%9}, {%0,%1,%2,%3};"
        : "+f"(c[0]), "+f"(c[1]), "+f"(c[2]), "+f"(c[3])
        : "r"(a0), "r"(a1), "r"(a2), "r"(a3), "r"(b0), "r"(b1));
}

// ---------------- scratch (device globals: no allocation allowed) ----------
__device__ int g_cnt0[NB], g_cnt1[NA], g_cnt2[NA];
__device__ int g_ptr0[NB + 1], g_ptr1[NA + 1], g_ptr2[NA + 1];
__device__ int g_wofs0[NB], g_wofs1[NA], g_wofs2[NA];
__device__ int g_col0[EMAX], g_col1[EMAX], g_col2[EMAX];
__device__ int g_csum[3 * 64];
// fp16 everywhere on the combine path
__device__ __align__(16) __half g_m0[NB * DD];
__device__ __align__(16) __half g_m1[NA * DD];
__device__ __align__(16) __half g_m2[NA * DD];
__device__ __align__(16) __half g_hA[NA * DD];
__device__ __align__(16) __half g_hB[NB * DD];
__device__ __align__(16) __half g_hA1[NA * DD];
__device__ __align__(16) __half g_hB1[NB * DD];
// fp16-MMA B-fragments. Per (ktile16, ntile8): 64 half2 = {b0 plane 32, b1 plane 32}
// A-side K=192 -> 12 ktiles; B-side K=128 -> 8 ktiles.
__device__ __align__(16) __half2 g_fragA[2][12 * 8 * 64];
__device__ __align__(16) __half2 g_fragB[2][8 * 8 * 64];
__device__ float g_bias[2][128];   // [l][0:64]=A bias, [64:128]=B bias

// ---------------- fp32 -> fp16 feature conversion ----------------------------
__global__ void conv_kernel(const float* __restrict__ xA, const float* __restrict__ xB) {
    int i = blockIdx.x * blockDim.x + threadIdx.x;
    int stride = gridDim.x * blockDim.x;
    const int n8 = NA * 8;
    for (int k = i; k < n8; k += stride) {
        float4 f0 = __ldg((const float4*)xA + k * 2);
        float4 f1 = __ldg((const float4*)xA + k * 2 + 1);
        __half2 h0 = __floats2half2_rn(f0.x, f0.y);
        __half2 h1 = __floats2half2_rn(f0.z, f0.w);
        __half2 h2 = __floats2half2_rn(f1.x, f1.y);
        __half2 h3 = __floats2half2_rn(f1.z, f1.w);
        uint4 o;
        o.x = *(unsigned*)&h0; o.y = *(unsigned*)&h1;
        o.z = *(unsigned*)&h2; o.w = *(unsigned*)&h3;
        ((uint4*)g_hA)[k] = o;
    }
    const int m8 = NB * 8;
    for (int k = i; k < m8; k += stride) {
        float4 f0 = __ldg((const float4*)xB + k * 2);
        float4 f1 = __ldg((const float4*)xB + k * 2 + 1);
        __half2 h0 = __floats2half2_rn(f0.x, f0.y);
        __half2 h1 = __floats2half2_rn(f0.z, f0.w);
        __half2 h2 = __floats2half2_rn(f1.x, f1.y);
        __half2 h3 = __floats2half2_rn(f1.z, f1.w);
        uint4 o;
        o.x = *(unsigned*)&h0; o.y = *(unsigned*)&h1;
        o.z = *(unsigned*)&h2; o.w = *(unsigned*)&h3;
        ((uint4*)g_hB)[k] = o;
    }
}

// ---------------- CSR build: histogram --------------------------------------
__global__ void hist_kernel(const int* __restrict__ d0,
                            const int* __restrict__ d1,
                            const int* __restrict__ d2,
                            int E0, int E1, int E2) {
    int i = blockIdx.x * blockDim.x + threadIdx.x;
    int stride = gridDim.x * blockDim.x;
    for (int e = i; e < E0; e += stride) atomicAdd(&g_cnt0[__ldg(d0 + e)], 1);
    for (int e = i; e < E1; e += stride) atomicAdd(&g_cnt1[__ldg(d1 + e)], 1);
    for (int e = i; e < E2; e += stride) atomicAdd(&g_cnt2[__ldg(d2 + e)], 1);
}

// ---------------- CSR build: chunk sums -------------------------------------
__global__ void chunk_sum_kernel() {
    int type = blockIdx.x / NCH, ch = blockIdx.x % NCH;
    const int* cnt = (type == 0) ? g_cnt0 : (type == 1) ? g_cnt1 : g_cnt2;
    int N = (type == 0) ? NB : NA;
    int i0 = ch * 2048 + threadIdx.x * 8;
    int s = 0;
#pragma unroll
    for (int k = 0; k < 8; k++) {
        int i = i0 + k;
        if (i < N) s += cnt[i];
    }
    __shared__ int red[256];
    red[threadIdx.x] = s;
    __syncthreads();
    for (int o = 128; o > 0; o >>= 1) {
        if (threadIdx.x < o) red[threadIdx.x] += red[threadIdx.x + o];
        __syncthreads();
    }
    if (threadIdx.x == 0) g_csum[type * 64 + ch] = red[0];
}

// ---------------- CSR build: write ptr (chunk prefix via smem) --------------
__global__ void write_ptr_kernel(int E0, int E1, int E2) {
    int type = blockIdx.x / NCH, ch = blockIdx.x % NCH;
    const int* cnt; int* ptr; int* wofs; int N;
    if (type == 0)      { cnt = g_cnt0; ptr = g_ptr0; wofs = g_wofs0; N = NB; }
    else if (type == 1) { cnt = g_cnt1; ptr = g_ptr1; wofs = g_wofs1; N = NA; }
    else                { cnt = g_cnt2; ptr = g_ptr2; wofs = g_wofs2; N = NA; }

    if (threadIdx.x == 0 && ch == 0) {
        if (type == 0) g_ptr0[NB] = E0;
        else if (type == 1) g_ptr1[NA] = E1;
        else g_ptr2[NA] = E2;
    }

    __shared__ int csh[NCH];
    if (threadIdx.x < NCH) csh[threadIdx.x] = __ldg(&g_csum[type * 64 + threadIdx.x]);

    int i0 = ch * 2048 + threadIdx.x * 8;
    int c[8];
    int s = 0;
#pragma unroll
    for (int k = 0; k < 8; k++) {
        int i = i0 + k;
        c[k] = (i < N) ? cnt[i] : 0;
        s += c[k];
    }
    __shared__ int sd[256];
    sd[threadIdx.x] = s;
    __syncthreads();
    for (int o = 1; o < 256; o <<= 1) {
        int v = (threadIdx.x >= o) ? sd[threadIdx.x - o] : 0;
        __syncthreads();
        sd[threadIdx.x] += v;
        __syncthreads();
    }
    int cbase = 0;
    for (int c2 = 0; c2 < ch; c2++) cbase += csh[c2];
    int base = cbase + sd[threadIdx.x] - s;
#pragma unroll
    for (int k = 0; k < 8; k++) {
        int i = i0 + k;
        if (i < N) {
            ptr[i] = base;
            wofs[i] = base;
            base += c[k];
        }
    }
}

// ---------------- CSR build: scatter src ids into dst-sorted order ----------
__global__ void scatter_kernel(const int* __restrict__ s0, const int* __restrict__ d0,
                               const int* __restrict__ s1, const int* __restrict__ d1,
                               const int* __restrict__ s2, const int* __restrict__ d2,
                               int E0, int E1, int E2) {
    int i = blockIdx.x * blockDim.x + threadIdx.x;
    int stride = gridDim.x * blockDim.x;
    for (int e = i; e < E0; e += stride) {
        int p = atomicAdd(&g_wofs0[__ldg(d0 + e)], 1);
        g_col0[p] = __ldg(s0 + e);
    }
    for (int e = i; e < E1; e += stride) {
        int p = atomicAdd(&g_wofs1[__ldg(d1 + e)], 1);
        g_col1[p] = __ldg(s1 + e);
    }
    for (int e = i; e < E2; e += stride) {
        int p = atomicAdd(&g_wofs2[__ldg(d2 + e)], 1);
        g_col2[p] = __ldg(s2 + e);
    }
}

// ---------------- weight prep: fold + emit fp16-MMA B-fragments -------------
// blocks 0..9: matrix m of layer l; block 10: biases.
// Each 64x64 matrix = 4 local ktiles (16 k each). Fragment planes per
// (gkt, nt): [0:32)=b0 {W[k0][n],W[k0+1][n]}, [32:64)=b1 {W[k0+8],W[k0+9]},
// with k0 = gkt*16 + (lane&3)*2, n = nt*8 + (lane>>2).
__global__ void prep_kernel(const float* __restrict__ Wn, const float* __restrict__ Wr,
                            const float* __restrict__ b,
                            const float* __restrict__ Wout, const float* __restrict__ bout) {
    if (blockIdx.x < 10) {
        int l = blockIdx.x / 5, m = blockIdx.x % 5;
        __shared__ float S[4096];
        __shared__ float T[4096];
        for (int i = threadIdx.x; i < 4096; i += blockDim.x) {
            float v;
            if (m == 0)      v = Wn[(l * 3 + 1) * 4096 + i];
            else if (m == 1) v = Wn[(l * 3 + 2) * 4096 + i];
            else if (m == 2) v = Wr[(l * 3 + 1) * 4096 + i] + Wr[(l * 3 + 2) * 4096 + i];
            else if (m == 3) v = Wn[(l * 3 + 0) * 4096 + i];
            else             v = Wr[(l * 3 + 0) * 4096 + i];
            S[i] = v;
        }
        __syncthreads();
        const float* src = S;
        if (l == 1) {
            for (int o = threadIdx.x; o < 4096; o += blockDim.x) {
                int i = o >> 6, j = o & 63;
                float acc = 0.f;
#pragma unroll 16
                for (int k = 0; k < 64; k++)
                    acc += S[i * 64 + k] * __ldg(Wout + k * 64 + j);
                T[o] = acc;
            }
            __syncthreads();
            src = T;
        }
        __half2* dst;
        int ktbase;
        if (m < 3) { dst = g_fragA[l]; ktbase = m * 4; }
        else       { dst = g_fragB[l]; ktbase = (m - 3) * 4; }
        for (int o = threadIdx.x; o < 1024; o += blockDim.x) {
            int kt2 = o >> 8, nt = (o >> 5) & 7, lane = o & 31;
            int k0 = kt2 * 16 + (lane & 3) * 2;
            int n = nt * 8 + (lane >> 2);
            int plane = ((ktbase + kt2) * 8 + nt) * 64 + lane;
            dst[plane]      = __floats2half2_rn(src[k0 * 64 + n], src[(k0 + 1) * 64 + n]);
            dst[plane + 32] = __floats2half2_rn(src[(k0 + 8) * 64 + n], src[(k0 + 9) * 64 + n]);
        }
    } else {
        int j = threadIdx.x;
        if (j < 64) {
            g_bias[0][j]      = b[1 * 64 + j] + b[2 * 64 + j];
            g_bias[0][64 + j] = b[j];
            float accA = 0.f, accB = 0.f;
            for (int k = 0; k < 64; k++) {
                float w = __ldg(Wout + k * 64 + j);
                accA += (b[4 * 64 + k] + b[5 * 64 + k]) * w;
                accB += b[3 * 64 + k] * w;
            }
            g_bias[1][j]      = accA + bout[j];
            g_bias[1][64 + j] = accB + bout[j];
        }
    }
}

// ---------------- atomic-free CSR gather: fp16 in, fp32 accum, fp16 out -----
__device__ __forceinline__ void acc_u4(uint4 u, float2* A) {
    const __half2* h = (const __half2*)&u;
    float2 f;
    f = __half22float2(h[0]); A[0].x += f.x; A[0].y += f.y;
    f = __half22float2(h[1]); A[1].x += f.x; A[1].y += f.y;
    f = __half22float2(h[2]); A[2].x += f.x; A[2].y += f.y;
    f = __half22float2(h[3]); A[3].x += f.x; A[3].y += f.y;
}

__global__ __launch_bounds__(256, 6)
void gather_kernel(const __half* __restrict__ hA, const __half* __restrict__ hB,
                   int nb0, int nb01) {
    int bid = blockIdx.x;
    const __half* x; const int* ptr; const int* col; __half* m; int row0;
    if (bid < nb0)       { row0 = bid * 32;          x = hA; ptr = g_ptr0; col = g_col0; m = g_m0; }
    else if (bid < nb01) { row0 = (bid - nb0) * 32;  x = hB; ptr = g_ptr1; col = g_col1; m = g_m1; }
    else                 { row0 = (bid - nb01) * 32; x = hA; ptr = g_ptr2; col = g_col2; m = g_m2; }

    int g = threadIdx.x >> 3;
    int c = threadIdx.x & 7;
    int n = row0 + g;
    int beg = __ldg(ptr + n), end = __ldg(ptr + n + 1);
    const uint4* X = (const uint4*)x;

    float2 A[4];
    A[0] = A[1] = A[2] = A[3] = make_float2(0.f, 0.f);

    int k = beg;
    while (k + 3 < end) {
        int i0 = __ldg(col + k);
        int i1 = __ldg(col + k + 1);
        int i2 = __ldg(col + k + 2);
        int i3 = __ldg(col + k + 3);
        uint4 u0 = __ldg(X + (size_t)i0 * 8 + c);
        uint4 u1 = __ldg(X + (size_t)i1 * 8 + c);
        uint4 u2 = __ldg(X + (size_t)i2 * 8 + c);
        uint4 u3 = __ldg(X + (size_t)i3 * 8 + c);
        acc_u4(u0, A); acc_u4(u1, A); acc_u4(u2, A); acc_u4(u3, A);
        k += 4;
    }
    while (k < end) {
        int i0 = __ldg(col + k);
        acc_u4(__ldg(X + (size_t)i0 * 8 + c), A);
        k++;
    }

    float inv = 1.0f / fmaxf((float)(end - beg), 1.0f);
    __half2 h0 = __floats2half2_rn(A[0].x * inv, A[0].y * inv);
    __half2 h1 = __floats2half2_rn(A[1].x * inv, A[1].y * inv);
    __half2 h2 = __floats2half2_rn(A[2].x * inv, A[2].y * inv);
    __half2 h3 = __floats2half2_rn(A[3].x * inv, A[3].y * inv);
    uint4 o;
    o.x = *(unsigned*)&h0; o.y = *(unsigned*)&h1;
    o.z = *(unsigned*)&h2; o.w = *(unsigned*)&h3;
    ((uint4*)(m + (size_t)n * 64))[c] = o;
}

// ---------------- combine via fp16 m16n8k16 tensor cores --------------------
// 64 rows/block, 8 warps: warp = (mtile 0..3, nhalf 0..1) -> m16 x n32 strip.
// A-side K=192 ([m1|m2|x]); B-side K=128 ([m0|x]).
// smem: X tile 64 rows x 200 halves (stride 200 -> A-loads conflict-free)
// followed by the half2 frag table.
#define XH 200   // halves per row
template<bool FP32OUT>
__global__ __launch_bounds__(256) void combine_kernel(
    const __half* __restrict__ hxA, const __half* __restrict__ hxB,
    const __half2* __restrict__ fragA, const __half2* __restrict__ fragB,
    const float* __restrict__ bl,
    float* __restrict__ outA, float* __restrict__ outB,
    __half* __restrict__ houtA, __half* __restrict__ houtB, int nbA) {
    extern __shared__ __align__(16) unsigned smraw[];
    __half* sxh = (__half*)smraw;                       // 64*200 halves = 25600B
    uint4* sxq = (uint4*)smraw;                         // row stride 25 uint4
    __half2* sfrag = (__half2*)((char*)smraw + 25600);
    const int lane = threadIdx.x & 31;
    const int warp = threadIdx.x >> 5;
    const int mt = warp & 3;
    const int nh = warp >> 2;
    const int r8 = lane >> 2;
    const int c4 = lane & 3;

    bool isA = (blockIdx.x < nbA);
    int row0, rows, KT;
    float* outX;
    __half* houtX;
    const float* blx;
    if (isA) {
        row0 = blockIdx.x * 64;
        rows = NA - row0 < 64 ? NA - row0 : 64;
        KT = 12;
        outX = outA; houtX = houtA; blx = bl;
        // stage [m1|m2|x]: 64 rows x 3 segs x 8 uint4 (fp16, no widening)
        for (int i = threadIdx.x; i < 1536; i += 256) {
            int r = i / 24, s8 = i % 24;
            int seg = s8 >> 3, q = s8 & 7;
            uint4 u = make_uint4(0, 0, 0, 0);
            if (r < rows) {
                const uint4* sp = (seg == 0) ? (const uint4*)g_m1
                                 : (seg == 1) ? (const uint4*)g_m2
                                              : (const uint4*)hxA;
                u = __ldg(sp + (size_t)(row0 + r) * 8 + q);
            }
            sxq[r * 25 + seg * 8 + q] = u;
        }
        for (int i = threadIdx.x; i < 1536; i += 256)       // 12*8*64 half2 / 4
            ((uint4*)sfrag)[i] = __ldg((const uint4*)fragA + i);
    } else {
        row0 = (blockIdx.x - nbA) * 64;
        rows = NB - row0 < 64 ? NB - row0 : 64;
        KT = 8;
        outX = outB; houtX = houtB; blx = bl + 64;
        for (int i = threadIdx.x; i < 1024; i += 256) {
            int r = i >> 4, s8 = i & 15;
            int seg = s8 >> 3, q = s8 & 7;
            uint4 u = make_uint4(0, 0, 0, 0);
            if (r < rows) {
                const uint4* sp = (seg == 0) ? (const uint4*)g_m0
                                              : (const uint4*)hxB;
                u = __ldg(sp + (size_t)(row0 + r) * 8 + q);
            }
            sxq[r * 25 + seg * 8 + q] = u;
        }
        for (int i = threadIdx.x; i < 1024; i += 256)       // 8*8*64 half2 / 4
            ((uint4*)sfrag)[i] = __ldg((const uint4*)fragB + i);
    }
    __syncthreads();

    float acc[4][4];
#pragma unroll
    for (int t = 0; t < 4; t++) {
        acc[t][0] = 0.f; acc[t][1] = 0.f; acc[t][2] = 0.f; acc[t][3] = 0.f;
    }

    // A fragment sources: row r = mt*16 + r8 (and +8), k0 = kt*16 + c4*2
    const __half* ap0 = sxh + (mt * 16 + r8) * XH + c4 * 2;
    for (int kt = 0; kt < KT; kt++) {
        const __half* ap = ap0 + kt * 16;
        unsigned a0 = *(const unsigned*)(ap);
        unsigned a1 = *(const unsigned*)(ap + 8 * XH);
        unsigned a2 = *(const unsigned*)(ap + 8);
        unsigned a3 = *(const unsigned*)(ap + 8 * XH + 8);
        const __half2* fp = sfrag + (kt * 8 + nh * 4) * 64 + lane;
#pragma unroll
        for (int t = 0; t < 4; t++) {
            __half2 b0 = fp[t * 64];
            __half2 b1 = fp[t * 64 + 32];
            mma_f16(acc[t], a0, a1, a2, a3,
                    *(unsigned*)&b0, *(unsigned*)&b1);
        }
    }

    // epilogue: +bias (, relu), store
    int r0 = mt * 16 + r8;
#pragma unroll
    for (int t = 0; t < 4; t++) {
        int colj = (nh * 4 + t) * 8 + c4 * 2;
        float b0 = __ldg(blx + colj), b1 = __ldg(blx + colj + 1);
        float v00 = acc[t][0] + b0, v01 = acc[t][1] + b1;
        float v10 = acc[t][2] + b0, v11 = acc[t][3] + b1;
        if (FP32OUT) {
            v00 = fmaxf(v00, 0.f); v01 = fmaxf(v01, 0.f);
            v10 = fmaxf(v10, 0.f); v11 = fmaxf(v11, 0.f);
            if (r0 < rows)
                *(float2*)&outX[(size_t)(row0 + r0) * 64 + colj] = make_float2(v00, v01);
            if (r0 + 8 < rows)
                *(float2*)&outX[(size_t)(row0 + r0 + 8) * 64 + colj] = make_float2(v10, v11);
        } else {
            if (r0 < rows)
                *(__half2*)&houtX[(size_t)(row0 + r0) * 64 + colj] = __floats2half2_rn(v00, v01);
            if (r0 + 8 < rows)
                *(__half2*)&houtX[(size_t)(row0 + r0 + 8) * 64 + colj] = __floats2half2_rn(v10, v11);
        }
    }
}

// ---------------- launcher --------------------------------------------------
extern "C" void kernel_launch(void* const* d_in, const int* in_sizes, int n_in,
                              void* d_out, int out_size) {
    const float* x_A   = (const float*)d_in[0];
    const float* x_B   = (const float*)d_in[1];
    const float* Wn    = (const float*)d_in[2];
    const float* Wr    = (const float*)d_in[3];
    const float* b     = (const float*)d_in[4];
    const float* W_out = (const float*)d_in[5];
    const float* b_out = (const float*)d_in[6];
    const int* src0 = (const int*)d_in[7];
    const int* dst0 = (const int*)d_in[8];
    const int* src1 = (const int*)d_in[9];
    const int* dst1 = (const int*)d_in[10];
    const int* src2 = (const int*)d_in[11];
    const int* dst2 = (const int*)d_in[12];
    const int E0 = in_sizes[7];
    const int E1 = in_sizes[9];
    const int E2 = in_sizes[11];
    float* out = (float*)d_out;

    float *bias0, *bias1;
    __half2 *frA, *frB;
    __half *hA, *hB, *hA1, *hB1;
    int *cnt0, *cnt1, *cnt2;
    cudaGetSymbolAddress((void**)&hA, g_hA);
    cudaGetSymbolAddress((void**)&hB, g_hB);
    cudaGetSymbolAddress((void**)&hA1, g_hA1);
    cudaGetSymbolAddress((void**)&hB1, g_hB1);
    cudaGetSymbolAddress((void**)&cnt0, g_cnt0);
    cudaGetSymbolAddress((void**)&cnt1, g_cnt1);
    cudaGetSymbolAddress((void**)&cnt2, g_cnt2);
    cudaGetSymbolAddress((void**)&frA, g_fragA);
    cudaGetSymbolAddress((void**)&frB, g_fragB);
    cudaGetSymbolAddress((void**)&bias0, g_bias);
    bias1 = bias0 + 128;

    const int nb0 = NB / 32, nb1 = NA / 32, nb2 = NA / 32;
    const int gatherBlocks = nb0 + nb1 + nb2;
    const int nbA = (NA + 63) / 64;
    const int nbB = (NB + 63) / 64;
    const int smemBytes = 25600 + 12 * 8 * 64 * 4;   // X tile + A-side frags = 50176

    cudaFuncSetAttribute(combine_kernel<false>,
                         cudaFuncAttributeMaxDynamicSharedMemorySize, smemBytes);
    cudaFuncSetAttribute(combine_kernel<true>,
                         cudaFuncAttributeMaxDynamicSharedMemorySize, smemBytes);

    // ---- prep: weights + fp16 feature conversion (independent of CSR) ----
    prep_kernel<<<11, 256>>>(Wn, Wr, b, W_out, b_out);
    conv_kernel<<<1024, 256>>>(x_A, x_B);

    // ---- CSR build ----
    cudaMemsetAsync(cnt0, 0, NB * sizeof(int));
    cudaMemsetAsync(cnt1, 0, NA * sizeof(int));
    cudaMemsetAsync(cnt2, 0, NA * sizeof(int));
    hist_kernel<<<1024, 256>>>(dst0, dst1, dst2, E0, E1, E2);
    chunk_sum_kernel<<<3 * NCH, 256>>>();
    write_ptr_kernel<<<3 * NCH, 256>>>(E0, E1, E2);
    scatter_kernel<<<1024, 256>>>(src0, dst0, src1, dst1, src2, dst2, E0, E1, E2);

    // ---- layer 0 (outputs fp16 only) ----
    gather_kernel<<<gatherBlocks, 256>>>(hA, hB, nb0, nb0 + nb1);
    combine_kernel<false><<<nbA + nbB, 256, smemBytes>>>(
        hA, hB, frA, frB, bias0, nullptr, nullptr, hA1, hB1, nbA);

    // ---- layer 1 (head folded into weights; relu at store; fp32 out) ----
    gather_kernel<<<gatherBlocks, 256>>>(hA1, hB1, nb0, nb0 + nb1);
    combine_kernel<true><<<nbA + nbB, 256, smemBytes>>>(
        hA1, hB1, frA + 12 * 8 * 64, frB + 8 * 8 * 64, bias1,
        out, out + (size_t)NA * 64, nullptr, nullptr, nbA);
}

// round 13
// speedup vs baseline: 3.6902x; 1.1215x over previous
#include <cuda_runtime.h>
#include <cuda_fp16.h>
#include <cstddef>

#define NA 100000
#define NB 100000
#define DD 64
#define EMAX 1250000
#define NCH 49          // chunks of 2048 nodes: 49*2048 >= 100000

// ---------------- fp16 mma helper (m16n8k16, fp32 accum) --------------------
__device__ __forceinline__ void mma_f16(float* c, unsigned a0, unsigned a1,
                                        unsigned a2, unsigned a3,
                                        unsigned b0, unsigned b1) {
    asm("mma.sync.aligned.m16n8k16.row.col.f32.f16.f16.f32 "
        "{%0,%1,%2,%3}, {%4,%5,%6,%7}, {%8,%9}, {%0,%1,%2,%3};"
        : "+f"(c[0]), "+f"(c[1]), "+f"(c[2]), "+f"(c[3])
        : "r"(a0), "r"(a1), "r"(a2), "r"(a3), "r"(b0), "r"(b1));
}

// ---------------- scratch (device globals: no allocation allowed) ----------
__device__ int g_cnt0[NB], g_cnt1[NA], g_cnt2[NA];
__device__ int g_ptr0[NB + 1], g_ptr1[NA + 1], g_ptr2[NA + 1];
__device__ int g_wofs0[NB], g_wofs1[NA], g_wofs2[NA];
__device__ int g_col0[EMAX], g_col1[EMAX], g_col2[EMAX];
__device__ int g_csum[3 * 64];
// fp16 feature tables
__device__ __align__(16) __half g_hA[NA * DD];
__device__ __align__(16) __half g_hB[NB * DD];
__device__ __align__(16) __half g_hA1[NA * DD];
__device__ __align__(16) __half g_hB1[NB * DD];
// fp16-MMA B-fragments. Per (ktile16, ntile8): 64 half2 = {b0 plane 32, b1 plane 32}
// A-side K=192 -> 12 ktiles; B-side K=128 -> 8 ktiles.
__device__ __align__(16) __half2 g_fragA[2][12 * 8 * 64];
__device__ __align__(16) __half2 g_fragB[2][8 * 8 * 64];
__device__ float g_bias[2][128];   // [l][0:64]=A bias, [64:128]=B bias

// ---------------- fp32 -> fp16 feature conversion ----------------------------
__global__ void conv_kernel(const float* __restrict__ xA, const float* __restrict__ xB) {
    int i = blockIdx.x * blockDim.x + threadIdx.x;
    int stride = gridDim.x * blockDim.x;
    const int n8 = NA * 8;
    for (int k = i; k < n8; k += stride) {
        float4 f0 = __ldg((const float4*)xA + k * 2);
        float4 f1 = __ldg((const float4*)xA + k * 2 + 1);
        __half2 h0 = __floats2half2_rn(f0.x, f0.y);
        __half2 h1 = __floats2half2_rn(f0.z, f0.w);
        __half2 h2 = __floats2half2_rn(f1.x, f1.y);
        __half2 h3 = __floats2half2_rn(f1.z, f1.w);
        uint4 o;
        o.x = *(unsigned*)&h0; o.y = *(unsigned*)&h1;
        o.z = *(unsigned*)&h2; o.w = *(unsigned*)&h3;
        ((uint4*)g_hA)[k] = o;
    }
    const int m8 = NB * 8;
    for (int k = i; k < m8; k += stride) {
        float4 f0 = __ldg((const float4*)xB + k * 2);
        float4 f1 = __ldg((const float4*)xB + k * 2 + 1);
        __half2 h0 = __floats2half2_rn(f0.x, f0.y);
        __half2 h1 = __floats2half2_rn(f0.z, f0.w);
        __half2 h2 = __floats2half2_rn(f1.x, f1.y);
        __half2 h3 = __floats2half2_rn(f1.z, f1.w);
        uint4 o;
        o.x = *(unsigned*)&h0; o.y = *(unsigned*)&h1;
        o.z = *(unsigned*)&h2; o.w = *(unsigned*)&h3;
        ((uint4*)g_hB)[k] = o;
    }
}

// ---------------- CSR build: histogram --------------------------------------
__global__ void hist_kernel(const int* __restrict__ d0,
                            const int* __restrict__ d1,
                            const int* __restrict__ d2,
                            int E0, int E1, int E2) {
    int i = blockIdx.x * blockDim.x + threadIdx.x;
    int stride = gridDim.x * blockDim.x;
    for (int e = i; e < E0; e += stride) atomicAdd(&g_cnt0[__ldg(d0 + e)], 1);
    for (int e = i; e < E1; e += stride) atomicAdd(&g_cnt1[__ldg(d1 + e)], 1);
    for (int e = i; e < E2; e += stride) atomicAdd(&g_cnt2[__ldg(d2 + e)], 1);
}

// ---------------- CSR build: chunk sums -------------------------------------
__global__ void chunk_sum_kernel() {
    int type = blockIdx.x / NCH, ch = blockIdx.x % NCH;
    const int* cnt = (type == 0) ? g_cnt0 : (type == 1) ? g_cnt1 : g_cnt2;
    int N = (type == 0) ? NB : NA;
    int i0 = ch * 2048 + threadIdx.x * 8;
    int s = 0;
#pragma unroll
    for (int k = 0; k < 8; k++) {
        int i = i0 + k;
        if (i < N) s += cnt[i];
    }
    __shared__ int red[256];
    red[threadIdx.x] = s;
    __syncthreads();
    for (int o = 128; o > 0; o >>= 1) {
        if (threadIdx.x < o) red[threadIdx.x] += red[threadIdx.x + o];
        __syncthreads();
    }
    if (threadIdx.x == 0) g_csum[type * 64 + ch] = red[0];
}

// ---------------- CSR build: write ptr (chunk prefix via smem) --------------
__global__ void write_ptr_kernel(int E0, int E1, int E2) {
    int type = blockIdx.x / NCH, ch = blockIdx.x % NCH;
    const int* cnt; int* ptr; int* wofs; int N;
    if (type == 0)      { cnt = g_cnt0; ptr = g_ptr0; wofs = g_wofs0; N = NB; }
    else if (type == 1) { cnt = g_cnt1; ptr = g_ptr1; wofs = g_wofs1; N = NA; }
    else                { cnt = g_cnt2; ptr = g_ptr2; wofs = g_wofs2; N = NA; }

    if (threadIdx.x == 0 && ch == 0) {
        if (type == 0) g_ptr0[NB] = E0;
        else if (type == 1) g_ptr1[NA] = E1;
        else g_ptr2[NA] = E2;
    }

    __shared__ int csh[NCH];
    if (threadIdx.x < NCH) csh[threadIdx.x] = __ldg(&g_csum[type * 64 + threadIdx.x]);

    int i0 = ch * 2048 + threadIdx.x * 8;
    int c[8];
    int s = 0;
#pragma unroll
    for (int k = 0; k < 8; k++) {
        int i = i0 + k;
        c[k] = (i < N) ? cnt[i] : 0;
        s += c[k];
    }
    __shared__ int sd[256];
    sd[threadIdx.x] = s;
    __syncthreads();
    for (int o = 1; o < 256; o <<= 1) {
        int v = (threadIdx.x >= o) ? sd[threadIdx.x - o] : 0;
        __syncthreads();
        sd[threadIdx.x] += v;
        __syncthreads();
    }
    int cbase = 0;
    for (int c2 = 0; c2 < ch; c2++) cbase += csh[c2];
    int base = cbase + sd[threadIdx.x] - s;
#pragma unroll
    for (int k = 0; k < 8; k++) {
        int i = i0 + k;
        if (i < N) {
            ptr[i] = base;
            wofs[i] = base;
            base += c[k];
        }
    }
}

// ---------------- CSR build: scatter src ids into dst-sorted order ----------
__global__ void scatter_kernel(const int* __restrict__ s0, const int* __restrict__ d0,
                               const int* __restrict__ s1, const int* __restrict__ d1,
                               const int* __restrict__ s2, const int* __restrict__ d2,
                               int E0, int E1, int E2) {
    int i = blockIdx.x * blockDim.x + threadIdx.x;
    int stride = gridDim.x * blockDim.x;
    for (int e = i; e < E0; e += stride) {
        int p = atomicAdd(&g_wofs0[__ldg(d0 + e)], 1);
        g_col0[p] = __ldg(s0 + e);
    }
    for (int e = i; e < E1; e += stride) {
        int p = atomicAdd(&g_wofs1[__ldg(d1 + e)], 1);
        g_col1[p] = __ldg(s1 + e);
    }
    for (int e = i; e < E2; e += stride) {
        int p = atomicAdd(&g_wofs2[__ldg(d2 + e)], 1);
        g_col2[p] = __ldg(s2 + e);
    }
}

// ---------------- weight prep: fold + emit fp16-MMA B-fragments -------------
__global__ void prep_kernel(const float* __restrict__ Wn, const float* __restrict__ Wr,
                            const float* __restrict__ b,
                            const float* __restrict__ Wout, const float* __restrict__ bout) {
    if (blockIdx.x < 10) {
        int l = blockIdx.x / 5, m = blockIdx.x % 5;
        __shared__ float S[4096];
        __shared__ float T[4096];
        for (int i = threadIdx.x; i < 4096; i += blockDim.x) {
            float v;
            if (m == 0)      v = Wn[(l * 3 + 1) * 4096 + i];
            else if (m == 1) v = Wn[(l * 3 + 2) * 4096 + i];
            else if (m == 2) v = Wr[(l * 3 + 1) * 4096 + i] + Wr[(l * 3 + 2) * 4096 + i];
            else if (m == 3) v = Wn[(l * 3 + 0) * 4096 + i];
            else             v = Wr[(l * 3 + 0) * 4096 + i];
            S[i] = v;
        }
        __syncthreads();
        const float* src = S;
        if (l == 1) {
            for (int o = threadIdx.x; o < 4096; o += blockDim.x) {
                int i = o >> 6, j = o & 63;
                float acc = 0.f;
#pragma unroll 16
                for (int k = 0; k < 64; k++)
                    acc += S[i * 64 + k] * __ldg(Wout + k * 64 + j);
                T[o] = acc;
            }
            __syncthreads();
            src = T;
        }
        __half2* dst;
        int ktbase;
        if (m < 3) { dst = g_fragA[l]; ktbase = m * 4; }
        else       { dst = g_fragB[l]; ktbase = (m - 3) * 4; }
        for (int o = threadIdx.x; o < 1024; o += blockDim.x) {
            int kt2 = o >> 8, nt = (o >> 5) & 7, lane = o & 31;
            int k0 = kt2 * 16 + (lane & 3) * 2;
            int n = nt * 8 + (lane >> 2);
            int plane = ((ktbase + kt2) * 8 + nt) * 64 + lane;
            dst[plane]      = __floats2half2_rn(src[k0 * 64 + n], src[(k0 + 1) * 64 + n]);
            dst[plane + 32] = __floats2half2_rn(src[(k0 + 8) * 64 + n], src[(k0 + 9) * 64 + n]);
        }
    } else {
        int j = threadIdx.x;
        if (j < 64) {
            g_bias[0][j]      = b[1 * 64 + j] + b[2 * 64 + j];
            g_bias[0][64 + j] = b[j];
            float accA = 0.f, accB = 0.f;
            for (int k = 0; k < 64; k++) {
                float w = __ldg(Wout + k * 64 + j);
                accA += (b[4 * 64 + k] + b[5 * 64 + k]) * w;
                accB += b[3 * 64 + k] * w;
            }
            g_bias[1][j]      = accA + bout[j];
            g_bias[1][64 + j] = accB + bout[j];
        }
    }
}

// ---------------- in-block CSR gather of one 32B slice of a node's mean -----
// 4 threads/node; thread c owns halves [16c, 16c+16) = 2 uint4 per edge.
// 2-edge pipeline -> 4 independent 16B loads in flight. Writes fp16 to smem.
__device__ __forceinline__ void acc8(uint4 u, float* a) {
    const __half2* h = (const __half2*)&u;
    float2 f;
    f = __half22float2(h[0]); a[0] += f.x; a[1] += f.y;
    f = __half22float2(h[1]); a[2] += f.x; a[3] += f.y;
    f = __half22float2(h[2]); a[4] += f.x; a[5] += f.y;
    f = __half22float2(h[3]); a[6] += f.x; a[7] += f.y;
}

__device__ __forceinline__ void gather_slice(
    __half* dst, const int* __restrict__ ptr, const int* __restrict__ col,
    const __half* __restrict__ x, int n, int c, bool valid) {
    float a[16];
#pragma unroll
    for (int t = 0; t < 16; t++) a[t] = 0.f;
    float inv = 1.0f;
    if (valid) {
        int beg = __ldg(ptr + n), end = __ldg(ptr + n + 1);
        const uint4* X = (const uint4*)x;
        int k = beg;
        int s0 = 0, s1 = 0;
        if (k < end) s0 = __ldg(col + k);
        if (k + 1 < end) s1 = __ldg(col + k + 1);
        while (k + 1 < end) {
            int ns0 = 0, ns1 = 0;
            if (k + 2 < end) ns0 = __ldg(col + k + 2);
            if (k + 3 < end) ns1 = __ldg(col + k + 3);
            uint4 u0 = __ldg(X + (size_t)s0 * 8 + c * 2);
            uint4 v0 = __ldg(X + (size_t)s0 * 8 + c * 2 + 1);
            uint4 u1 = __ldg(X + (size_t)s1 * 8 + c * 2);
            uint4 v1 = __ldg(X + (size_t)s1 * 8 + c * 2 + 1);
            acc8(u0, a); acc8(v0, a + 8);
            acc8(u1, a); acc8(v1, a + 8);
            s0 = ns0; s1 = ns1; k += 2;
        }
        if (k < end) {
            uint4 u0 = __ldg(X + (size_t)s0 * 8 + c * 2);
            uint4 v0 = __ldg(X + (size_t)s0 * 8 + c * 2 + 1);
            acc8(u0, a); acc8(v0, a + 8);
        }
        inv = 1.0f / fmaxf((float)(end - beg), 1.0f);
    }
    __half2 h[8];
#pragma unroll
    for (int t = 0; t < 8; t++)
        h[t] = __floats2half2_rn(a[2 * t] * inv, a[2 * t + 1] * inv);
    uint4 o0, o1;
    o0.x = *(unsigned*)&h[0]; o0.y = *(unsigned*)&h[1];
    o0.z = *(unsigned*)&h[2]; o0.w = *(unsigned*)&h[3];
    o1.x = *(unsigned*)&h[4]; o1.y = *(unsigned*)&h[5];
    o1.z = *(unsigned*)&h[6]; o1.w = *(unsigned*)&h[7];
    ((uint4*)dst)[0] = o0;
    ((uint4*)dst)[1] = o1;
}

// ---------------- fused layer: in-block gather + fp16 m16n8k16 combine ------
// 64 rows/block, 8 warps: warp = (mtile 0..3, nhalf 0..1) -> m16 x n32 strip.
// A-side K=192 ([m1|m2|x]); B-side K=128 ([m0|x]); means gathered in-block.
// smem: X tile 64 rows x 200 halves (stride 200) + half2 frag table.
#define XH 200   // halves per row
template<bool FP32OUT>
__global__ __launch_bounds__(256, 4) void layer_kernel(
    const __half* __restrict__ hxA, const __half* __restrict__ hxB,
    const __half2* __restrict__ fragA, const __half2* __restrict__ fragB,
    const float* __restrict__ bl,
    float* __restrict__ outA, float* __restrict__ outB,
    __half* __restrict__ houtA, __half* __restrict__ houtB, int nbA) {
    extern __shared__ __align__(16) unsigned smraw[];
    __half* sxh = (__half*)smraw;                       // 64*200 halves = 25600B
    uint4* sxq = (uint4*)smraw;                         // row stride 25 uint4
    __half2* sfrag = (__half2*)((char*)smraw + 25600);
    const int lane = threadIdx.x & 31;
    const int warp = threadIdx.x >> 5;
    const int mt = warp & 3;
    const int nh = warp >> 2;
    const int r8 = lane >> 2;
    const int c4 = lane & 3;
    const int gn = threadIdx.x >> 2;   // node in tile, 0..63 (gather phase)
    const int gc = threadIdx.x & 3;    // 32B slice, 0..3

    bool isA = (blockIdx.x < nbA);
    int row0, rows, KT;
    float* outX;
    __half* houtX;
    const float* blx;
    if (isA) {
        row0 = blockIdx.x * 64;
        rows = NA - row0 < 64 ? NA - row0 : 64;
        KT = 12;
        outX = outA; houtX = houtA; blx = bl;
        // frag loads first (independent; in flight during gather)
        for (int i = threadIdx.x; i < 1536; i += 256)       // 12*8*64 half2 / 4
            ((uint4*)sfrag)[i] = __ldg((const uint4*)fragA + i);
        // seg2 = copy of own features hxA
        for (int i = threadIdx.x; i < 512; i += 256) {
            int r = i >> 3, q = i & 7;
            uint4 u = make_uint4(0, 0, 0, 0);
            if (r < rows) u = __ldg((const uint4*)hxA + (size_t)(row0 + r) * 8 + q);
            sxq[r * 25 + 16 + q] = u;
        }
        // seg0 = mean over B->A edges (m1), seg1 = mean over A->A edges (m2)
        bool valid = (gn < rows);
        int n = row0 + gn;
        gather_slice(sxh + gn * XH + 0 * 64 + gc * 16, g_ptr1, g_col1, hxB, n, gc, valid);
        gather_slice(sxh + gn * XH + 1 * 64 + gc * 16, g_ptr2, g_col2, hxA, n, gc, valid);
    } else {
        row0 = (blockIdx.x - nbA) * 64;
        rows = NB - row0 < 64 ? NB - row0 : 64;
        KT = 8;
        outX = outB; houtX = houtB; blx = bl + 64;
        for (int i = threadIdx.x; i < 1024; i += 256)       // 8*8*64 half2 / 4
            ((uint4*)sfrag)[i] = __ldg((const uint4*)fragB + i);
        // seg1 = copy of own features hxB
        for (int i = threadIdx.x; i < 512; i += 256) {
            int r = i >> 3, q = i & 7;
            uint4 u = make_uint4(0, 0, 0, 0);
            if (r < rows) u = __ldg((const uint4*)hxB + (size_t)(row0 + r) * 8 + q);
            sxq[r * 25 + 8 + q] = u;
        }
        // seg0 = mean over A->B edges (m0)
        bool valid = (gn < rows);
        int n = row0 + gn;
        gather_slice(sxh + gn * XH + 0 * 64 + gc * 16, g_ptr0, g_col0, hxA, n, gc, valid);
    }
    __syncthreads();

    float acc[4][4];
#pragma unroll
    for (int t = 0; t < 4; t++) {
        acc[t][0] = 0.f; acc[t][1] = 0.f; acc[t][2] = 0.f; acc[t][3] = 0.f;
    }

    // A fragment sources: row r = mt*16 + r8 (and +8), k0 = kt*16 + c4*2
    const __half* ap0 = sxh + (mt * 16 + r8) * XH + c4 * 2;
    for (int kt = 0; kt < KT; kt++) {
        const __half* ap = ap0 + kt * 16;
        unsigned a0 = *(const unsigned*)(ap);
        unsigned a1 = *(const unsigned*)(ap + 8 * XH);
        unsigned a2 = *(const unsigned*)(ap + 8);
        unsigned a3 = *(const unsigned*)(ap + 8 * XH + 8);
        const __half2* fp = sfrag + (kt * 8 + nh * 4) * 64 + lane;
#pragma unroll
        for (int t = 0; t < 4; t++) {
            __half2 b0 = fp[t * 64];
            __half2 b1 = fp[t * 64 + 32];
            mma_f16(acc[t], a0, a1, a2, a3,
                    *(unsigned*)&b0, *(unsigned*)&b1);
        }
    }

    // epilogue: +bias (, relu), store
    int r0 = mt * 16 + r8;
#pragma unroll
    for (int t = 0; t < 4; t++) {
        int colj = (nh * 4 + t) * 8 + c4 * 2;
        float b0 = __ldg(blx + colj), b1 = __ldg(blx + colj + 1);
        float v00 = acc[t][0] + b0, v01 = acc[t][1] + b1;
        float v10 = acc[t][2] + b0, v11 = acc[t][3] + b1;
        if (FP32OUT) {
            v00 = fmaxf(v00, 0.f); v01 = fmaxf(v01, 0.f);
            v10 = fmaxf(v10, 0.f); v11 = fmaxf(v11, 0.f);
            if (r0 < rows)
                *(float2*)&outX[(size_t)(row0 + r0) * 64 + colj] = make_float2(v00, v01);
            if (r0 + 8 < rows)
                *(float2*)&outX[(size_t)(row0 + r0 + 8) * 64 + colj] = make_float2(v10, v11);
        } else {
            if (r0 < rows)
                *(__half2*)&houtX[(size_t)(row0 + r0) * 64 + colj] = __floats2half2_rn(v00, v01);
            if (r0 + 8 < rows)
                *(__half2*)&houtX[(size_t)(row0 + r0 + 8) * 64 + colj] = __floats2half2_rn(v10, v11);
        }
    }
}

// ---------------- launcher --------------------------------------------------
extern "C" void kernel_launch(void* const* d_in, const int* in_sizes, int n_in,
                              void* d_out, int out_size) {
    const float* x_A   = (const float*)d_in[0];
    const float* x_B   = (const float*)d_in[1];
    const float* Wn    = (const float*)d_in[2];
    const float* Wr    = (const float*)d_in[3];
    const float* b     = (const float*)d_in[4];
    const float* W_out = (const float*)d_in[5];
    const float* b_out = (const float*)d_in[6];
    const int* src0 = (const int*)d_in[7];
    const int* dst0 = (const int*)d_in[8];
    const int* src1 = (const int*)d_in[9];
    const int* dst1 = (const int*)d_in[10];
    const int* src2 = (const int*)d_in[11];
    const int* dst2 = (const int*)d_in[12];
    const int E0 = in_sizes[7];
    const int E1 = in_sizes[9];
    const int E2 = in_sizes[11];
    float* out = (float*)d_out;

    float *bias0, *bias1;
    __half2 *frA, *frB;
    __half *hA, *hB, *hA1, *hB1;
    int *cnt0, *cnt1, *cnt2;
    cudaGetSymbolAddress((void**)&hA, g_hA);
    cudaGetSymbolAddress((void**)&hB, g_hB);
    cudaGetSymbolAddress((void**)&hA1, g_hA1);
    cudaGetSymbolAddress((void**)&hB1, g_hB1);
    cudaGetSymbolAddress((void**)&cnt0, g_cnt0);
    cudaGetSymbolAddress((void**)&cnt1, g_cnt1);
    cudaGetSymbolAddress((void**)&cnt2, g_cnt2);
    cudaGetSymbolAddress((void**)&frA, g_fragA);
    cudaGetSymbolAddress((void**)&frB, g_fragB);
    cudaGetSymbolAddress((void**)&bias0, g_bias);
    bias1 = bias0 + 128;

    const int nbA = (NA + 63) / 64;
    const int nbB = (NB + 63) / 64;
    const int smemBytes = 25600 + 12 * 8 * 64 * 4;   // X tile + A-side frags = 50176

    cudaFuncSetAttribute(layer_kernel<false>,
                         cudaFuncAttributeMaxDynamicSharedMemorySize, smemBytes);
    cudaFuncSetAttribute(layer_kernel<true>,
                         cudaFuncAttributeMaxDynamicSharedMemorySize, smemBytes);

    // ---- prep: weights + fp16 feature conversion (independent of CSR) ----
    prep_kernel<<<11, 256>>>(Wn, Wr, b, W_out, b_out);
    conv_kernel<<<1024, 256>>>(x_A, x_B);

    // ---- CSR build ----
    cudaMemsetAsync(cnt0, 0, NB * sizeof(int));
    cudaMemsetAsync(cnt1, 0, NA * sizeof(int));
    cudaMemsetAsync(cnt2, 0, NA * sizeof(int));
    hist_kernel<<<1024, 256>>>(dst0, dst1, dst2, E0, E1, E2);
    chunk_sum_kernel<<<3 * NCH, 256>>>();
    write_ptr_kernel<<<3 * NCH, 256>>>(E0, E1, E2);
    scatter_kernel<<<1024, 256>>>(src0, dst0, src1, dst1, src2, dst2, E0, E1, E2);

    // ---- layer 0 (fused gather+combine; outputs fp16 only) ----
    layer_kernel<false><<<nbA + nbB, 256, smemBytes>>>(
        hA, hB, frA, frB, bias0, nullptr, nullptr, hA1, hB1, nbA);

    // ---- layer 1 (fused; head folded into weights; relu at store; fp32 out) ----
    layer_kernel<true><<<nbA + nbB, 256, smemBytes>>>(
        hA1, hB1, frA + 12 * 8 * 64, frB + 8 * 8 * 64, bias1,
        out, out + (size_t)NA * 64, nullptr, nullptr, nbA);
}

// round 14
// speedup vs baseline: 4.2245x; 1.1448x over previous
#include <cuda_runtime.h>
#include <cuda_fp16.h>
#include <cstddef>

#define NA 100000
#define NB 100000
#define DD 64
#define EMAX 1250000
#define NCH 49          // chunks of 2048 nodes: 49*2048 >= 100000

// ---------------- fp16 mma helper (m16n8k16, fp32 accum) --------------------
__device__ __forceinline__ void mma_f16(float* c, unsigned a0, unsigned a1,
                                        unsigned a2, unsigned a3,
                                        unsigned b0, unsigned b1) {
    asm("mma.sync.aligned.m16n8k16.row.col.f32.f16.f16.f32 "
        "{%0,%1,%2,%3}, {%4,%5,%6,%7}, {%8,%9}, {%0,%1,%2,%3};"
        : "+f"(c[0]), "+f"(c[1]), "+f"(c[2]), "+f"(c[3])
        : "r"(a0), "r"(a1), "r"(a2), "r"(a3), "r"(b0), "r"(b1));
}

// ---------------- scratch (device globals: no allocation allowed) ----------
__device__ int g_cnt0[NB], g_cnt1[NA], g_cnt2[NA];
__device__ int g_ptr0[NB + 1], g_ptr1[NA + 1], g_ptr2[NA + 1];
__device__ int g_wofs0[NB], g_wofs1[NA], g_wofs2[NA];
__device__ int g_col0[EMAX], g_col1[EMAX], g_col2[EMAX];
__device__ int g_csum[3 * 64];
// fp16 feature tables
__device__ __align__(16) __half g_hA[NA * DD];
__device__ __align__(16) __half g_hB[NB * DD];
__device__ __align__(16) __half g_hA1[NA * DD];
__device__ __align__(16) __half g_hB1[NB * DD];
// fp16-MMA B-fragments. Per (ktile16, ntile8): 64 half2 = {b0 plane 32, b1 plane 32}
// A-side K=192 -> 12 ktiles; B-side K=128 -> 8 ktiles. Read via L1 (shared
// read-only across all blocks), NOT staged in smem.
__device__ __align__(16) __half2 g_fragA[2][12 * 8 * 64];
__device__ __align__(16) __half2 g_fragB[2][8 * 8 * 64];
__device__ float g_bias[2][128];   // [l][0:64]=A bias, [64:128]=B bias

// ---------------- fp32 -> fp16 feature conversion ----------------------------
__global__ void conv_kernel(const float* __restrict__ xA, const float* __restrict__ xB) {
    int i = blockIdx.x * blockDim.x + threadIdx.x;
    int stride = gridDim.x * blockDim.x;
    const int n8 = NA * 8;
    for (int k = i; k < n8; k += stride) {
        float4 f0 = __ldg((const float4*)xA + k * 2);
        float4 f1 = __ldg((const float4*)xA + k * 2 + 1);
        __half2 h0 = __floats2half2_rn(f0.x, f0.y);
        __half2 h1 = __floats2half2_rn(f0.z, f0.w);
        __half2 h2 = __floats2half2_rn(f1.x, f1.y);
        __half2 h3 = __floats2half2_rn(f1.z, f1.w);
        uint4 o;
        o.x = *(unsigned*)&h0; o.y = *(unsigned*)&h1;
        o.z = *(unsigned*)&h2; o.w = *(unsigned*)&h3;
        ((uint4*)g_hA)[k] = o;
    }
    const int m8 = NB * 8;
    for (int k = i; k < m8; k += stride) {
        float4 f0 = __ldg((const float4*)xB + k * 2);
        float4 f1 = __ldg((const float4*)xB + k * 2 + 1);
        __half2 h0 = __floats2half2_rn(f0.x, f0.y);
        __half2 h1 = __floats2half2_rn(f0.z, f0.w);
        __half2 h2 = __floats2half2_rn(f1.x, f1.y);
        __half2 h3 = __floats2half2_rn(f1.z, f1.w);
        uint4 o;
        o.x = *(unsigned*)&h0; o.y = *(unsigned*)&h1;
        o.z = *(unsigned*)&h2; o.w = *(unsigned*)&h3;
        ((uint4*)g_hB)[k] = o;
    }
}

// ---------------- CSR build: histogram --------------------------------------
__global__ void hist_kernel(const int* __restrict__ d0,
                            const int* __restrict__ d1,
                            const int* __restrict__ d2,
                            int E0, int E1, int E2) {
    int i = blockIdx.x * blockDim.x + threadIdx.x;
    int stride = gridDim.x * blockDim.x;
    for (int e = i; e < E0; e += stride) atomicAdd(&g_cnt0[__ldg(d0 + e)], 1);
    for (int e = i; e < E1; e += stride) atomicAdd(&g_cnt1[__ldg(d1 + e)], 1);
    for (int e = i; e < E2; e += stride) atomicAdd(&g_cnt2[__ldg(d2 + e)], 1);
}

// ---------------- CSR build: chunk sums -------------------------------------
__global__ void chunk_sum_kernel() {
    int type = blockIdx.x / NCH, ch = blockIdx.x % NCH;
    const int* cnt = (type == 0) ? g_cnt0 : (type == 1) ? g_cnt1 : g_cnt2;
    int N = (type == 0) ? NB : NA;
    int i0 = ch * 2048 + threadIdx.x * 8;
    int s = 0;
#pragma unroll
    for (int k = 0; k < 8; k++) {
        int i = i0 + k;
        if (i < N) s += cnt[i];
    }
    __shared__ int red[256];
    red[threadIdx.x] = s;
    __syncthreads();
    for (int o = 128; o > 0; o >>= 1) {
        if (threadIdx.x < o) red[threadIdx.x] += red[threadIdx.x + o];
        __syncthreads();
    }
    if (threadIdx.x == 0) g_csum[type * 64 + ch] = red[0];
}

// ---------------- CSR build: write ptr + SELF-RESET counts ------------------
// Resets cnt to zero after consuming it, so no memsets are needed: device
// globals start zero-initialized and every pass leaves them zero again.
__global__ void write_ptr_kernel(int E0, int E1, int E2) {
    int type = blockIdx.x / NCH, ch = blockIdx.x % NCH;
    int* cnt; int* ptr; int* wofs; int N;
    if (type == 0)      { cnt = g_cnt0; ptr = g_ptr0; wofs = g_wofs0; N = NB; }
    else if (type == 1) { cnt = g_cnt1; ptr = g_ptr1; wofs = g_wofs1; N = NA; }
    else                { cnt = g_cnt2; ptr = g_ptr2; wofs = g_wofs2; N = NA; }

    if (threadIdx.x == 0 && ch == 0) {
        if (type == 0) g_ptr0[NB] = E0;
        else if (type == 1) g_ptr1[NA] = E1;
        else g_ptr2[NA] = E2;
    }

    __shared__ int csh[NCH];
    if (threadIdx.x < NCH) csh[threadIdx.x] = __ldg(&g_csum[type * 64 + threadIdx.x]);

    int i0 = ch * 2048 + threadIdx.x * 8;
    int c[8];
    int s = 0;
#pragma unroll
    for (int k = 0; k < 8; k++) {
        int i = i0 + k;
        c[k] = (i < N) ? cnt[i] : 0;
        s += c[k];
    }
    __shared__ int sd[256];
    sd[threadIdx.x] = s;
    __syncthreads();
    for (int o = 1; o < 256; o <<= 1) {
        int v = (threadIdx.x >= o) ? sd[threadIdx.x - o] : 0;
        __syncthreads();
        sd[threadIdx.x] += v;
        __syncthreads();
    }
    int cbase = 0;
    for (int c2 = 0; c2 < ch; c2++) cbase += csh[c2];
    int base = cbase + sd[threadIdx.x] - s;
#pragma unroll
    for (int k = 0; k < 8; k++) {
        int i = i0 + k;
        if (i < N) {
            ptr[i] = base;
            wofs[i] = base;
            cnt[i] = 0;          // self-reset for the next graph replay
            base += c[k];
        }
    }
}

// ---------------- CSR build: scatter src ids into dst-sorted order ----------
__global__ void scatter_kernel(const int* __restrict__ s0, const int* __restrict__ d0,
                               const int* __restrict__ s1, const int* __restrict__ d1,
                               const int* __restrict__ s2, const int* __restrict__ d2,
                               int E0, int E1, int E2) {
    int i = blockIdx.x * blockDim.x + threadIdx.x;
    int stride = gridDim.x * blockDim.x;
    for (int e = i; e < E0; e += stride) {
        int p = atomicAdd(&g_wofs0[__ldg(d0 + e)], 1);
        g_col0[p] = __ldg(s0 + e);
    }
    for (int e = i; e < E1; e += stride) {
        int p = atomicAdd(&g_wofs1[__ldg(d1 + e)], 1);
        g_col1[p] = __ldg(s1 + e);
    }
    for (int e = i; e < E2; e += stride) {
        int p = atomicAdd(&g_wofs2[__ldg(d2 + e)], 1);
        g_col2[p] = __ldg(s2 + e);
    }
}

// ---------------- weight prep: fold + emit fp16-MMA B-fragments -------------
__global__ void prep_kernel(const float* __restrict__ Wn, const float* __restrict__ Wr,
                            const float* __restrict__ b,
                            const float* __restrict__ Wout, const float* __restrict__ bout) {
    if (blockIdx.x < 10) {
        int l = blockIdx.x / 5, m = blockIdx.x % 5;
        __shared__ float S[4096];
        __shared__ float T[4096];
        for (int i = threadIdx.x; i < 4096; i += blockDim.x) {
            float v;
            if (m == 0)      v = Wn[(l * 3 + 1) * 4096 + i];
            else if (m == 1) v = Wn[(l * 3 + 2) * 4096 + i];
            else if (m == 2) v = Wr[(l * 3 + 1) * 4096 + i] + Wr[(l * 3 + 2) * 4096 + i];
            else if (m == 3) v = Wn[(l * 3 + 0) * 4096 + i];
            else             v = Wr[(l * 3 + 0) * 4096 + i];
            S[i] = v;
        }
        __syncthreads();
        const float* src = S;
        if (l == 1) {
            for (int o = threadIdx.x; o < 4096; o += blockDim.x) {
                int i = o >> 6, j = o & 63;
                float acc = 0.f;
#pragma unroll 16
                for (int k = 0; k < 64; k++)
                    acc += S[i * 64 + k] * __ldg(Wout + k * 64 + j);
                T[o] = acc;
            }
            __syncthreads();
            src = T;
        }
        __half2* dst;
        int ktbase;
        if (m < 3) { dst = g_fragA[l]; ktbase = m * 4; }
        else       { dst = g_fragB[l]; ktbase = (m - 3) * 4; }
        for (int o = threadIdx.x; o < 1024; o += blockDim.x) {
            int kt2 = o >> 8, nt = (o >> 5) & 7, lane = o & 31;
            int k0 = kt2 * 16 + (lane & 3) * 2;
            int n = nt * 8 + (lane >> 2);
            int plane = ((ktbase + kt2) * 8 + nt) * 64 + lane;
            dst[plane]      = __floats2half2_rn(src[k0 * 64 + n], src[(k0 + 1) * 64 + n]);
            dst[plane + 32] = __floats2half2_rn(src[(k0 + 8) * 64 + n], src[(k0 + 9) * 64 + n]);
        }
    } else {
        int j = threadIdx.x;
        if (j < 64) {
            g_bias[0][j]      = b[1 * 64 + j] + b[2 * 64 + j];
            g_bias[0][64 + j] = b[j];
            float accA = 0.f, accB = 0.f;
            for (int k = 0; k < 64; k++) {
                float w = __ldg(Wout + k * 64 + j);
                accA += (b[4 * 64 + k] + b[5 * 64 + k]) * w;
                accB += b[3 * 64 + k] * w;
            }
            g_bias[1][j]      = accA + bout[j];
            g_bias[1][64 + j] = accB + bout[j];
        }
    }
}

// ---------------- in-block CSR gather of one 32B slice of a node's mean -----
// 4 threads/node; thread c owns halves [16c, 16c+16) = 2 uint4 per edge.
// 2-edge pipeline -> 4 independent 16B loads in flight. Writes fp16 to smem.
__device__ __forceinline__ void acc8(uint4 u, float* a) {
    const __half2* h = (const __half2*)&u;
    float2 f;
    f = __half22float2(h[0]); a[0] += f.x; a[1] += f.y;
    f = __half22float2(h[1]); a[2] += f.x; a[3] += f.y;
    f = __half22float2(h[2]); a[4] += f.x; a[5] += f.y;
    f = __half22float2(h[3]); a[6] += f.x; a[7] += f.y;
}

__device__ __forceinline__ void gather_slice(
    __half* dst, const int* __restrict__ ptr, const int* __restrict__ col,
    const __half* __restrict__ x, int n, int c, bool valid) {
    float a[16];
#pragma unroll
    for (int t = 0; t < 16; t++) a[t] = 0.f;
    float inv = 1.0f;
    if (valid) {
        int beg = __ldg(ptr + n), end = __ldg(ptr + n + 1);
        const uint4* X = (const uint4*)x;
        int k = beg;
        int s0 = 0, s1 = 0;
        if (k < end) s0 = __ldg(col + k);
        if (k + 1 < end) s1 = __ldg(col + k + 1);
        while (k + 1 < end) {
            int ns0 = 0, ns1 = 0;
            if (k + 2 < end) ns0 = __ldg(col + k + 2);
            if (k + 3 < end) ns1 = __ldg(col + k + 3);
            uint4 u0 = __ldg(X + (size_t)s0 * 8 + c * 2);
            uint4 v0 = __ldg(X + (size_t)s0 * 8 + c * 2 + 1);
            uint4 u1 = __ldg(X + (size_t)s1 * 8 + c * 2);
            uint4 v1 = __ldg(X + (size_t)s1 * 8 + c * 2 + 1);
            acc8(u0, a); acc8(v0, a + 8);
            acc8(u1, a); acc8(v1, a + 8);
            s0 = ns0; s1 = ns1; k += 2;
        }
        if (k < end) {
            uint4 u0 = __ldg(X + (size_t)s0 * 8 + c * 2);
            uint4 v0 = __ldg(X + (size_t)s0 * 8 + c * 2 + 1);
            acc8(u0, a); acc8(v0, a + 8);
        }
        inv = 1.0f / fmaxf((float)(end - beg), 1.0f);
    }
    __half2 h[8];
#pragma unroll
    for (int t = 0; t < 8; t++)
        h[t] = __floats2half2_rn(a[2 * t] * inv, a[2 * t + 1] * inv);
    uint4 o0, o1;
    o0.x = *(unsigned*)&h[0]; o0.y = *(unsigned*)&h[1];
    o0.z = *(unsigned*)&h[2]; o0.w = *(unsigned*)&h[3];
    o1.x = *(unsigned*)&h[4]; o1.y = *(unsigned*)&h[5];
    o1.z = *(unsigned*)&h[6]; o1.w = *(unsigned*)&h[7];
    ((uint4*)dst)[0] = o0;
    ((uint4*)dst)[1] = o1;
}

// ---------------- fused layer: in-block gather + fp16 m16n8k16 combine ------
// 64 rows/block, 8 warps: warp = (mtile 0..3, nhalf 0..1) -> m16 x n32 strip.
// A-side K=192 ([m1|m2|x]); B-side K=128 ([m0|x]); means gathered in-block.
// smem: X tile only (64 rows x 200 halves). B-fragments read via __ldg
// (identical across blocks -> L1-resident) -> 25.6KB smem, 5 blocks/SM.
#define XH 200   // halves per row
template<bool FP32OUT>
__global__ __launch_bounds__(256, 5) void layer_kernel(
    const __half* __restrict__ hxA, const __half* __restrict__ hxB,
    const __half2* __restrict__ fragA, const __half2* __restrict__ fragB,
    const float* __restrict__ bl,
    float* __restrict__ outA, float* __restrict__ outB,
    __half* __restrict__ houtA, __half* __restrict__ houtB, int nbA) {
    extern __shared__ __align__(16) unsigned smraw[];
    __half* sxh = (__half*)smraw;                       // 64*200 halves = 25600B
    uint4* sxq = (uint4*)smraw;                         // row stride 25 uint4
    const int lane = threadIdx.x & 31;
    const int warp = threadIdx.x >> 5;
    const int mt = warp & 3;
    const int nh = warp >> 2;
    const int r8 = lane >> 2;
    const int c4 = lane & 3;
    const int gn = threadIdx.x >> 2;   // node in tile, 0..63 (gather phase)
    const int gc = threadIdx.x & 3;    // 32B slice, 0..3

    bool isA = (blockIdx.x < nbA);
    int row0, rows, KT;
    float* outX;
    __half* houtX;
    const float* blx;
    const __half2* frag;
    if (isA) {
        row0 = blockIdx.x * 64;
        rows = NA - row0 < 64 ? NA - row0 : 64;
        KT = 12;
        outX = outA; houtX = houtA; blx = bl; frag = fragA;
        // seg2 = copy of own features hxA
        for (int i = threadIdx.x; i < 512; i += 256) {
            int r = i >> 3, q = i & 7;
            uint4 u = make_uint4(0, 0, 0, 0);
            if (r < rows) u = __ldg((const uint4*)hxA + (size_t)(row0 + r) * 8 + q);
            sxq[r * 25 + 16 + q] = u;
        }
        // seg0 = mean over B->A edges (m1), seg1 = mean over A->A edges (m2)
        bool valid = (gn < rows);
        int n = row0 + gn;
        gather_slice(sxh + gn * XH + 0 * 64 + gc * 16, g_ptr1, g_col1, hxB, n, gc, valid);
        gather_slice(sxh + gn * XH + 1 * 64 + gc * 16, g_ptr2, g_col2, hxA, n, gc, valid);
    } else {
        row0 = (blockIdx.x - nbA) * 64;
        rows = NB - row0 < 64 ? NB - row0 : 64;
        KT = 8;
        outX = outB; houtX = houtB; blx = bl + 64; frag = fragB;
        // seg1 = copy of own features hxB
        for (int i = threadIdx.x; i < 512; i += 256) {
            int r = i >> 3, q = i & 7;
            uint4 u = make_uint4(0, 0, 0, 0);
            if (r < rows) u = __ldg((const uint4*)hxB + (size_t)(row0 + r) * 8 + q);
            sxq[r * 25 + 8 + q] = u;
        }
        // seg0 = mean over A->B edges (m0)
        bool valid = (gn < rows);
        int n = row0 + gn;
        gather_slice(sxh + gn * XH + 0 * 64 + gc * 16, g_ptr0, g_col0, hxA, n, gc, valid);
    }
    __syncthreads();

    float acc[4][4];
#pragma unroll
    for (int t = 0; t < 4; t++) {
        acc[t][0] = 0.f; acc[t][1] = 0.f; acc[t][2] = 0.f; acc[t][3] = 0.f;
    }

    // A fragment sources: row r = mt*16 + r8 (and +8), k0 = kt*16 + c4*2
    const __half* ap0 = sxh + (mt * 16 + r8) * XH + c4 * 2;
    for (int kt = 0; kt < KT; kt++) {
        const __half* ap = ap0 + kt * 16;
        unsigned a0 = *(const unsigned*)(ap);
        unsigned a1 = *(const unsigned*)(ap + 8 * XH);
        unsigned a2 = *(const unsigned*)(ap + 8);
        unsigned a3 = *(const unsigned*)(ap + 8 * XH + 8);
        const __half2* fp = frag + (kt * 8 + nh * 4) * 64 + lane;
#pragma unroll
        for (int t = 0; t < 4; t++) {
            __half2 b0 = __ldg(fp + t * 64);
            __half2 b1 = __ldg(fp + t * 64 + 32);
            mma_f16(acc[t], a0, a1, a2, a3,
                    *(unsigned*)&b0, *(unsigned*)&b1);
        }
    }

    // epilogue: +bias (, relu), store
    int r0 = mt * 16 + r8;
#pragma unroll
    for (int t = 0; t < 4; t++) {
        int colj = (nh * 4 + t) * 8 + c4 * 2;
        float b0 = __ldg(blx + colj), b1 = __ldg(blx + colj + 1);
        float v00 = acc[t][0] + b0, v01 = acc[t][1] + b1;
        float v10 = acc[t][2] + b0, v11 = acc[t][3] + b1;
        if (FP32OUT) {
            v00 = fmaxf(v00, 0.f); v01 = fmaxf(v01, 0.f);
            v10 = fmaxf(v10, 0.f); v11 = fmaxf(v11, 0.f);
            if (r0 < rows)
                *(float2*)&outX[(size_t)(row0 + r0) * 64 + colj] = make_float2(v00, v01);
            if (r0 + 8 < rows)
                *(float2*)&outX[(size_t)(row0 + r0 + 8) * 64 + colj] = make_float2(v10, v11);
        } else {
            if (r0 < rows)
                *(__half2*)&houtX[(size_t)(row0 + r0) * 64 + colj] = __floats2half2_rn(v00, v01);
            if (r0 + 8 < rows)
                *(__half2*)&houtX[(size_t)(row0 + r0 + 8) * 64 + colj] = __floats2half2_rn(v10, v11);
        }
    }
}

// ---------------- launcher --------------------------------------------------
extern "C" void kernel_launch(void* const* d_in, const int* in_sizes, int n_in,
                              void* d_out, int out_size) {
    const float* x_A   = (const float*)d_in[0];
    const float* x_B   = (const float*)d_in[1];
    const float* Wn    = (const float*)d_in[2];
    const float* Wr    = (const float*)d_in[3];
    const float* b     = (const float*)d_in[4];
    const float* W_out = (const float*)d_in[5];
    const float* b_out = (const float*)d_in[6];
    const int* src0 = (const int*)d_in[7];
    const int* dst0 = (const int*)d_in[8];
    const int* src1 = (const int*)d_in[9];
    const int* dst1 = (const int*)d_in[10];
    const int* src2 = (const int*)d_in[11];
    const int* dst2 = (const int*)d_in[12];
    const int E0 = in_sizes[7];
    const int E1 = in_sizes[9];
    const int E2 = in_sizes[11];
    float* out = (float*)d_out;

    float *bias0, *bias1;
    __half2 *frA, *frB;
    __half *hA, *hB, *hA1, *hB1;
    cudaGetSymbolAddress((void**)&hA, g_hA);
    cudaGetSymbolAddress((void**)&hB, g_hB);
    cudaGetSymbolAddress((void**)&hA1, g_hA1);
    cudaGetSymbolAddress((void**)&hB1, g_hB1);
    cudaGetSymbolAddress((void**)&frA, g_fragA);
    cudaGetSymbolAddress((void**)&frB, g_fragB);
    cudaGetSymbolAddress((void**)&bias0, g_bias);
    bias1 = bias0 + 128;

    const int nbA = (NA + 63) / 64;
    const int nbB = (NB + 63) / 64;
    const int smemBytes = 25600;   // X tile only; frags live in L1

    cudaFuncSetAttribute(layer_kernel<false>,
                         cudaFuncAttributeMaxDynamicSharedMemorySize, smemBytes);
    cudaFuncSetAttribute(layer_kernel<true>,
                         cudaFuncAttributeMaxDynamicSharedMemorySize, smemBytes);

    // ---- prep: weights + fp16 feature conversion (independent of CSR) ----
    prep_kernel<<<11, 256>>>(Wn, Wr, b, W_out, b_out);
    conv_kernel<<<1024, 256>>>(x_A, x_B);

    // ---- CSR build (cnt arrays self-reset by write_ptr; no memsets) ----
    hist_kernel<<<1024, 256>>>(dst0, dst1, dst2, E0, E1, E2);
    chunk_sum_kernel<<<3 * NCH, 256>>>();
    write_ptr_kernel<<<3 * NCH, 256>>>(E0, E1, E2);
    scatter_kernel<<<1024, 256>>>(src0, dst0, src1, dst1, src2, dst2, E0, E1, E2);

    // ---- layer 0 (fused gather+combine; outputs fp16 only) ----
    layer_kernel<false><<<nbA + nbB, 256, smemBytes>>>(
        hA, hB, frA, frB, bias0, nullptr, nullptr, hA1, hB1, nbA);

    // ---- layer 1 (fused; head folded into weights; relu at store; fp32 out) ----
    layer_kernel<true><<<nbA + nbB, 256, smemBytes>>>(
        hA1, hB1, frA + 12 * 8 * 64, frB + 8 * 8 * 64, bias1,
        out, out + (size_t)NA * 64, nullptr, nullptr, nbA);
}

// round 15
// speedup vs baseline: 4.3639x; 1.0330x over previous
#include <cuda_runtime.h>
#include <cuda_fp16.h>
#include <cstddef>

#define NA 100000
#define NB 100000
#define DD 64
#define EMAX 1250000
#define NCH 49          // chunks of 2048 nodes: 49*2048 >= 100000

// ---------------- fp16 mma helper (m16n8k16, fp32 accum) --------------------
__device__ __forceinline__ void mma_f16(float* c, unsigned a0, unsigned a1,
                                        unsigned a2, unsigned a3,
                                        unsigned b0, unsigned b1) {
    asm("mma.sync.aligned.m16n8k16.row.col.f32.f16.f16.f32 "
        "{%0,%1,%2,%3}, {%4,%5,%6,%7}, {%8,%9}, {%0,%1,%2,%3};"
        : "+f"(c[0]), "+f"(c[1]), "+f"(c[2]), "+f"(c[3])
        : "r"(a0), "r"(a1), "r"(a2), "r"(a3), "r"(b0), "r"(b1));
}

// ---------------- scratch (device globals: no allocation allowed) ----------
__device__ int g_cnt0[NB], g_cnt1[NA], g_cnt2[NA];
__device__ int g_ptr0[NB + 1], g_ptr1[NA + 1], g_ptr2[NA + 1];
__device__ int g_wofs0[NB], g_wofs1[NA], g_wofs2[NA];
__device__ int g_col0[EMAX], g_col1[EMAX], g_col2[EMAX];
__device__ int g_csum[3 * 64];
// fp16 feature tables
__device__ __align__(16) __half g_hA[NA * DD];
__device__ __align__(16) __half g_hB[NB * DD];
__device__ __align__(16) __half g_hA1[NA * DD];
__device__ __align__(16) __half g_hB1[NB * DD];
// fp16-MMA B-fragments. Per (ktile16, ntile8): 64 half2 = {b0 plane 32, b1 plane 32}
// A-side K=192 -> 12 ktiles; B-side K=128 -> 8 ktiles. Read via L1.
__device__ __align__(16) __half2 g_fragA[2][12 * 8 * 64];
__device__ __align__(16) __half2 g_fragB[2][8 * 8 * 64];
__device__ float g_bias[2][128];   // [l][0:64]=A bias, [64:128]=B bias

// ---------------- fused prologue: hist (vec) + fp16 conv + weight prep ------
// blocks 0..1023  : histogram of dst arrays (int4 loads) + fp32->fp16 conv
// blocks 1024..1033: weight matrix prep (fold + fragment pack)
// block 1034      : biases
__global__ void prologue_kernel(
    const float* __restrict__ xA, const float* __restrict__ xB,
    const float* __restrict__ Wn, const float* __restrict__ Wr,
    const float* __restrict__ b,
    const float* __restrict__ Wout, const float* __restrict__ bout,
    const int* __restrict__ d0, const int* __restrict__ d1,
    const int* __restrict__ d2,
    int E0, int E1, int E2) {
    if (blockIdx.x < 1024) {
        int t = blockIdx.x * 256 + threadIdx.x;
        const int stride = 1024 * 256;
        // ---- histogram, 4 edges per int4 load ----
        {
            int q4 = E0 >> 2;
            for (int q = t; q < q4; q += stride) {
                int4 d = __ldg((const int4*)d0 + q);
                atomicAdd(&g_cnt0[d.x], 1); atomicAdd(&g_cnt0[d.y], 1);
                atomicAdd(&g_cnt0[d.z], 1); atomicAdd(&g_cnt0[d.w], 1);
            }
            for (int e = q4 * 4 + t; e < E0; e += stride)
                atomicAdd(&g_cnt0[__ldg(d0 + e)], 1);
            q4 = E1 >> 2;
            for (int q = t; q < q4; q += stride) {
                int4 d = __ldg((const int4*)d1 + q);
                atomicAdd(&g_cnt1[d.x], 1); atomicAdd(&g_cnt1[d.y], 1);
                atomicAdd(&g_cnt1[d.z], 1); atomicAdd(&g_cnt1[d.w], 1);
            }
            for (int e = q4 * 4 + t; e < E1; e += stride)
                atomicAdd(&g_cnt1[__ldg(d1 + e)], 1);
            q4 = E2 >> 2;
            for (int q = t; q < q4; q += stride) {
                int4 d = __ldg((const int4*)d2 + q);
                atomicAdd(&g_cnt2[d.x], 1); atomicAdd(&g_cnt2[d.y], 1);
                atomicAdd(&g_cnt2[d.z], 1); atomicAdd(&g_cnt2[d.w], 1);
            }
            for (int e = q4 * 4 + t; e < E2; e += stride)
                atomicAdd(&g_cnt2[__ldg(d2 + e)], 1);
        }
        // ---- fp32 -> fp16 feature conversion ----
        const int n8 = NA * 8;
        for (int k = t; k < n8; k += stride) {
            float4 f0 = __ldg((const float4*)xA + k * 2);
            float4 f1 = __ldg((const float4*)xA + k * 2 + 1);
            __half2 h0 = __floats2half2_rn(f0.x, f0.y);
            __half2 h1 = __floats2half2_rn(f0.z, f0.w);
            __half2 h2 = __floats2half2_rn(f1.x, f1.y);
            __half2 h3 = __floats2half2_rn(f1.z, f1.w);
            uint4 o;
            o.x = *(unsigned*)&h0; o.y = *(unsigned*)&h1;
            o.z = *(unsigned*)&h2; o.w = *(unsigned*)&h3;
            ((uint4*)g_hA)[k] = o;
        }
        const int m8 = NB * 8;
        for (int k = t; k < m8; k += stride) {
            float4 f0 = __ldg((const float4*)xB + k * 2);
            float4 f1 = __ldg((const float4*)xB + k * 2 + 1);
            __half2 h0 = __floats2half2_rn(f0.x, f0.y);
            __half2 h1 = __floats2half2_rn(f0.z, f0.w);
            __half2 h2 = __floats2half2_rn(f1.x, f1.y);
            __half2 h3 = __floats2half2_rn(f1.z, f1.w);
            uint4 o;
            o.x = *(unsigned*)&h0; o.y = *(unsigned*)&h1;
            o.z = *(unsigned*)&h2; o.w = *(unsigned*)&h3;
            ((uint4*)g_hB)[k] = o;
        }
    } else if (blockIdx.x < 1034) {
        // ---- weight prep: fold + emit fp16-MMA B-fragments ----
        int l = (blockIdx.x - 1024) / 5, m = (blockIdx.x - 1024) % 5;
        __shared__ float S[4096];
        __shared__ float T[4096];
        for (int i = threadIdx.x; i < 4096; i += blockDim.x) {
            float v;
            if (m == 0)      v = Wn[(l * 3 + 1) * 4096 + i];
            else if (m == 1) v = Wn[(l * 3 + 2) * 4096 + i];
            else if (m == 2) v = Wr[(l * 3 + 1) * 4096 + i] + Wr[(l * 3 + 2) * 4096 + i];
            else if (m == 3) v = Wn[(l * 3 + 0) * 4096 + i];
            else             v = Wr[(l * 3 + 0) * 4096 + i];
            S[i] = v;
        }
        __syncthreads();
        const float* src = S;
        if (l == 1) {
            for (int o = threadIdx.x; o < 4096; o += blockDim.x) {
                int i = o >> 6, j = o & 63;
                float acc = 0.f;
#pragma unroll 16
                for (int k = 0; k < 64; k++)
                    acc += S[i * 64 + k] * __ldg(Wout + k * 64 + j);
                T[o] = acc;
            }
            __syncthreads();
            src = T;
        }
        __half2* dst;
        int ktbase;
        if (m < 3) { dst = g_fragA[l]; ktbase = m * 4; }
        else       { dst = g_fragB[l]; ktbase = (m - 3) * 4; }
        for (int o = threadIdx.x; o < 1024; o += blockDim.x) {
            int kt2 = o >> 8, nt = (o >> 5) & 7, lane = o & 31;
            int k0 = kt2 * 16 + (lane & 3) * 2;
            int n = nt * 8 + (lane >> 2);
            int plane = ((ktbase + kt2) * 8 + nt) * 64 + lane;
            dst[plane]      = __floats2half2_rn(src[k0 * 64 + n], src[(k0 + 1) * 64 + n]);
            dst[plane + 32] = __floats2half2_rn(src[(k0 + 8) * 64 + n], src[(k0 + 9) * 64 + n]);
        }
    } else {
        // ---- biases (head-folded for layer 1) ----
        int j = threadIdx.x;
        if (j < 64) {
            g_bias[0][j]      = b[1 * 64 + j] + b[2 * 64 + j];
            g_bias[0][64 + j] = b[j];
            float accA = 0.f, accB = 0.f;
            for (int k = 0; k < 64; k++) {
                float w = __ldg(Wout + k * 64 + j);
                accA += (b[4 * 64 + k] + b[5 * 64 + k]) * w;
                accB += b[3 * 64 + k] * w;
            }
            g_bias[1][j]      = accA + bout[j];
            g_bias[1][64 + j] = accB + bout[j];
        }
    }
}

// ---------------- CSR build: chunk sums -------------------------------------
__global__ void chunk_sum_kernel() {
    int type = blockIdx.x / NCH, ch = blockIdx.x % NCH;
    const int* cnt = (type == 0) ? g_cnt0 : (type == 1) ? g_cnt1 : g_cnt2;
    int N = (type == 0) ? NB : NA;
    int i0 = ch * 2048 + threadIdx.x * 8;
    int s = 0;
#pragma unroll
    for (int k = 0; k < 8; k++) {
        int i = i0 + k;
        if (i < N) s += cnt[i];
    }
    __shared__ int red[256];
    red[threadIdx.x] = s;
    __syncthreads();
    for (int o = 128; o > 0; o >>= 1) {
        if (threadIdx.x < o) red[threadIdx.x] += red[threadIdx.x + o];
        __syncthreads();
    }
    if (threadIdx.x == 0) g_csum[type * 64 + ch] = red[0];
}

// ---------------- CSR build: write ptr + SELF-RESET counts ------------------
__global__ void write_ptr_kernel(int E0, int E1, int E2) {
    int type = blockIdx.x / NCH, ch = blockIdx.x % NCH;
    int* cnt; int* ptr; int* wofs; int N;
    if (type == 0)      { cnt = g_cnt0; ptr = g_ptr0; wofs = g_wofs0; N = NB; }
    else if (type == 1) { cnt = g_cnt1; ptr = g_ptr1; wofs = g_wofs1; N = NA; }
    else                { cnt = g_cnt2; ptr = g_ptr2; wofs = g_wofs2; N = NA; }

    if (threadIdx.x == 0 && ch == 0) {
        if (type == 0) g_ptr0[NB] = E0;
        else if (type == 1) g_ptr1[NA] = E1;
        else g_ptr2[NA] = E2;
    }

    __shared__ int csh[NCH];
    if (threadIdx.x < NCH) csh[threadIdx.x] = __ldg(&g_csum[type * 64 + threadIdx.x]);

    int i0 = ch * 2048 + threadIdx.x * 8;
    int c[8];
    int s = 0;
#pragma unroll
    for (int k = 0; k < 8; k++) {
        int i = i0 + k;
        c[k] = (i < N) ? cnt[i] : 0;
        s += c[k];
    }
    __shared__ int sd[256];
    sd[threadIdx.x] = s;
    __syncthreads();
    for (int o = 1; o < 256; o <<= 1) {
        int v = (threadIdx.x >= o) ? sd[threadIdx.x - o] : 0;
        __syncthreads();
        sd[threadIdx.x] += v;
        __syncthreads();
    }
    int cbase = 0;
    for (int c2 = 0; c2 < ch; c2++) cbase += csh[c2];
    int base = cbase + sd[threadIdx.x] - s;
#pragma unroll
    for (int k = 0; k < 8; k++) {
        int i = i0 + k;
        if (i < N) {
            ptr[i] = base;
            wofs[i] = base;
            cnt[i] = 0;          // self-reset for the next graph replay
            base += c[k];
        }
    }
}

// ---------------- CSR build: scatter (vectorized edge loads) ----------------
__device__ __forceinline__ void scat4(int4 s, int4 d, int* wofs, int* colv) {
    int p0 = atomicAdd(&wofs[d.x], 1);
    int p1 = atomicAdd(&wofs[d.y], 1);
    int p2 = atomicAdd(&wofs[d.z], 1);
    int p3 = atomicAdd(&wofs[d.w], 1);
    colv[p0] = s.x; colv[p1] = s.y; colv[p2] = s.z; colv[p3] = s.w;
}

__global__ void scatter_kernel(const int* __restrict__ s0, const int* __restrict__ d0,
                               const int* __restrict__ s1, const int* __restrict__ d1,
                               const int* __restrict__ s2, const int* __restrict__ d2,
                               int E0, int E1, int E2) {
    int t = blockIdx.x * blockDim.x + threadIdx.x;
    int stride = gridDim.x * blockDim.x;
    int q4 = E0 >> 2;
    for (int q = t; q < q4; q += stride)
        scat4(__ldg((const int4*)s0 + q), __ldg((const int4*)d0 + q), g_wofs0, g_col0);
    for (int e = q4 * 4 + t; e < E0; e += stride) {
        int p = atomicAdd(&g_wofs0[__ldg(d0 + e)], 1);
        g_col0[p] = __ldg(s0 + e);
    }
    q4 = E1 >> 2;
    for (int q = t; q < q4; q += stride)
        scat4(__ldg((const int4*)s1 + q), __ldg((const int4*)d1 + q), g_wofs1, g_col1);
    for (int e = q4 * 4 + t; e < E1; e += stride) {
        int p = atomicAdd(&g_wofs1[__ldg(d1 + e)], 1);
        g_col1[p] = __ldg(s1 + e);
    }
    q4 = E2 >> 2;
    for (int q = t; q < q4; q += stride)
        scat4(__ldg((const int4*)s2 + q), __ldg((const int4*)d2 + q), g_wofs2, g_col2);
    for (int e = q4 * 4 + t; e < E2; e += stride) {
        int p = atomicAdd(&g_wofs2[__ldg(d2 + e)], 1);
        g_col2[p] = __ldg(s2 + e);
    }
}

// ---------------- in-block CSR gather of one 32B slice of a node's mean -----
// 4 threads/node; thread c owns halves [16c, 16c+16) = 2 uint4 per edge.
__device__ __forceinline__ void acc8(uint4 u, float* a) {
    const __half2* h = (const __half2*)&u;
    float2 f;
    f = __half22float2(h[0]); a[0] += f.x; a[1] += f.y;
    f = __half22float2(h[1]); a[2] += f.x; a[3] += f.y;
    f = __half22float2(h[2]); a[4] += f.x; a[5] += f.y;
    f = __half22float2(h[3]); a[6] += f.x; a[7] += f.y;
}

__device__ __forceinline__ void gather_slice(
    __half* dst, const int* __restrict__ ptr, const int* __restrict__ col,
    const __half* __restrict__ x, int n, int c, bool valid) {
    float a[16];
#pragma unroll
    for (int t = 0; t < 16; t++) a[t] = 0.f;
    float inv = 1.0f;
    if (valid) {
        int beg = __ldg(ptr + n), end = __ldg(ptr + n + 1);
        const uint4* X = (const uint4*)x;
        int k = beg;
        int s0 = 0, s1 = 0;
        if (k < end) s0 = __ldg(col + k);
        if (k + 1 < end) s1 = __ldg(col + k + 1);
        while (k + 1 < end) {
            int ns0 = 0, ns1 = 0;
            if (k + 2 < end) ns0 = __ldg(col + k + 2);
            if (k + 3 < end) ns1 = __ldg(col + k + 3);
            uint4 u0 = __ldg(X + (size_t)s0 * 8 + c * 2);
            uint4 v0 = __ldg(X + (size_t)s0 * 8 + c * 2 + 1);
            uint4 u1 = __ldg(X + (size_t)s1 * 8 + c * 2);
            uint4 v1 = __ldg(X + (size_t)s1 * 8 + c * 2 + 1);
            acc8(u0, a); acc8(v0, a + 8);
            acc8(u1, a); acc8(v1, a + 8);
            s0 = ns0; s1 = ns1; k += 2;
        }
        if (k < end) {
            uint4 u0 = __ldg(X + (size_t)s0 * 8 + c * 2);
            uint4 v0 = __ldg(X + (size_t)s0 * 8 + c * 2 + 1);
            acc8(u0, a); acc8(v0, a + 8);
        }
        inv = 1.0f / fmaxf((float)(end - beg), 1.0f);
    }
    __half2 h[8];
#pragma unroll
    for (int t = 0; t < 8; t++)
        h[t] = __floats2half2_rn(a[2 * t] * inv, a[2 * t + 1] * inv);
    uint4 o0, o1;
    o0.x = *(unsigned*)&h[0]; o0.y = *(unsigned*)&h[1];
    o0.z = *(unsigned*)&h[2]; o0.w = *(unsigned*)&h[3];
    o1.x = *(unsigned*)&h[4]; o1.y = *(unsigned*)&h[5];
    o1.z = *(unsigned*)&h[6]; o1.w = *(unsigned*)&h[7];
    ((uint4*)dst)[0] = o0;
    ((uint4*)dst)[1] = o1;
}

// ---------------- fused layer: in-block gather + fp16 m16n8k16 combine ------
#define XH 200   // halves per row
template<bool FP32OUT>
__global__ __launch_bounds__(256, 5) void layer_kernel(
    const __half* __restrict__ hxA, const __half* __restrict__ hxB,
    const __half2* __restrict__ fragA, const __half2* __restrict__ fragB,
    const float* __restrict__ bl,
    float* __restrict__ outA, float* __restrict__ outB,
    __half* __restrict__ houtA, __half* __restrict__ houtB, int nbA) {
    extern __shared__ __align__(16) unsigned smraw[];
    __half* sxh = (__half*)smraw;                       // 64*200 halves = 25600B
    uint4* sxq = (uint4*)smraw;                         // row stride 25 uint4
    const int lane = threadIdx.x & 31;
    const int warp = threadIdx.x >> 5;
    const int mt = warp & 3;
    const int nh = warp >> 2;
    const int r8 = lane >> 2;
    const int c4 = lane & 3;
    const int gn = threadIdx.x >> 2;   // node in tile, 0..63 (gather phase)
    const int gc = threadIdx.x & 3;    // 32B slice, 0..3

    bool isA = (blockIdx.x < nbA);
    int row0, rows, KT;
    float* outX;
    __half* houtX;
    const float* blx;
    const __half2* frag;
    if (isA) {
        row0 = blockIdx.x * 64;
        rows = NA - row0 < 64 ? NA - row0 : 64;
        KT = 12;
        outX = outA; houtX = houtA; blx = bl; frag = fragA;
        for (int i = threadIdx.x; i < 512; i += 256) {
            int r = i >> 3, q = i & 7;
            uint4 u = make_uint4(0, 0, 0, 0);
            if (r < rows) u = __ldg((const uint4*)hxA + (size_t)(row0 + r) * 8 + q);
            sxq[r * 25 + 16 + q] = u;
        }
        bool valid = (gn < rows);
        int n = row0 + gn;
        gather_slice(sxh + gn * XH + 0 * 64 + gc * 16, g_ptr1, g_col1, hxB, n, gc, valid);
        gather_slice(sxh + gn * XH + 1 * 64 + gc * 16, g_ptr2, g_col2, hxA, n, gc, valid);
    } else {
        row0 = (blockIdx.x - nbA) * 64;
        rows = NB - row0 < 64 ? NB - row0 : 64;
        KT = 8;
        outX = outB; houtX = houtB; blx = bl + 64; frag = fragB;
        for (int i = threadIdx.x; i < 512; i += 256) {
            int r = i >> 3, q = i & 7;
            uint4 u = make_uint4(0, 0, 0, 0);
            if (r < rows) u = __ldg((const uint4*)hxB + (size_t)(row0 + r) * 8 + q);
            sxq[r * 25 + 8 + q] = u;
        }
        bool valid = (gn < rows);
        int n = row0 + gn;
        gather_slice(sxh + gn * XH + 0 * 64 + gc * 16, g_ptr0, g_col0, hxA, n, gc, valid);
    }
    __syncthreads();

    float acc[4][4];
#pragma unroll
    for (int t = 0; t < 4; t++) {
        acc[t][0] = 0.f; acc[t][1] = 0.f; acc[t][2] = 0.f; acc[t][3] = 0.f;
    }

    const __half* ap0 = sxh + (mt * 16 + r8) * XH + c4 * 2;
    for (int kt = 0; kt < KT; kt++) {
        const __half* ap = ap0 + kt * 16;
        unsigned a0 = *(const unsigned*)(ap);
        unsigned a1 = *(const unsigned*)(ap + 8 * XH);
        unsigned a2 = *(const unsigned*)(ap + 8);
        unsigned a3 = *(const unsigned*)(ap + 8 * XH + 8);
        const __half2* fp = frag + (kt * 8 + nh * 4) * 64 + lane;
#pragma unroll
        for (int t = 0; t < 4; t++) {
            __half2 b0 = __ldg(fp + t * 64);
            __half2 b1 = __ldg(fp + t * 64 + 32);
            mma_f16(acc[t], a0, a1, a2, a3,
                    *(unsigned*)&b0, *(unsigned*)&b1);
        }
    }

    int r0 = mt * 16 + r8;
#pragma unroll
    for (int t = 0; t < 4; t++) {
        int colj = (nh * 4 + t) * 8 + c4 * 2;
        float b0 = __ldg(blx + colj), b1 = __ldg(blx + colj + 1);
        float v00 = acc[t][0] + b0, v01 = acc[t][1] + b1;
        float v10 = acc[t][2] + b0, v11 = acc[t][3] + b1;
        if (FP32OUT) {
            v00 = fmaxf(v00, 0.f); v01 = fmaxf(v01, 0.f);
            v10 = fmaxf(v10, 0.f); v11 = fmaxf(v11, 0.f);
            if (r0 < rows)
                *(float2*)&outX[(size_t)(row0 + r0) * 64 + colj] = make_float2(v00, v01);
            if (r0 + 8 < rows)
                *(float2*)&outX[(size_t)(row0 + r0 + 8) * 64 + colj] = make_float2(v10, v11);
        } else {
            if (r0 < rows)
                *(__half2*)&houtX[(size_t)(row0 + r0) * 64 + colj] = __floats2half2_rn(v00, v01);
            if (r0 + 8 < rows)
                *(__half2*)&houtX[(size_t)(row0 + r0 + 8) * 64 + colj] = __floats2half2_rn(v10, v11);
        }
    }
}

// ---------------- launcher --------------------------------------------------
extern "C" void kernel_launch(void* const* d_in, const int* in_sizes, int n_in,
                              void* d_out, int out_size) {
    const float* x_A   = (const float*)d_in[0];
    const float* x_B   = (const float*)d_in[1];
    const float* Wn    = (const float*)d_in[2];
    const float* Wr    = (const float*)d_in[3];
    const float* b     = (const float*)d_in[4];
    const float* W_out = (const float*)d_in[5];
    const float* b_out = (const float*)d_in[6];
    const int* src0 = (const int*)d_in[7];
    const int* dst0 = (const int*)d_in[8];
    const int* src1 = (const int*)d_in[9];
    const int* dst1 = (const int*)d_in[10];
    const int* src2 = (const int*)d_in[11];
    const int* dst2 = (const int*)d_in[12];
    const int E0 = in_sizes[7];
    const int E1 = in_sizes[9];
    const int E2 = in_sizes[11];
    float* out = (float*)d_out;

    float *bias0, *bias1;
    __half2 *frA, *frB;
    __half *hA, *hB, *hA1, *hB1;
    cudaGetSymbolAddress((void**)&hA, g_hA);
    cudaGetSymbolAddress((void**)&hB, g_hB);
    cudaGetSymbolAddress((void**)&hA1, g_hA1);
    cudaGetSymbolAddress((void**)&hB1, g_hB1);
    cudaGetSymbolAddress((void**)&frA, g_fragA);
    cudaGetSymbolAddress((void**)&frB, g_fragB);
    cudaGetSymbolAddress((void**)&bias0, g_bias);
    bias1 = bias0 + 128;

    const int nbA = (NA + 63) / 64;
    const int nbB = (NB + 63) / 64;
    const int smemBytes = 25600;   // X tile only; frags live in L1

    cudaFuncSetAttribute(layer_kernel<false>,
                         cudaFuncAttributeMaxDynamicSharedMemorySize, smemBytes);
    cudaFuncSetAttribute(layer_kernel<true>,
                         cudaFuncAttributeMaxDynamicSharedMemorySize, smemBytes);

    // ---- fused prologue: hist + conv + weight prep (all independent) ----
    prologue_kernel<<<1035, 256>>>(x_A, x_B, Wn, Wr, b, W_out, b_out,
                                   dst0, dst1, dst2, E0, E1, E2);

    // ---- CSR build (cnt arrays self-reset by write_ptr; no memsets) ----
    chunk_sum_kernel<<<3 * NCH, 256>>>();
    write_ptr_kernel<<<3 * NCH, 256>>>(E0, E1, E2);
    scatter_kernel<<<1024, 256>>>(src0, dst0, src1, dst1, src2, dst2, E0, E1, E2);

    // ---- layer 0 (fused gather+combine; outputs fp16 only) ----
    layer_kernel<false><<<nbA + nbB, 256, smemBytes>>>(
        hA, hB, frA, frB, bias0, nullptr, nullptr, hA1, hB1, nbA);

    // ---- layer 1 (fused; head folded into weights; relu at store; fp32 out) ----
    layer_kernel<true><<<nbA + nbB, 256, smemBytes>>>(
        hA1, hB1, frA + 12 * 8 * 64, frB + 8 * 8 * 64, bias1,
        out, out + (size_t)NA * 64, nullptr, nullptr, nbA);
}

// round 16
// speedup vs baseline: 4.3932x; 1.0067x over previous
#include <cuda_runtime.h>
#include <cuda_fp16.h>
#include <cstddef>

#define NA 100000
#define NB 100000
#define DD 64
#define EMAX 1250000
#define NCH 49          // chunks of 2048 nodes: 49*2048 >= 100000

// ---------------- fp16 mma helper (m16n8k16, fp32 accum) --------------------
__device__ __forceinline__ void mma_f16(float* c, unsigned a0, unsigned a1,
                                        unsigned a2, unsigned a3,
                                        unsigned b0, unsigned b1) {
    asm("mma.sync.aligned.m16n8k16.row.col.f32.f16.f16.f32 "
        "{%0,%1,%2,%3}, {%4,%5,%6,%7}, {%8,%9}, {%0,%1,%2,%3};"
        : "+f"(c[0]), "+f"(c[1]), "+f"(c[2]), "+f"(c[3])
        : "r"(a0), "r"(a1), "r"(a2), "r"(a3), "r"(b0), "r"(b1));
}

// ---------------- scratch (device globals: no allocation allowed) ----------
__device__ int g_cnt0[NB], g_cnt1[NA], g_cnt2[NA];
__device__ int g_ptr0[NB + 1], g_ptr1[NA + 1], g_ptr2[NA + 1];
__device__ int g_wofs0[NB], g_wofs1[NA], g_wofs2[NA];
__device__ int g_col0[EMAX], g_col1[EMAX], g_col2[EMAX];
__device__ int g_csum[3 * 64];
// fp16 feature tables
__device__ __align__(16) __half g_hA[NA * DD];
__device__ __align__(16) __half g_hB[NB * DD];
__device__ __align__(16) __half g_hA1[NA * DD];
__device__ __align__(16) __half g_hB1[NB * DD];
// fp16-MMA B-fragments. Per (ktile16, ntile8): 64 half2 = {b0 plane 32, b1 plane 32}
// A-side K=192 -> 12 ktiles; B-side K=128 -> 8 ktiles. Read via L1.
__device__ __align__(16) __half2 g_fragA[2][12 * 8 * 64];
__device__ __align__(16) __half2 g_fragB[2][8 * 8 * 64];
__device__ float g_bias[2][128];   // [l][0:64]=A bias, [64:128]=B bias

// ---------------- fused prologue: hist (vec) + fp16 conv + weight prep ------
// blocks 0..1023  : histogram of dst arrays (int4 loads) + fp32->fp16 conv
// blocks 1024..1033: weight matrix prep (fold + fragment pack)
// block 1034      : biases
__global__ void prologue_kernel(
    const float* __restrict__ xA, const float* __restrict__ xB,
    const float* __restrict__ Wn, const float* __restrict__ Wr,
    const float* __restrict__ b,
    const float* __restrict__ Wout, const float* __restrict__ bout,
    const int* __restrict__ d0, const int* __restrict__ d1,
    const int* __restrict__ d2,
    int E0, int E1, int E2) {
    if (blockIdx.x < 1024) {
        int t = blockIdx.x * 256 + threadIdx.x;
        const int stride = 1024 * 256;
        // ---- histogram, 4 edges per int4 load ----
        {
            int q4 = E0 >> 2;
            for (int q = t; q < q4; q += stride) {
                int4 d = __ldg((const int4*)d0 + q);
                atomicAdd(&g_cnt0[d.x], 1); atomicAdd(&g_cnt0[d.y], 1);
                atomicAdd(&g_cnt0[d.z], 1); atomicAdd(&g_cnt0[d.w], 1);
            }
            for (int e = q4 * 4 + t; e < E0; e += stride)
                atomicAdd(&g_cnt0[__ldg(d0 + e)], 1);
            q4 = E1 >> 2;
            for (int q = t; q < q4; q += stride) {
                int4 d = __ldg((const int4*)d1 + q);
                atomicAdd(&g_cnt1[d.x], 1); atomicAdd(&g_cnt1[d.y], 1);
                atomicAdd(&g_cnt1[d.z], 1); atomicAdd(&g_cnt1[d.w], 1);
            }
            for (int e = q4 * 4 + t; e < E1; e += stride)
                atomicAdd(&g_cnt1[__ldg(d1 + e)], 1);
            q4 = E2 >> 2;
            for (int q = t; q < q4; q += stride) {
                int4 d = __ldg((const int4*)d2 + q);
                atomicAdd(&g_cnt2[d.x], 1); atomicAdd(&g_cnt2[d.y], 1);
                atomicAdd(&g_cnt2[d.z], 1); atomicAdd(&g_cnt2[d.w], 1);
            }
            for (int e = q4 * 4 + t; e < E2; e += stride)
                atomicAdd(&g_cnt2[__ldg(d2 + e)], 1);
        }
        // ---- fp32 -> fp16 feature conversion ----
        const int n8 = NA * 8;
        for (int k = t; k < n8; k += stride) {
            float4 f0 = __ldg((const float4*)xA + k * 2);
            float4 f1 = __ldg((const float4*)xA + k * 2 + 1);
            __half2 h0 = __floats2half2_rn(f0.x, f0.y);
            __half2 h1 = __floats2half2_rn(f0.z, f0.w);
            __half2 h2 = __floats2half2_rn(f1.x, f1.y);
            __half2 h3 = __floats2half2_rn(f1.z, f1.w);
            uint4 o;
            o.x = *(unsigned*)&h0; o.y = *(unsigned*)&h1;
            o.z = *(unsigned*)&h2; o.w = *(unsigned*)&h3;
            ((uint4*)g_hA)[k] = o;
        }
        const int m8 = NB * 8;
        for (int k = t; k < m8; k += stride) {
            float4 f0 = __ldg((const float4*)xB + k * 2);
            float4 f1 = __ldg((const float4*)xB + k * 2 + 1);
            __half2 h0 = __floats2half2_rn(f0.x, f0.y);
            __half2 h1 = __floats2half2_rn(f0.z, f0.w);
            __half2 h2 = __floats2half2_rn(f1.x, f1.y);
            __half2 h3 = __floats2half2_rn(f1.z, f1.w);
            uint4 o;
            o.x = *(unsigned*)&h0; o.y = *(unsigned*)&h1;
            o.z = *(unsigned*)&h2; o.w = *(unsigned*)&h3;
            ((uint4*)g_hB)[k] = o;
        }
    } else if (blockIdx.x < 1034) {
        // ---- weight prep: fold + emit fp16-MMA B-fragments ----
        int l = (blockIdx.x - 1024) / 5, m = (blockIdx.x - 1024) % 5;
        __shared__ float S[4096];
        __shared__ float T[4096];
        for (int i = threadIdx.x; i < 4096; i += blockDim.x) {
            float v;
            if (m == 0)      v = Wn[(l * 3 + 1) * 4096 + i];
            else if (m == 1) v = Wn[(l * 3 + 2) * 4096 + i];
            else if (m == 2) v = Wr[(l * 3 + 1) * 4096 + i] + Wr[(l * 3 + 2) * 4096 + i];
            else if (m == 3) v = Wn[(l * 3 + 0) * 4096 + i];
            else             v = Wr[(l * 3 + 0) * 4096 + i];
            S[i] = v;
        }
        __syncthreads();
        const float* src = S;
        if (l == 1) {
            for (int o = threadIdx.x; o < 4096; o += blockDim.x) {
                int i = o >> 6, j = o & 63;
                float acc = 0.f;
#pragma unroll 16
                for (int k = 0; k < 64; k++)
                    acc += S[i * 64 + k] * __ldg(Wout + k * 64 + j);
                T[o] = acc;
            }
            __syncthreads();
            src = T;
        }
        __half2* dst;
        int ktbase;
        if (m < 3) { dst = g_fragA[l]; ktbase = m * 4; }
        else       { dst = g_fragB[l]; ktbase = (m - 3) * 4; }
        for (int o = threadIdx.x; o < 1024; o += blockDim.x) {
            int kt2 = o >> 8, nt = (o >> 5) & 7, lane = o & 31;
            int k0 = kt2 * 16 + (lane & 3) * 2;
            int n = nt * 8 + (lane >> 2);
            int plane = ((ktbase + kt2) * 8 + nt) * 64 + lane;
            dst[plane]      = __floats2half2_rn(src[k0 * 64 + n], src[(k0 + 1) * 64 + n]);
            dst[plane + 32] = __floats2half2_rn(src[(k0 + 8) * 64 + n], src[(k0 + 9) * 64 + n]);
        }
    } else {
        // ---- biases (head-folded for layer 1) ----
        int j = threadIdx.x;
        if (j < 64) {
            g_bias[0][j]      = b[1 * 64 + j] + b[2 * 64 + j];
            g_bias[0][64 + j] = b[j];
            float accA = 0.f, accB = 0.f;
            for (int k = 0; k < 64; k++) {
                float w = __ldg(Wout + k * 64 + j);
                accA += (b[4 * 64 + k] + b[5 * 64 + k]) * w;
                accB += b[3 * 64 + k] * w;
            }
            g_bias[1][j]      = accA + bout[j];
            g_bias[1][64 + j] = accB + bout[j];
        }
    }
}

// ---------------- CSR build: chunk sums -------------------------------------
__global__ void chunk_sum_kernel() {
    int type = blockIdx.x / NCH, ch = blockIdx.x % NCH;
    const int* cnt = (type == 0) ? g_cnt0 : (type == 1) ? g_cnt1 : g_cnt2;
    int N = (type == 0) ? NB : NA;
    int i0 = ch * 2048 + threadIdx.x * 8;
    int s = 0;
#pragma unroll
    for (int k = 0; k < 8; k++) {
        int i = i0 + k;
        if (i < N) s += cnt[i];
    }
    __shared__ int red[256];
    red[threadIdx.x] = s;
    __syncthreads();
    for (int o = 128; o > 0; o >>= 1) {
        if (threadIdx.x < o) red[threadIdx.x] += red[threadIdx.x + o];
        __syncthreads();
    }
    if (threadIdx.x == 0) g_csum[type * 64 + ch] = red[0];
}

// ---------------- CSR build: write ptr + SELF-RESET counts ------------------
__global__ void write_ptr_kernel(int E0, int E1, int E2) {
    int type = blockIdx.x / NCH, ch = blockIdx.x % NCH;
    int* cnt; int* ptr; int* wofs; int N;
    if (type == 0)      { cnt = g_cnt0; ptr = g_ptr0; wofs = g_wofs0; N = NB; }
    else if (type == 1) { cnt = g_cnt1; ptr = g_ptr1; wofs = g_wofs1; N = NA; }
    else                { cnt = g_cnt2; ptr = g_ptr2; wofs = g_wofs2; N = NA; }

    if (threadIdx.x == 0 && ch == 0) {
        if (type == 0) g_ptr0[NB] = E0;
        else if (type == 1) g_ptr1[NA] = E1;
        else g_ptr2[NA] = E2;
    }

    __shared__ int csh[NCH];
    if (threadIdx.x < NCH) csh[threadIdx.x] = __ldg(&g_csum[type * 64 + threadIdx.x]);

    int i0 = ch * 2048 + threadIdx.x * 8;
    int c[8];
    int s = 0;
#pragma unroll
    for (int k = 0; k < 8; k++) {
        int i = i0 + k;
        c[k] = (i < N) ? cnt[i] : 0;
        s += c[k];
    }
    __shared__ int sd[256];
    sd[threadIdx.x] = s;
    __syncthreads();
    for (int o = 1; o < 256; o <<= 1) {
        int v = (threadIdx.x >= o) ? sd[threadIdx.x - o] : 0;
        __syncthreads();
        sd[threadIdx.x] += v;
        __syncthreads();
    }
    int cbase = 0;
    for (int c2 = 0; c2 < ch; c2++) cbase += csh[c2];
    int base = cbase + sd[threadIdx.x] - s;
#pragma unroll
    for (int k = 0; k < 8; k++) {
        int i = i0 + k;
        if (i < N) {
            ptr[i] = base;
            wofs[i] = base;
            cnt[i] = 0;          // self-reset for the next graph replay
            base += c[k];
        }
    }
}

// ---------------- CSR build: scatter (8 edges / iteration, deep MLP) --------
__device__ __forceinline__ void scat8(int4 sa, int4 da, int4 sb, int4 db,
                                      int* wofs, int* colv) {
    int p0 = atomicAdd(&wofs[da.x], 1);
    int p1 = atomicAdd(&wofs[da.y], 1);
    int p2 = atomicAdd(&wofs[da.z], 1);
    int p3 = atomicAdd(&wofs[da.w], 1);
    int p4 = atomicAdd(&wofs[db.x], 1);
    int p5 = atomicAdd(&wofs[db.y], 1);
    int p6 = atomicAdd(&wofs[db.z], 1);
    int p7 = atomicAdd(&wofs[db.w], 1);
    colv[p0] = sa.x; colv[p1] = sa.y; colv[p2] = sa.z; colv[p3] = sa.w;
    colv[p4] = sb.x; colv[p5] = sb.y; colv[p6] = sb.z; colv[p7] = sb.w;
}

__device__ __forceinline__ void scatter_one(const int* __restrict__ s,
                                            const int* __restrict__ d,
                                            int* wofs, int* colv,
                                            int E, int t, int stride) {
    int q8 = E >> 3;   // groups of 8 edges (2 int4)
    for (int q = t; q < q8; q += stride) {
        int4 da = __ldg((const int4*)d + q * 2);
        int4 db = __ldg((const int4*)d + q * 2 + 1);
        int4 sa = __ldg((const int4*)s + q * 2);
        int4 sb = __ldg((const int4*)s + q * 2 + 1);
        scat8(sa, da, sb, db, wofs, colv);
    }
    for (int e = q8 * 8 + t; e < E; e += stride) {
        int p = atomicAdd(&wofs[__ldg(d + e)], 1);
        colv[p] = __ldg(s + e);
    }
}

__global__ void scatter_kernel(const int* __restrict__ s0, const int* __restrict__ d0,
                               const int* __restrict__ s1, const int* __restrict__ d1,
                               const int* __restrict__ s2, const int* __restrict__ d2,
                               int E0, int E1, int E2) {
    int t = blockIdx.x * blockDim.x + threadIdx.x;
    int stride = gridDim.x * blockDim.x;
    scatter_one(s0, d0, g_wofs0, g_col0, E0, t, stride);
    scatter_one(s1, d1, g_wofs1, g_col1, E1, t, stride);
    scatter_one(s2, d2, g_wofs2, g_col2, E2, t, stride);
}

// ---------------- in-block CSR gather of one 32B slice of a node's mean -----
// 4 threads/node; thread c owns halves [16c, 16c+16) = 2 uint4 per edge.
__device__ __forceinline__ void acc8(uint4 u, float* a) {
    const __half2* h = (const __half2*)&u;
    float2 f;
    f = __half22float2(h[0]); a[0] += f.x; a[1] += f.y;
    f = __half22float2(h[1]); a[2] += f.x; a[3] += f.y;
    f = __half22float2(h[2]); a[4] += f.x; a[5] += f.y;
    f = __half22float2(h[3]); a[6] += f.x; a[7] += f.y;
}

__device__ __forceinline__ void gather_slice(
    __half* dst, const int* __restrict__ ptr, const int* __restrict__ col,
    const __half* __restrict__ x, int n, int c, bool valid) {
    float a[16];
#pragma unroll
    for (int t = 0; t < 16; t++) a[t] = 0.f;
    float inv = 1.0f;
    if (valid) {
        int beg = __ldg(ptr + n), end = __ldg(ptr + n + 1);
        const uint4* X = (const uint4*)x;
        int k = beg;
        int s0 = 0, s1 = 0;
        if (k < end) s0 = __ldg(col + k);
        if (k + 1 < end) s1 = __ldg(col + k + 1);
        while (k + 1 < end) {
            int ns0 = 0, ns1 = 0;
            if (k + 2 < end) ns0 = __ldg(col + k + 2);
            if (k + 3 < end) ns1 = __ldg(col + k + 3);
            uint4 u0 = __ldg(X + (size_t)s0 * 8 + c * 2);
            uint4 v0 = __ldg(X + (size_t)s0 * 8 + c * 2 + 1);
            uint4 u1 = __ldg(X + (size_t)s1 * 8 + c * 2);
            uint4 v1 = __ldg(X + (size_t)s1 * 8 + c * 2 + 1);
            acc8(u0, a); acc8(v0, a + 8);
            acc8(u1, a); acc8(v1, a + 8);
            s0 = ns0; s1 = ns1; k += 2;
        }
        if (k < end) {
            uint4 u0 = __ldg(X + (size_t)s0 * 8 + c * 2);
            uint4 v0 = __ldg(X + (size_t)s0 * 8 + c * 2 + 1);
            acc8(u0, a); acc8(v0, a + 8);
        }
        inv = 1.0f / fmaxf((float)(end - beg), 1.0f);
    }
    __half2 h[8];
#pragma unroll
    for (int t = 0; t < 8; t++)
        h[t] = __floats2half2_rn(a[2 * t] * inv, a[2 * t + 1] * inv);
    uint4 o0, o1;
    o0.x = *(unsigned*)&h[0]; o0.y = *(unsigned*)&h[1];
    o0.z = *(unsigned*)&h[2]; o0.w = *(unsigned*)&h[3];
    o1.x = *(unsigned*)&h[4]; o1.y = *(unsigned*)&h[5];
    o1.z = *(unsigned*)&h[6]; o1.w = *(unsigned*)&h[7];
    ((uint4*)dst)[0] = o0;
    ((uint4*)dst)[1] = o1;
}

// ---------------- fused layer: in-block gather + fp16 m16n8k16 combine ------
#define XH 200   // halves per row
template<bool FP32OUT>
__global__ __launch_bounds__(256, 5) void layer_kernel(
    const __half* __restrict__ hxA, const __half* __restrict__ hxB,
    const __half2* __restrict__ fragA, const __half2* __restrict__ fragB,
    const float* __restrict__ bl,
    float* __restrict__ outA, float* __restrict__ outB,
    __half* __restrict__ houtA, __half* __restrict__ houtB, int nbA) {
    extern __shared__ __align__(16) unsigned smraw[];
    __half* sxh = (__half*)smraw;                       // 64*200 halves = 25600B
    uint4* sxq = (uint4*)smraw;                         // row stride 25 uint4
    const int lane = threadIdx.x & 31;
    const int warp = threadIdx.x >> 5;
    const int mt = warp & 3;
    const int nh = warp >> 2;
    const int r8 = lane >> 2;
    const int c4 = lane & 3;
    const int gn = threadIdx.x >> 2;   // node in tile, 0..63 (gather phase)
    const int gc = threadIdx.x & 3;    // 32B slice, 0..3

    bool isA = (blockIdx.x < nbA);
    int row0, rows, KT;
    float* outX;
    __half* houtX;
    const float* blx;
    const __half2* frag;
    if (isA) {
        row0 = blockIdx.x * 64;
        rows = NA - row0 < 64 ? NA - row0 : 64;
        KT = 12;
        outX = outA; houtX = houtA; blx = bl; frag = fragA;
        for (int i = threadIdx.x; i < 512; i += 256) {
            int r = i >> 3, q = i & 7;
            uint4 u = make_uint4(0, 0, 0, 0);
            if (r < rows) u = __ldg((const uint4*)hxA + (size_t)(row0 + r) * 8 + q);
            sxq[r * 25 + 16 + q] = u;
        }
        bool valid = (gn < rows);
        int n = row0 + gn;
        gather_slice(sxh + gn * XH + 0 * 64 + gc * 16, g_ptr1, g_col1, hxB, n, gc, valid);
        gather_slice(sxh + gn * XH + 1 * 64 + gc * 16, g_ptr2, g_col2, hxA, n, gc, valid);
    } else {
        row0 = (blockIdx.x - nbA) * 64;
        rows = NB - row0 < 64 ? NB - row0 : 64;
        KT = 8;
        outX = outB; houtX = houtB; blx = bl + 64; frag = fragB;
        for (int i = threadIdx.x; i < 512; i += 256) {
            int r = i >> 3, q = i & 7;
            uint4 u = make_uint4(0, 0, 0, 0);
            if (r < rows) u = __ldg((const uint4*)hxB + (size_t)(row0 + r) * 8 + q);
            sxq[r * 25 + 8 + q] = u;
        }
        bool valid = (gn < rows);
        int n = row0 + gn;
        gather_slice(sxh + gn * XH + 0 * 64 + gc * 16, g_ptr0, g_col0, hxA, n, gc, valid);
    }
    __syncthreads();

    float acc[4][4];
#pragma unroll
    for (int t = 0; t < 4; t++) {
        acc[t][0] = 0.f; acc[t][1] = 0.f; acc[t][2] = 0.f; acc[t][3] = 0.f;
    }

    const __half* ap0 = sxh + (mt * 16 + r8) * XH + c4 * 2;
    for (int kt = 0; kt < KT; kt++) {
        const __half* ap = ap0 + kt * 16;
        unsigned a0 = *(const unsigned*)(ap);
        unsigned a1 = *(const unsigned*)(ap + 8 * XH);
        unsigned a2 = *(const unsigned*)(ap + 8);
        unsigned a3 = *(const unsigned*)(ap + 8 * XH + 8);
        const __half2* fp = frag + (kt * 8 + nh * 4) * 64 + lane;
#pragma unroll
        for (int t = 0; t < 4; t++) {
            __half2 b0 = __ldg(fp + t * 64);
            __half2 b1 = __ldg(fp + t * 64 + 32);
            mma_f16(acc[t], a0, a1, a2, a3,
                    *(unsigned*)&b0, *(unsigned*)&b1);
        }
    }

    int r0 = mt * 16 + r8;
#pragma unroll
    for (int t = 0; t < 4; t++) {
        int colj = (nh * 4 + t) * 8 + c4 * 2;
        float b0 = __ldg(blx + colj), b1 = __ldg(blx + colj + 1);
        float v00 = acc[t][0] + b0, v01 = acc[t][1] + b1;
        float v10 = acc[t][2] + b0, v11 = acc[t][3] + b1;
        if (FP32OUT) {
            v00 = fmaxf(v00, 0.f); v01 = fmaxf(v01, 0.f);
            v10 = fmaxf(v10, 0.f); v11 = fmaxf(v11, 0.f);
            if (r0 < rows)
                *(float2*)&outX[(size_t)(row0 + r0) * 64 + colj] = make_float2(v00, v01);
            if (r0 + 8 < rows)
                *(float2*)&outX[(size_t)(row0 + r0 + 8) * 64 + colj] = make_float2(v10, v11);
        } else {
            if (r0 < rows)
                *(__half2*)&houtX[(size_t)(row0 + r0) * 64 + colj] = __floats2half2_rn(v00, v01);
            if (r0 + 8 < rows)
                *(__half2*)&houtX[(size_t)(row0 + r0 + 8) * 64 + colj] = __floats2half2_rn(v10, v11);
        }
    }
}

// ---------------- launcher --------------------------------------------------
extern "C" void kernel_launch(void* const* d_in, const int* in_sizes, int n_in,
                              void* d_out, int out_size) {
    const float* x_A   = (const float*)d_in[0];
    const float* x_B   = (const float*)d_in[1];
    const float* Wn    = (const float*)d_in[2];
    const float* Wr    = (const float*)d_in[3];
    const float* b     = (const float*)d_in[4];
    const float* W_out = (const float*)d_in[5];
    const float* b_out = (const float*)d_in[6];
    const int* src0 = (const int*)d_in[7];
    const int* dst0 = (const int*)d_in[8];
    const int* src1 = (const int*)d_in[9];
    const int* dst1 = (const int*)d_in[10];
    const int* src2 = (const int*)d_in[11];
    const int* dst2 = (const int*)d_in[12];
    const int E0 = in_sizes[7];
    const int E1 = in_sizes[9];
    const int E2 = in_sizes[11];
    float* out = (float*)d_out;

    float *bias0, *bias1;
    __half2 *frA, *frB;
    __half *hA, *hB, *hA1, *hB1;
    cudaGetSymbolAddress((void**)&hA, g_hA);
    cudaGetSymbolAddress((void**)&hB, g_hB);
    cudaGetSymbolAddress((void**)&hA1, g_hA1);
    cudaGetSymbolAddress((void**)&hB1, g_hB1);
    cudaGetSymbolAddress((void**)&frA, g_fragA);
    cudaGetSymbolAddress((void**)&frB, g_fragB);
    cudaGetSymbolAddress((void**)&bias0, g_bias);
    bias1 = bias0 + 128;

    const int nbA = (NA + 63) / 64;
    const int nbB = (NB + 63) / 64;
    const int smemBytes = 25600;   // X tile only; frags live in L1

    cudaFuncSetAttribute(layer_kernel<false>,
                         cudaFuncAttributeMaxDynamicSharedMemorySize, smemBytes);
    cudaFuncSetAttribute(layer_kernel<true>,
                         cudaFuncAttributeMaxDynamicSharedMemorySize, smemBytes);

    // ---- fused prologue: hist + conv + weight prep (all independent) ----
    prologue_kernel<<<1035, 256>>>(x_A, x_B, Wn, Wr, b, W_out, b_out,
                                   dst0, dst1, dst2, E0, E1, E2);

    // ---- CSR build (cnt arrays self-reset by write_ptr; no memsets) ----
    chunk_sum_kernel<<<3 * NCH, 256>>>();
    write_ptr_kernel<<<3 * NCH, 256>>>(E0, E1, E2);
    scatter_kernel<<<1024, 256>>>(src0, dst0, src1, dst1, src2, dst2, E0, E1, E2);

    // ---- layer 0 (fused gather+combine; outputs fp16 only) ----
    layer_kernel<false><<<nbA + nbB, 256, smemBytes>>>(
        hA, hB, frA, frB, bias0, nullptr, nullptr, hA1, hB1, nbA);

    // ---- layer 1 (fused; head folded into weights; relu at store; fp32 out) ----
    layer_kernel<true><<<nbA + nbB, 256, smemBytes>>>(
        hA1, hB1, frA + 12 * 8 * 64, frB + 8 * 8 * 64, bias1,
        out, out + (size_t)NA * 64, nullptr, nullptr, nbA);
}

// round 17
// speedup vs baseline: 4.4277x; 1.0079x over previous
#include <cuda_runtime.h>
#include <cuda_fp16.h>
#include <cstddef>

#define NA 100000
#define NB 100000
#define DD 64
#define EMAX 1250000
#define NCH 49          // chunks of 2048 nodes: 49*2048 >= 100000

// ---------------- fp16 mma helper (m16n8k16, fp32 accum) --------------------
__device__ __forceinline__ void mma_f16(float* c, unsigned a0, unsigned a1,
                                        unsigned a2, unsigned a3,
                                        unsigned b0, unsigned b1) {
    asm("mma.sync.aligned.m16n8k16.row.col.f32.f16.f16.f32 "
        "{%0,%1,%2,%3}, {%4,%5,%6,%7}, {%8,%9}, {%0,%1,%2,%3};"
        : "+f"(c[0]), "+f"(c[1]), "+f"(c[2]), "+f"(c[3])
        : "r"(a0), "r"(a1), "r"(a2), "r"(a3), "r"(b0), "r"(b1));
}

// ---------------- scratch (device globals: no allocation allowed) ----------
__device__ int g_cnt0[NB], g_cnt1[NA], g_cnt2[NA];
__device__ int g_ptr0[NB + 1], g_ptr1[NA + 1], g_ptr2[NA + 1];
__device__ int g_wofs0[NB], g_wofs1[NA], g_wofs2[NA];
__device__ int g_col0[EMAX], g_col1[EMAX], g_col2[EMAX];
__device__ int g_csum[3 * 64];
// fp16 feature tables
__device__ __align__(16) __half g_hA[NA * DD];
__device__ __align__(16) __half g_hB[NB * DD];
__device__ __align__(16) __half g_hA1[NA * DD];
__device__ __align__(16) __half g_hB1[NB * DD];
// fp16-MMA B-fragments. Per (ktile16, ntile8): 64 half2 = {b0 plane 32, b1 plane 32}
// A-side K=192 -> 12 ktiles; B-side K=128 -> 8 ktiles. Read via L1.
__device__ __align__(16) __half2 g_fragA[2][12 * 8 * 64];
__device__ __align__(16) __half2 g_fragB[2][8 * 8 * 64];
__device__ float g_bias[2][128];   // [l][0:64]=A bias, [64:128]=B bias

// ---------------- fused prologue: hist (vec) + fp16 conv + weight prep ------
// blocks 0..1023  : histogram of dst arrays (int4 loads) + fp32->fp16 conv
// blocks 1024..1033: weight matrix prep (fold + fragment pack)
// block 1034      : biases
__global__ void prologue_kernel(
    const float* __restrict__ xA, const float* __restrict__ xB,
    const float* __restrict__ Wn, const float* __restrict__ Wr,
    const float* __restrict__ b,
    const float* __restrict__ Wout, const float* __restrict__ bout,
    const int* __restrict__ d0, const int* __restrict__ d1,
    const int* __restrict__ d2,
    int E0, int E1, int E2) {
    if (blockIdx.x < 1024) {
        int t = blockIdx.x * 256 + threadIdx.x;
        const int stride = 1024 * 256;
        // ---- histogram, 4 edges per int4 load ----
        {
            int q4 = E0 >> 2;
            for (int q = t; q < q4; q += stride) {
                int4 d = __ldg((const int4*)d0 + q);
                atomicAdd(&g_cnt0[d.x], 1); atomicAdd(&g_cnt0[d.y], 1);
                atomicAdd(&g_cnt0[d.z], 1); atomicAdd(&g_cnt0[d.w], 1);
            }
            for (int e = q4 * 4 + t; e < E0; e += stride)
                atomicAdd(&g_cnt0[__ldg(d0 + e)], 1);
            q4 = E1 >> 2;
            for (int q = t; q < q4; q += stride) {
                int4 d = __ldg((const int4*)d1 + q);
                atomicAdd(&g_cnt1[d.x], 1); atomicAdd(&g_cnt1[d.y], 1);
                atomicAdd(&g_cnt1[d.z], 1); atomicAdd(&g_cnt1[d.w], 1);
            }
            for (int e = q4 * 4 + t; e < E1; e += stride)
                atomicAdd(&g_cnt1[__ldg(d1 + e)], 1);
            q4 = E2 >> 2;
            for (int q = t; q < q4; q += stride) {
                int4 d = __ldg((const int4*)d2 + q);
                atomicAdd(&g_cnt2[d.x], 1); atomicAdd(&g_cnt2[d.y], 1);
                atomicAdd(&g_cnt2[d.z], 1); atomicAdd(&g_cnt2[d.w], 1);
            }
            for (int e = q4 * 4 + t; e < E2; e += stride)
                atomicAdd(&g_cnt2[__ldg(d2 + e)], 1);
        }
        // ---- fp32 -> fp16 feature conversion ----
        const int n8 = NA * 8;
        for (int k = t; k < n8; k += stride) {
            float4 f0 = __ldg((const float4*)xA + k * 2);
            float4 f1 = __ldg((const float4*)xA + k * 2 + 1);
            __half2 h0 = __floats2half2_rn(f0.x, f0.y);
            __half2 h1 = __floats2half2_rn(f0.z, f0.w);
            __half2 h2 = __floats2half2_rn(f1.x, f1.y);
            __half2 h3 = __floats2half2_rn(f1.z, f1.w);
            uint4 o;
            o.x = *(unsigned*)&h0; o.y = *(unsigned*)&h1;
            o.z = *(unsigned*)&h2; o.w = *(unsigned*)&h3;
            ((uint4*)g_hA)[k] = o;
        }
        const int m8 = NB * 8;
        for (int k = t; k < m8; k += stride) {
            float4 f0 = __ldg((const float4*)xB + k * 2);
            float4 f1 = __ldg((const float4*)xB + k * 2 + 1);
            __half2 h0 = __floats2half2_rn(f0.x, f0.y);
            __half2 h1 = __floats2half2_rn(f0.z, f0.w);
            __half2 h2 = __floats2half2_rn(f1.x, f1.y);
            __half2 h3 = __floats2half2_rn(f1.z, f1.w);
            uint4 o;
            o.x = *(unsigned*)&h0; o.y = *(unsigned*)&h1;
            o.z = *(unsigned*)&h2; o.w = *(unsigned*)&h3;
            ((uint4*)g_hB)[k] = o;
        }
    } else if (blockIdx.x < 1034) {
        // ---- weight prep: fold + emit fp16-MMA B-fragments ----
        int l = (blockIdx.x - 1024) / 5, m = (blockIdx.x - 1024) % 5;
        __shared__ float S[4096];
        __shared__ float T[4096];
        for (int i = threadIdx.x; i < 4096; i += blockDim.x) {
            float v;
            if (m == 0)      v = Wn[(l * 3 + 1) * 4096 + i];
            else if (m == 1) v = Wn[(l * 3 + 2) * 4096 + i];
            else if (m == 2) v = Wr[(l * 3 + 1) * 4096 + i] + Wr[(l * 3 + 2) * 4096 + i];
            else if (m == 3) v = Wn[(l * 3 + 0) * 4096 + i];
            else             v = Wr[(l * 3 + 0) * 4096 + i];
            S[i] = v;
        }
        __syncthreads();
        const float* src = S;
        if (l == 1) {
            for (int o = threadIdx.x; o < 4096; o += blockDim.x) {
                int i = o >> 6, j = o & 63;
                float acc = 0.f;
#pragma unroll 16
                for (int k = 0; k < 64; k++)
                    acc += S[i * 64 + k] * __ldg(Wout + k * 64 + j);
                T[o] = acc;
            }
            __syncthreads();
            src = T;
        }
        __half2* dst;
        int ktbase;
        if (m < 3) { dst = g_fragA[l]; ktbase = m * 4; }
        else       { dst = g_fragB[l]; ktbase = (m - 3) * 4; }
        for (int o = threadIdx.x; o < 1024; o += blockDim.x) {
            int kt2 = o >> 8, nt = (o >> 5) & 7, lane = o & 31;
            int k0 = kt2 * 16 + (lane & 3) * 2;
            int n = nt * 8 + (lane >> 2);
            int plane = ((ktbase + kt2) * 8 + nt) * 64 + lane;
            dst[plane]      = __floats2half2_rn(src[k0 * 64 + n], src[(k0 + 1) * 64 + n]);
            dst[plane + 32] = __floats2half2_rn(src[(k0 + 8) * 64 + n], src[(k0 + 9) * 64 + n]);
        }
    } else {
        // ---- biases (head-folded for layer 1) ----
        int j = threadIdx.x;
        if (j < 64) {
            g_bias[0][j]      = b[1 * 64 + j] + b[2 * 64 + j];
            g_bias[0][64 + j] = b[j];
            float accA = 0.f, accB = 0.f;
            for (int k = 0; k < 64; k++) {
                float w = __ldg(Wout + k * 64 + j);
                accA += (b[4 * 64 + k] + b[5 * 64 + k]) * w;
                accB += b[3 * 64 + k] * w;
            }
            g_bias[1][j]      = accA + bout[j];
            g_bias[1][64 + j] = accB + bout[j];
        }
    }
}

// ---------------- CSR build: chunk sums -------------------------------------
__global__ void chunk_sum_kernel() {
    int type = blockIdx.x / NCH, ch = blockIdx.x % NCH;
    const int* cnt = (type == 0) ? g_cnt0 : (type == 1) ? g_cnt1 : g_cnt2;
    int N = (type == 0) ? NB : NA;
    int i0 = ch * 2048 + threadIdx.x * 8;
    int s = 0;
#pragma unroll
    for (int k = 0; k < 8; k++) {
        int i = i0 + k;
        if (i < N) s += cnt[i];
    }
    __shared__ int red[256];
    red[threadIdx.x] = s;
    __syncthreads();
    for (int o = 128; o > 0; o >>= 1) {
        if (threadIdx.x < o) red[threadIdx.x] += red[threadIdx.x + o];
        __syncthreads();
    }
    if (threadIdx.x == 0) g_csum[type * 64 + ch] = red[0];
}

// ---------------- CSR build: write ptr + SELF-RESET counts ------------------
__global__ void write_ptr_kernel(int E0, int E1, int E2) {
    int type = blockIdx.x / NCH, ch = blockIdx.x % NCH;
    int* cnt; int* ptr; int* wofs; int N;
    if (type == 0)      { cnt = g_cnt0; ptr = g_ptr0; wofs = g_wofs0; N = NB; }
    else if (type == 1) { cnt = g_cnt1; ptr = g_ptr1; wofs = g_wofs1; N = NA; }
    else                { cnt = g_cnt2; ptr = g_ptr2; wofs = g_wofs2; N = NA; }

    if (threadIdx.x == 0 && ch == 0) {
        if (type == 0) g_ptr0[NB] = E0;
        else if (type == 1) g_ptr1[NA] = E1;
        else g_ptr2[NA] = E2;
    }

    __shared__ int csh[NCH];
    if (threadIdx.x < NCH) csh[threadIdx.x] = __ldg(&g_csum[type * 64 + threadIdx.x]);

    int i0 = ch * 2048 + threadIdx.x * 8;
    int c[8];
    int s = 0;
#pragma unroll
    for (int k = 0; k < 8; k++) {
        int i = i0 + k;
        c[k] = (i < N) ? cnt[i] : 0;
        s += c[k];
    }
    __shared__ int sd[256];
    sd[threadIdx.x] = s;
    __syncthreads();
    for (int o = 1; o < 256; o <<= 1) {
        int v = (threadIdx.x >= o) ? sd[threadIdx.x - o] : 0;
        __syncthreads();
        sd[threadIdx.x] += v;
        __syncthreads();
    }
    int cbase = 0;
    for (int c2 = 0; c2 < ch; c2++) cbase += csh[c2];
    int base = cbase + sd[threadIdx.x] - s;
#pragma unroll
    for (int k = 0; k < 8; k++) {
        int i = i0 + k;
        if (i < N) {
            ptr[i] = base;
            wofs[i] = base;
            cnt[i] = 0;          // self-reset for the next graph replay
            base += c[k];
        }
    }
}

// ---------------- CSR build: scatter, per-type grid segments ----------------
// Blocks [0,SB): type0, [SB,2SB): type1, [2SB,3SB): type2. 4-wide loads;
// each thread loops ~2x within its type -> atomic latency overlapped, and
// no serial 3-type chain per thread.
#define SB 512
__device__ __forceinline__ void scat4(int4 s, int4 d, int* wofs, int* colv) {
    int p0 = atomicAdd(&wofs[d.x], 1);
    int p1 = atomicAdd(&wofs[d.y], 1);
    int p2 = atomicAdd(&wofs[d.z], 1);
    int p3 = atomicAdd(&wofs[d.w], 1);
    colv[p0] = s.x; colv[p1] = s.y; colv[p2] = s.z; colv[p3] = s.w;
}

__global__ void scatter_kernel(const int* __restrict__ s0, const int* __restrict__ d0,
                               const int* __restrict__ s1, const int* __restrict__ d1,
                               const int* __restrict__ s2, const int* __restrict__ d2,
                               int E0, int E1, int E2) {
    const int* s; const int* d; int* wofs; int* colv; int E, bloc;
    if (blockIdx.x < SB)          { bloc = blockIdx.x;          s = s0; d = d0; wofs = g_wofs0; colv = g_col0; E = E0; }
    else if (blockIdx.x < 2 * SB) { bloc = blockIdx.x - SB;     s = s1; d = d1; wofs = g_wofs1; colv = g_col1; E = E1; }
    else                          { bloc = blockIdx.x - 2 * SB; s = s2; d = d2; wofs = g_wofs2; colv = g_col2; E = E2; }

    int t = bloc * 256 + threadIdx.x;
    const int stride = SB * 256;
    int q4 = E >> 2;
    for (int q = t; q < q4; q += stride)
        scat4(__ldg((const int4*)s + q), __ldg((const int4*)d + q), wofs, colv);
    for (int e = q4 * 4 + t; e < E; e += stride) {
        int p = atomicAdd(&wofs[__ldg(d + e)], 1);
        colv[p] = __ldg(s + e);
    }
}

// ---------------- in-block CSR gather of one 32B slice of a node's mean -----
// 4 threads/node; thread c owns halves [16c, 16c+16) = 2 uint4 per edge.
__device__ __forceinline__ void acc8(uint4 u, float* a) {
    const __half2* h = (const __half2*)&u;
    float2 f;
    f = __half22float2(h[0]); a[0] += f.x; a[1] += f.y;
    f = __half22float2(h[1]); a[2] += f.x; a[3] += f.y;
    f = __half22float2(h[2]); a[4] += f.x; a[5] += f.y;
    f = __half22float2(h[3]); a[6] += f.x; a[7] += f.y;
}

__device__ __forceinline__ void gather_slice(
    __half* dst, const int* __restrict__ ptr, const int* __restrict__ col,
    const __half* __restrict__ x, int n, int c, bool valid) {
    float a[16];
#pragma unroll
    for (int t = 0; t < 16; t++) a[t] = 0.f;
    float inv = 1.0f;
    if (valid) {
        int beg = __ldg(ptr + n), end = __ldg(ptr + n + 1);
        const uint4* X = (const uint4*)x;
        int k = beg;
        int s0 = 0, s1 = 0;
        if (k < end) s0 = __ldg(col + k);
        if (k + 1 < end) s1 = __ldg(col + k + 1);
        while (k + 1 < end) {
            int ns0 = 0, ns1 = 0;
            if (k + 2 < end) ns0 = __ldg(col + k + 2);
            if (k + 3 < end) ns1 = __ldg(col + k + 3);
            uint4 u0 = __ldg(X + (size_t)s0 * 8 + c * 2);
            uint4 v0 = __ldg(X + (size_t)s0 * 8 + c * 2 + 1);
            uint4 u1 = __ldg(X + (size_t)s1 * 8 + c * 2);
            uint4 v1 = __ldg(X + (size_t)s1 * 8 + c * 2 + 1);
            acc8(u0, a); acc8(v0, a + 8);
            acc8(u1, a); acc8(v1, a + 8);
            s0 = ns0; s1 = ns1; k += 2;
        }
        if (k < end) {
            uint4 u0 = __ldg(X + (size_t)s0 * 8 + c * 2);
            uint4 v0 = __ldg(X + (size_t)s0 * 8 + c * 2 + 1);
            acc8(u0, a); acc8(v0, a + 8);
        }
        inv = 1.0f / fmaxf((float)(end - beg), 1.0f);
    }
    __half2 h[8];
#pragma unroll
    for (int t = 0; t < 8; t++)
        h[t] = __floats2half2_rn(a[2 * t] * inv, a[2 * t + 1] * inv);
    uint4 o0, o1;
    o0.x = *(unsigned*)&h[0]; o0.y = *(unsigned*)&h[1];
    o0.z = *(unsigned*)&h[2]; o0.w = *(unsigned*)&h[3];
    o1.x = *(unsigned*)&h[4]; o1.y = *(unsigned*)&h[5];
    o1.z = *(unsigned*)&h[6]; o1.w = *(unsigned*)&h[7];
    ((uint4*)dst)[0] = o0;
    ((uint4*)dst)[1] = o1;
}

// ---------------- fused layer: in-block gather + fp16 m16n8k16 combine ------
#define XH 200   // halves per row
template<bool FP32OUT>
__global__ __launch_bounds__(256, 5) void layer_kernel(
    const __half* __restrict__ hxA, const __half* __restrict__ hxB,
    const __half2* __restrict__ fragA, const __half2* __restrict__ fragB,
    const float* __restrict__ bl,
    float* __restrict__ outA, float* __restrict__ outB,
    __half* __restrict__ houtA, __half* __restrict__ houtB, int nbA) {
    extern __shared__ __align__(16) unsigned smraw[];
    __half* sxh = (__half*)smraw;                       // 64*200 halves = 25600B
    uint4* sxq = (uint4*)smraw;                         // row stride 25 uint4
    const int lane = threadIdx.x & 31;
    const int warp = threadIdx.x >> 5;
    const int mt = warp & 3;
    const int nh = warp >> 2;
    const int r8 = lane >> 2;
    const int c4 = lane & 3;
    const int gn = threadIdx.x >> 2;   // node in tile, 0..63 (gather phase)
    const int gc = threadIdx.x & 3;    // 32B slice, 0..3

    bool isA = (blockIdx.x < nbA);
    int row0, rows, KT;
    float* outX;
    __half* houtX;
    const float* blx;
    const __half2* frag;
    if (isA) {
        row0 = blockIdx.x * 64;
        rows = NA - row0 < 64 ? NA - row0 : 64;
        KT = 12;
        outX = outA; houtX = houtA; blx = bl; frag = fragA;
        for (int i = threadIdx.x; i < 512; i += 256) {
            int r = i >> 3, q = i & 7;
            uint4 u = make_uint4(0, 0, 0, 0);
            if (r < rows) u = __ldg((const uint4*)hxA + (size_t)(row0 + r) * 8 + q);
            sxq[r * 25 + 16 + q] = u;
        }
        bool valid = (gn < rows);
        int n = row0 + gn;
        gather_slice(sxh + gn * XH + 0 * 64 + gc * 16, g_ptr1, g_col1, hxB, n, gc, valid);
        gather_slice(sxh + gn * XH + 1 * 64 + gc * 16, g_ptr2, g_col2, hxA, n, gc, valid);
    } else {
        row0 = (blockIdx.x - nbA) * 64;
        rows = NB - row0 < 64 ? NB - row0 : 64;
        KT = 8;
        outX = outB; houtX = houtB; blx = bl + 64; frag = fragB;
        for (int i = threadIdx.x; i < 512; i += 256) {
            int r = i >> 3, q = i & 7;
            uint4 u = make_uint4(0, 0, 0, 0);
            if (r < rows) u = __ldg((const uint4*)hxB + (size_t)(row0 + r) * 8 + q);
            sxq[r * 25 + 8 + q] = u;
        }
        bool valid = (gn < rows);
        int n = row0 + gn;
        gather_slice(sxh + gn * XH + 0 * 64 + gc * 16, g_ptr0, g_col0, hxA, n, gc, valid);
    }
    __syncthreads();

    float acc[4][4];
#pragma unroll
    for (int t = 0; t < 4; t++) {
        acc[t][0] = 0.f; acc[t][1] = 0.f; acc[t][2] = 0.f; acc[t][3] = 0.f;
    }

    const __half* ap0 = sxh + (mt * 16 + r8) * XH + c4 * 2;
    for (int kt = 0; kt < KT; kt++) {
        const __half* ap = ap0 + kt * 16;
        unsigned a0 = *(const unsigned*)(ap);
        unsigned a1 = *(const unsigned*)(ap + 8 * XH);
        unsigned a2 = *(const unsigned*)(ap + 8);
        unsigned a3 = *(const unsigned*)(ap + 8 * XH + 8);
        const __half2* fp = frag + (kt * 8 + nh * 4) * 64 + lane;
#pragma unroll
        for (int t = 0; t < 4; t++) {
            __half2 b0 = __ldg(fp + t * 64);
            __half2 b1 = __ldg(fp + t * 64 + 32);
            mma_f16(acc[t], a0, a1, a2, a3,
                    *(unsigned*)&b0, *(unsigned*)&b1);
        }
    }

    int r0 = mt * 16 + r8;
#pragma unroll
    for (int t = 0; t < 4; t++) {
        int colj = (nh * 4 + t) * 8 + c4 * 2;
        float b0 = __ldg(blx + colj), b1 = __ldg(blx + colj + 1);
        float v00 = acc[t][0] + b0, v01 = acc[t][1] + b1;
        float v10 = acc[t][2] + b0, v11 = acc[t][3] + b1;
        if (FP32OUT) {
            v00 = fmaxf(v00, 0.f); v01 = fmaxf(v01, 0.f);
            v10 = fmaxf(v10, 0.f); v11 = fmaxf(v11, 0.f);
            if (r0 < rows)
                *(float2*)&outX[(size_t)(row0 + r0) * 64 + colj] = make_float2(v00, v01);
            if (r0 + 8 < rows)
                *(float2*)&outX[(size_t)(row0 + r0 + 8) * 64 + colj] = make_float2(v10, v11);
        } else {
            if (r0 < rows)
                *(__half2*)&houtX[(size_t)(row0 + r0) * 64 + colj] = __floats2half2_rn(v00, v01);
            if (r0 + 8 < rows)
                *(__half2*)&houtX[(size_t)(row0 + r0 + 8) * 64 + colj] = __floats2half2_rn(v10, v11);
        }
    }
}

// ---------------- launcher --------------------------------------------------
extern "C" void kernel_launch(void* const* d_in, const int* in_sizes, int n_in,
                              void* d_out, int out_size) {
    const float* x_A   = (const float*)d_in[0];
    const float* x_B   = (const float*)d_in[1];
    const float* Wn    = (const float*)d_in[2];
    const float* Wr    = (const float*)d_in[3];
    const float* b     = (const float*)d_in[4];
    const float* W_out = (const float*)d_in[5];
    const float* b_out = (const float*)d_in[6];
    const int* src0 = (const int*)d_in[7];
    const int* dst0 = (const int*)d_in[8];
    const int* src1 = (const int*)d_in[9];
    const int* dst1 = (const int*)d_in[10];
    const int* src2 = (const int*)d_in[11];
    const int* dst2 = (const int*)d_in[12];
    const int E0 = in_sizes[7];
    const int E1 = in_sizes[9];
    const int E2 = in_sizes[11];
    float* out = (float*)d_out;

    float *bias0, *bias1;
    __half2 *frA, *frB;
    __half *hA, *hB, *hA1, *hB1;
    cudaGetSymbolAddress((void**)&hA, g_hA);
    cudaGetSymbolAddress((void**)&hB, g_hB);
    cudaGetSymbolAddress((void**)&hA1, g_hA1);
    cudaGetSymbolAddress((void**)&hB1, g_hB1);
    cudaGetSymbolAddress((void**)&frA, g_fragA);
    cudaGetSymbolAddress((void**)&frB, g_fragB);
    cudaGetSymbolAddress((void**)&bias0, g_bias);
    bias1 = bias0 + 128;

    const int nbA = (NA + 63) / 64;
    const int nbB = (NB + 63) / 64;
    const int smemBytes = 25600;   // X tile only; frags live in L1

    cudaFuncSetAttribute(layer_kernel<false>,
                         cudaFuncAttributeMaxDynamicSharedMemorySize, smemBytes);
    cudaFuncSetAttribute(layer_kernel<true>,
                         cudaFuncAttributeMaxDynamicSharedMemorySize, smemBytes);

    // ---- fused prologue: hist + conv + weight prep (all independent) ----
    prologue_kernel<<<1035, 256>>>(x_A, x_B, Wn, Wr, b, W_out, b_out,
                                   dst0, dst1, dst2, E0, E1, E2);

    // ---- CSR build (cnt arrays self-reset by write_ptr; no memsets) ----
    chunk_sum_kernel<<<3 * NCH, 256>>>();
    write_ptr_kernel<<<3 * NCH, 256>>>(E0, E1, E2);
    scatter_kernel<<<3 * SB, 256>>>(src0, dst0, src1, dst1, src2, dst2, E0, E1, E2);

    // ---- layer 0 (fused gather+combine; outputs fp16 only) ----
    layer_kernel<false><<<nbA + nbB, 256, smemBytes>>>(
        hA, hB, frA, frB, bias0, nullptr, nullptr, hA1, hB1, nbA);

    // ---- layer 1 (fused; head folded into weights; relu at store; fp32 out) ----
    layer_kernel<true><<<nbA + nbB, 256, smemBytes>>>(
        hA1, hB1, frA + 12 * 8 * 64, frB + 8 * 8 * 64, bias1,
        out, out + (size_t)NA * 64, nullptr, nullptr, nbA);
}